// round 1
// baseline (speedup 1.0000x reference)
#include <cuda_runtime.h>
#include <cstdint>

// ---------------- problem constants ----------------
#define BATCH    2
#define LSEQ     2048
#define DMODEL   2048
#define INTERD   4096
#define NHEADS   64
#define HDIM     64
#define NSTATE   128
#define KCONV    4
#define CSIZE    256
#define NCHUNK   (LSEQ / CSIZE)                 // 8
#define CONVDIM  (INTERD + 2 * NSTATE)          // 4352
#define PROJDIM  (INTERD + CONVDIM + NHEADS)    // 8512
#define BL       (BATCH * LSEQ)                 // 4096
#define EPSV     1e-5f

// ---------------- device scratch (static; no allocs allowed) ----------------
__device__ float g_proj  [(size_t)BL * PROJDIM];                       // 139 MB
__device__ float g_xBC   [(size_t)BL * CONVDIM];                       //  71 MB
__device__ float g_dtv   [(size_t)BL * NHEADS];
__device__ float g_Acum  [(size_t)BATCH * NHEADS * NCHUNK * CSIZE];
__device__ float g_CB    [(size_t)BATCH * NCHUNK * CSIZE * CSIZE];     //   4 MB
__device__ float g_states[(size_t)BATCH * NCHUNK * NHEADS * HDIM * NSTATE]; // 33.5 MB
__device__ float g_prev  [(size_t)BATCH * NCHUNK * NHEADS * HDIM * NSTATE]; // 33.5 MB
__device__ float g_Y     [(size_t)BL * INTERD];                        //  67 MB

// ---------------- generic NT SGEMM: C[M,N] = A[M,K] * B[N,K]^T ----------------
// A row-major lda, B row-major ldb (both K contiguous), C row-major ldc.
// 128x128 block tile, 16 K-tile, 256 threads, 8x8 microtile. Batched via grid.z.
__global__ __launch_bounds__(256) void sgemm_nt(
    const float* __restrict__ A, const float* __restrict__ B, float* __restrict__ C,
    int M, int N, int K, int lda, int ldb, int ldc,
    long long sA, long long sB, long long sC)
{
    A += (long long)blockIdx.z * sA;
    B += (long long)blockIdx.z * sB;
    C += (long long)blockIdx.z * sC;
    const int bm = blockIdx.y * 128, bn = blockIdx.x * 128;
    __shared__ float As[16][128];
    __shared__ float Bs[16][128];
    const int tid = threadIdx.x;
    const int lr = tid >> 2;           // 0..63
    const int lc = (tid & 3) << 2;     // 0,4,8,12
    const int tx = tid & 15, ty = tid >> 4;

    float acc[8][8];
#pragma unroll
    for (int i = 0; i < 8; ++i)
#pragma unroll
        for (int j = 0; j < 8; ++j) acc[i][j] = 0.f;

    for (int k0 = 0; k0 < K; k0 += 16) {
#pragma unroll
        for (int r = 0; r < 2; ++r) {
            int row = lr + r * 64;
            int gr  = bm + row;
            float4 v = make_float4(0.f, 0.f, 0.f, 0.f);
            if (gr < M) v = *(const float4*)&A[(long long)gr * lda + k0 + lc];
            As[lc + 0][row] = v.x; As[lc + 1][row] = v.y;
            As[lc + 2][row] = v.z; As[lc + 3][row] = v.w;
        }
#pragma unroll
        for (int r = 0; r < 2; ++r) {
            int row = lr + r * 64;
            int gr  = bn + row;
            float4 v = make_float4(0.f, 0.f, 0.f, 0.f);
            if (gr < N) v = *(const float4*)&B[(long long)gr * ldb + k0 + lc];
            Bs[lc + 0][row] = v.x; Bs[lc + 1][row] = v.y;
            Bs[lc + 2][row] = v.z; Bs[lc + 3][row] = v.w;
        }
        __syncthreads();
#pragma unroll
        for (int k = 0; k < 16; ++k) {
            float a[8], b[8];
            *(float4*)&a[0] = *(const float4*)&As[k][ty * 8];
            *(float4*)&a[4] = *(const float4*)&As[k][ty * 8 + 4];
            *(float4*)&b[0] = *(const float4*)&Bs[k][tx * 8];
            *(float4*)&b[4] = *(const float4*)&Bs[k][tx * 8 + 4];
#pragma unroll
            for (int ii = 0; ii < 8; ++ii)
#pragma unroll
                for (int jj = 0; jj < 8; ++jj) acc[ii][jj] += a[ii] * b[jj];
        }
        __syncthreads();
    }
#pragma unroll
    for (int ii = 0; ii < 8; ++ii) {
        int gr = bm + ty * 8 + ii;
        if (gr >= M) continue;
#pragma unroll
        for (int jj = 0; jj < 8; ++jj) {
            int gc = bn + tx * 8 + jj;
            if (gc < N) C[(long long)gr * ldc + gc] = acc[ii][jj];
        }
    }
}

// ---------------- depthwise causal conv (K=4) + bias + silu ----------------
__global__ void conv_silu_kernel(const float* __restrict__ proj,
                                 const float* __restrict__ cw,
                                 const float* __restrict__ cb,
                                 float* __restrict__ xBC)
{
    int idx = blockIdx.x * blockDim.x + threadIdx.x;
    if (idx >= BL * CONVDIM) return;
    int ch = idx % CONVDIM;
    int bl = idx / CONVDIM;
    int l  = bl % LSEQ;
    float4 w = *(const float4*)&cw[ch * 4];
    float acc = cb[ch];
    const float* base = proj + (size_t)bl * PROJDIM + INTERD + ch;
    if (l >= 3) {
        acc += w.x * base[-3 * PROJDIM] + w.y * base[-2 * PROJDIM]
             + w.z * base[-1 * PROJDIM] + w.w * base[0];
    } else {
        float wk[4] = {w.x, w.y, w.z, w.w};
        for (int k = 3 - l; k < 4; ++k) acc += wk[k] * base[(k - 3) * PROJDIM];
    }
    xBC[idx] = acc / (1.f + expf(-acc));
}

// ---------------- softplus(dt+bias), per-chunk inclusive cumsum of dA ----------------
__global__ void dt_acum_kernel(const float* __restrict__ proj,
                               const float* __restrict__ dt_bias,
                               const float* __restrict__ A_log,
                               float* __restrict__ dtv,
                               float* __restrict__ Acum)
{
    int cc = blockIdx.x, h = blockIdx.y, b = blockIdx.z;
    int i  = threadIdx.x;
    int l  = cc * CSIZE + i;
    float d  = proj[(size_t)(b * LSEQ + l) * PROJDIM + INTERD + CONVDIM + h] + dt_bias[h];
    float sp = (d > 20.f) ? d : log1pf(expf(d));
    dtv[(size_t)(b * LSEQ + l) * NHEADS + h] = sp;
    float dA = sp * (-expf(A_log[h]));
    __shared__ float sbuf[CSIZE];
    sbuf[i] = dA;
    __syncthreads();
    for (int off = 1; off < CSIZE; off <<= 1) {
        float v = sbuf[i];
        if (i >= off) v += sbuf[i - off];
        __syncthreads();
        sbuf[i] = v;
        __syncthreads();
    }
    Acum[(((size_t)b * NHEADS + h) * NCHUNK + cc) * CSIZE + i] = sbuf[i];
}

// ---------------- per (b,h,chunk): states[p,n] = sum_j w_j * x[j,p] * B[j,n] ----------------
__global__ __launch_bounds__(256) void states_kernel(
    const float* __restrict__ xBC, const float* __restrict__ dtv,
    const float* __restrict__ Acum, float* __restrict__ states)
{
    int cc = blockIdx.x, h = blockIdx.y, b = blockIdx.z;
    int tid = threadIdx.x;
    int tn = tid & 15, tp = tid >> 4;
    __shared__ float Bs[16][128];
    __shared__ float wxs[16][64];
    const float* Ab = Acum + (((size_t)b * NHEADS + h) * NCHUNK + cc) * CSIZE;
    float AcLast = Ab[CSIZE - 1];
    float acc[4][8];
#pragma unroll
    for (int p = 0; p < 4; ++p)
#pragma unroll
        for (int n = 0; n < 8; ++n) acc[p][n] = 0.f;
    int l0 = b * LSEQ + cc * CSIZE;
    for (int jt = 0; jt < CSIZE; jt += 16) {
#pragma unroll
        for (int r = 0; r < 2; ++r) {
            int f  = tid + r * 256;     // 0..511 float4s
            int jr = f >> 5;            // 32 float4 per row
            int n4 = f & 31;
            *(float4*)&Bs[jr][n4 * 4] =
                *(const float4*)&xBC[(size_t)(l0 + jt + jr) * CONVDIM + INTERD + n4 * 4];
        }
        {
            int jr = tid >> 4, p4 = tid & 15;
            int j  = jt + jr;
            float w = expf(AcLast - Ab[j]) * dtv[(size_t)(l0 + j) * NHEADS + h];
            float4 xv = *(const float4*)&xBC[(size_t)(l0 + j) * CONVDIM + h * HDIM + p4 * 4];
            xv.x *= w; xv.y *= w; xv.z *= w; xv.w *= w;
            *(float4*)&wxs[jr][p4 * 4] = xv;
        }
        __syncthreads();
#pragma unroll
        for (int j = 0; j < 16; ++j) {
            float bx[8], px[4];
            *(float4*)&bx[0] = *(const float4*)&Bs[j][tn * 8];
            *(float4*)&bx[4] = *(const float4*)&Bs[j][tn * 8 + 4];
            *(float4*)&px[0] = *(const float4*)&wxs[j][tp * 4];
#pragma unroll
            for (int p = 0; p < 4; ++p)
#pragma unroll
                for (int n = 0; n < 8; ++n) acc[p][n] += px[p] * bx[n];
        }
        __syncthreads();
    }
    float* so = states + (((size_t)b * NCHUNK + cc) * NHEADS + h) * (HDIM * NSTATE);
#pragma unroll
    for (int p = 0; p < 4; ++p) {
#pragma unroll
        for (int n = 0; n < 8; n += 4) {
            float4 v = make_float4(acc[p][n], acc[p][n + 1], acc[p][n + 2], acc[p][n + 3]);
            *(float4*)&so[(tp * 4 + p) * NSTATE + tn * 8 + n] = v;
        }
    }
}

// ---------------- inter-chunk recurrence (scan over 8 chunks) ----------------
__global__ void scan_kernel(const float* __restrict__ states,
                            const float* __restrict__ Acum,
                            float* __restrict__ prev)
{
    int h = blockIdx.x, b = blockIdx.y, tid = threadIdx.x;
    float carry[32];
#pragma unroll
    for (int t = 0; t < 32; ++t) carry[t] = 0.f;
    for (int cc = 0; cc < NCHUNK; ++cc) {
        float cd = expf(Acum[(((size_t)b * NHEADS + h) * NCHUNK + cc) * CSIZE + CSIZE - 1]);
        size_t base = (((size_t)b * NCHUNK + cc) * NHEADS + h) * (HDIM * NSTATE);
#pragma unroll
        for (int t = 0; t < 32; ++t) {
            size_t idx = base + tid + t * 256;
            prev[idx]  = carry[t];
            carry[t]   = cd * carry[t] + states[idx];
        }
    }
}

// ---------------- per (b,h,chunk): Ydiag + Yoff + D*x -> Y ----------------
__global__ __launch_bounds__(256) void y_kernel(
    const float* __restrict__ xBC, const float* __restrict__ dtv,
    const float* __restrict__ Acum, const float* __restrict__ CB,
    const float* __restrict__ prev, const float* __restrict__ Dp,
    float* __restrict__ Y)
{
    int cc = blockIdx.x, h = blockIdx.y, b = blockIdx.z;
    int i  = threadIdx.x;
    __shared__ float dts[CSIZE], Ac[CSIZE];
    __shared__ float xs[16][64];
    __shared__ float prevs[HDIM * NSTATE];   // 32 KB
    int l0 = b * LSEQ + cc * CSIZE;
    dts[i] = dtv[(size_t)(l0 + i) * NHEADS + h];
    Ac[i]  = Acum[(((size_t)b * NHEADS + h) * NCHUNK + cc) * CSIZE + i];
    __syncthreads();
    float Ai = Ac[i];
    float y[64];
#pragma unroll
    for (int p = 0; p < 64; ++p) y[p] = 0.f;
    const float* CBrow = CB + (((size_t)b * NCHUNK + cc) * CSIZE + i) * CSIZE;

    for (int jt = 0; jt < CSIZE; jt += 16) {
        {
            int jr = threadIdx.x >> 4, p4 = threadIdx.x & 15;
            *(float4*)&xs[jr][p4 * 4] =
                *(const float4*)&xBC[(size_t)(l0 + jt + jr) * CONVDIM + h * HDIM + p4 * 4];
        }
        __syncthreads();
        if (i >= jt) {
            int jmax = i - jt + 1;
            if (jmax > 16) jmax = 16;
            for (int jl = 0; jl < jmax; ++jl) {
                int j = jt + jl;
                float coef = CBrow[j] * expf(Ai - Ac[j]) * dts[j];
#pragma unroll
                for (int p4 = 0; p4 < 16; ++p4) {
                    float4 xv = *(const float4*)&xs[jl][p4 * 4];
                    y[p4 * 4 + 0] += coef * xv.x;
                    y[p4 * 4 + 1] += coef * xv.y;
                    y[p4 * 4 + 2] += coef * xv.z;
                    y[p4 * 4 + 3] += coef * xv.w;
                }
            }
        }
        __syncthreads();
    }

    // stage prev[h, p, n] into smem (coalesced, layout preserved)
    {
        const float4* src =
            (const float4*)(prev + (((size_t)b * NCHUNK + cc) * NHEADS + h) * (HDIM * NSTATE));
        float4* dst = (float4*)prevs;
        for (int f = threadIdx.x; f < (HDIM * NSTATE) / 4; f += 256) dst[f] = src[f];
    }
    __syncthreads();
    float eAi = expf(Ai);
    const float* Crow = xBC + (size_t)(l0 + i) * CONVDIM + INTERD + NSTATE;
    for (int nt = 0; nt < NSTATE; nt += 8) {
        float cf[8];
#pragma unroll
        for (int q = 0; q < 8; ++q) cf[q] = eAi * Crow[nt + q];
#pragma unroll
        for (int p = 0; p < 64; ++p) {
            const float* pr = &prevs[p * NSTATE + nt];
            float4 v0 = *(const float4*)pr;
            float4 v1 = *(const float4*)(pr + 4);
            y[p] += cf[0] * v0.x + cf[1] * v0.y + cf[2] * v0.z + cf[3] * v0.w
                  + cf[4] * v1.x + cf[5] * v1.y + cf[6] * v1.z + cf[7] * v1.w;
        }
    }

    float Dh = Dp[h];
    float* yo = Y + (size_t)(l0 + i) * INTERD + h * HDIM;
    const float* xr = xBC + (size_t)(l0 + i) * CONVDIM + h * HDIM;
#pragma unroll
    for (int p4 = 0; p4 < 16; ++p4) {
        float4 xv = *(const float4*)&xr[p4 * 4];
        float4 ov;
        ov.x = y[p4 * 4 + 0] + Dh * xv.x;
        ov.y = y[p4 * 4 + 1] + Dh * xv.y;
        ov.z = y[p4 * 4 + 2] + Dh * xv.z;
        ov.w = y[p4 * 4 + 3] + Dh * xv.w;
        *(float4*)&yo[p4 * 4] = ov;
    }
}

// ---------------- gate (silu) + RMSNorm, in place on g_Y ----------------
__global__ void gate_rms_kernel(const float* __restrict__ proj,
                                const float* __restrict__ norm_w,
                                float* __restrict__ Y)
{
    int row = blockIdx.x, tid = threadIdx.x;
    const float* gr = proj + (size_t)row * PROJDIM;
    float* yr = Y + (size_t)row * INTERD;
    float yv[16];
    float ss = 0.f;
#pragma unroll
    for (int t = 0; t < 16; ++t) {
        int e = tid + t * 256;
        float g = gr[e];
        float v = yr[e] * (g / (1.f + expf(-g)));
        yv[t] = v;
        ss += v * v;
    }
    __shared__ float red[8];
#pragma unroll
    for (int o = 16; o > 0; o >>= 1) ss += __shfl_xor_sync(0xffffffff, ss, o);
    if ((tid & 31) == 0) red[tid >> 5] = ss;
    __syncthreads();
    float tot = 0.f;
#pragma unroll
    for (int w = 0; w < 8; ++w) tot += red[w];
    float scale = rsqrtf(tot / (float)INTERD + EPSV);
#pragma unroll
    for (int t = 0; t < 16; ++t) {
        int e = tid + t * 256;
        yr[e] = yv[t] * scale * norm_w[e];
    }
}

// ---------------- launch ----------------
extern "C" void kernel_launch(void* const* d_in, const int* in_sizes, int n_in,
                              void* d_out, int out_size)
{
    const float* hs      = (const float*)d_in[0];
    const float* W_in    = (const float*)d_in[1];
    const float* conv_w  = (const float*)d_in[2];
    const float* conv_b  = (const float*)d_in[3];
    const float* dt_bias = (const float*)d_in[4];
    const float* A_log   = (const float*)d_in[5];
    const float* Dp      = (const float*)d_in[6];
    const float* norm_w  = (const float*)d_in[7];
    const float* W_out   = (const float*)d_in[8];
    float* out = (float*)d_out;

    float *proj, *xBC, *dtv, *Acum, *CB, *states, *prev, *Y;
    cudaGetSymbolAddress((void**)&proj,   g_proj);
    cudaGetSymbolAddress((void**)&xBC,    g_xBC);
    cudaGetSymbolAddress((void**)&dtv,    g_dtv);
    cudaGetSymbolAddress((void**)&Acum,   g_Acum);
    cudaGetSymbolAddress((void**)&CB,     g_CB);
    cudaGetSymbolAddress((void**)&states, g_states);
    cudaGetSymbolAddress((void**)&prev,   g_prev);
    cudaGetSymbolAddress((void**)&Y,      g_Y);

    // 1) proj = hs @ W_in^T   [4096 x 8512, K=2048]
    sgemm_nt<<<dim3((PROJDIM + 127) / 128, BL / 128, 1), 256>>>(
        hs, W_in, proj, BL, PROJDIM, DMODEL, DMODEL, DMODEL, PROJDIM, 0, 0, 0);

    // 2) depthwise causal conv + silu -> xBC
    {
        int total = BL * CONVDIM;
        conv_silu_kernel<<<(total + 255) / 256, 256>>>(proj, conv_w, conv_b, xBC);
    }

    // 3) softplus(dt) + per-chunk cumsum of dA
    dt_acum_kernel<<<dim3(NCHUNK, NHEADS, BATCH), CSIZE>>>(proj, dt_bias, A_log, dtv, Acum);

    // 4) CB[b,c,i,j] = C_i . B_j  (shared across all heads, G=1)
    sgemm_nt<<<dim3(2, 2, BATCH * NCHUNK), 256>>>(
        xBC + (INTERD + NSTATE), xBC + INTERD, CB,
        CSIZE, CSIZE, NSTATE, CONVDIM, CONVDIM, CSIZE,
        (long long)CSIZE * CONVDIM, (long long)CSIZE * CONVDIM, (long long)CSIZE * CSIZE);

    // 5) per-chunk states
    states_kernel<<<dim3(NCHUNK, NHEADS, BATCH), 256>>>(xBC, dtv, Acum, states);

    // 6) inter-chunk scan -> prev
    scan_kernel<<<dim3(NHEADS, BATCH), 256>>>(states, Acum, prev);

    // 7) Ydiag + Yoff + D*x -> Y
    y_kernel<<<dim3(NCHUNK, NHEADS, BATCH), CSIZE>>>(xBC, dtv, Acum, CB, prev, Dp, Y);

    // 8) gate + RMSNorm (in place on Y)
    gate_rms_kernel<<<BL, 256>>>(proj, norm_w, Y);

    // 9) out = Y @ W_out^T   [4096 x 2048, K=4096]
    sgemm_nt<<<dim3(DMODEL / 128, BL / 128, 1), 256>>>(
        Y, W_out, out, BL, DMODEL, INTERD, INTERD, INTERD, DMODEL, 0, 0, 0);
}

// round 3
// speedup vs baseline: 2.2503x; 2.2503x over previous
#include <cuda_runtime.h>
#include <cuda_bf16.h>
#include <cstdint>

// ---------------- problem constants ----------------
#define BATCH    2
#define LSEQ     2048
#define DMODEL   2048
#define INTERD   4096
#define NHEADS   64
#define HDIM     64
#define NSTATE   128
#define KCONV    4
#define CSIZE    256
#define NCHUNK   (LSEQ / CSIZE)                 // 8
#define CONVDIM  (INTERD + 2 * NSTATE)          // 4352
#define PROJDIM  (INTERD + CONVDIM + NHEADS)    // 8512
#define BL       (BATCH * LSEQ)                 // 4096
#define EPSV     1e-5f

// ---------------- device scratch (static; no allocs allowed) ----------------
__device__ float g_proj  [(size_t)BL * PROJDIM];
__device__ float g_xBC   [(size_t)BL * CONVDIM];
__device__ float g_dtv   [(size_t)BL * NHEADS];
__device__ float g_Acum  [(size_t)BATCH * NHEADS * NCHUNK * CSIZE];
__device__ float g_CB    [(size_t)BATCH * NCHUNK * CSIZE * CSIZE];
__device__ float g_states[(size_t)BATCH * NCHUNK * NHEADS * HDIM * NSTATE];
__device__ float g_prev  [(size_t)BATCH * NCHUNK * NHEADS * HDIM * NSTATE];
__device__ float g_Y     [(size_t)BL * INTERD];
// bf16 split-K operands (hi/lo/hi stacking; K' = 3K)
__device__ __nv_bfloat16 g_A2   [(size_t)BL * 3 * DMODEL];
__device__ __nv_bfloat16 g_Win2 [(size_t)PROJDIM * 3 * DMODEL];
__device__ __nv_bfloat16 g_Y2   [(size_t)BL * 3 * INTERD];
__device__ __nv_bfloat16 g_Wout2[(size_t)DMODEL * 3 * INTERD];

// =====================================================================
// mma.sync bf16 GEMM machinery (plain sm_103-target-safe PTX only)
// =====================================================================
__device__ __forceinline__ uint32_t smem_u32(const void* p) {
    return (uint32_t)__cvta_generic_to_shared(p);
}
#define SW128(o) ((o) ^ (((o) >> 3) & 0x70))

__device__ __forceinline__ void cp_async16(uint32_t d, const void* g, int sz) {
    asm volatile("cp.async.cg.shared.global [%0], [%1], 16, %2;"
                 :: "r"(d), "l"(g), "r"(sz) : "memory");
}
#define CP_COMMIT() asm volatile("cp.async.commit_group;" ::: "memory")
#define CP_WAIT1()  asm volatile("cp.async.wait_group 1;" ::: "memory")
#define CP_WAIT0()  asm volatile("cp.async.wait_group 0;" ::: "memory")

__device__ __forceinline__ void ldsm4(uint32_t& r0, uint32_t& r1, uint32_t& r2,
                                      uint32_t& r3, uint32_t a) {
    asm volatile("ldmatrix.sync.aligned.m8n8.x4.shared.b16 {%0,%1,%2,%3}, [%4];"
                 : "=r"(r0), "=r"(r1), "=r"(r2), "=r"(r3) : "r"(a));
}
__device__ __forceinline__ void mma16816(float* c, const uint32_t* a, const uint32_t* b) {
    asm volatile(
        "mma.sync.aligned.m16n8k16.row.col.f32.bf16.bf16.f32 "
        "{%0,%1,%2,%3}, {%4,%5,%6,%7}, {%8,%9}, {%0,%1,%2,%3};"
        : "+f"(c[0]), "+f"(c[1]), "+f"(c[2]), "+f"(c[3])
        : "r"(a[0]), "r"(a[1]), "r"(a[2]), "r"(a[3]), "r"(b[0]), "r"(b[1]));
}

// C[M,N] = A[M,K]*B[N,K]^T, fp32 accum. BM=BN=128, BK=64, 3 stages, 256 thr.
#define TSTAGE_B 32768            // A tile 16384 + B tile 16384
#define TSMEM    (3 * TSTAGE_B)   // 98304

__global__ void __launch_bounds__(256, 1) gemm_bf16_mma(
    const __nv_bfloat16* __restrict__ A, const __nv_bfloat16* __restrict__ Bm,
    float* __restrict__ C, int M, int N, int K, int ldc)
{
    extern __shared__ __align__(1024) char smem[];
    const uint32_t sbase = smem_u32(smem);
    const int tid  = threadIdx.x;
    const int wid  = tid >> 5, lane = tid & 31;
    const int bm   = blockIdx.x * 128, bn = blockIdx.y * 128;
    const int wm   = (wid & 1) * 64;
    const int wn   = (wid >> 1) * 32;
    const int KT   = K >> 6;

    // precompute per-thread load coords
    const int lr = tid >> 3;         // 0..31 (row step 32)
    const int lu = tid & 7;          // 16B unit within 128B row

    float c[4][4][4];
#pragma unroll
    for (int mt = 0; mt < 4; ++mt)
#pragma unroll
        for (int nt = 0; nt < 4; ++nt)
#pragma unroll
            for (int q = 0; q < 4; ++q) c[mt][nt][q] = 0.f;

#define LOAD_STAGE(kt, s) do {                                               \
    uint32_t st_ = sbase + (s) * TSTAGE_B;                                   \
    _Pragma("unroll")                                                        \
    for (int i_ = 0; i_ < 4; ++i_) {                                         \
        int r_ = lr + i_ * 32;                                               \
        uint32_t d_ = st_ + SW128((uint32_t)(r_ * 128 + lu * 16));           \
        const void* g_ = (const char*)A +                                    \
            (((size_t)(bm + r_) * K + (size_t)(kt) * 64 + lu * 8) << 1);     \
        cp_async16(d_, g_, 16);                                              \
    }                                                                        \
    _Pragma("unroll")                                                        \
    for (int i_ = 0; i_ < 4; ++i_) {                                         \
        int r_ = lr + i_ * 32;                                               \
        int gn_ = bn + r_;                                                   \
        uint32_t d_ = st_ + 16384 + SW128((uint32_t)(r_ * 128 + lu * 16));   \
        const void* g_ = (const char*)Bm +                                   \
            (((size_t)gn_ * K + (size_t)(kt) * 64 + lu * 8) << 1);           \
        cp_async16(d_, g_, gn_ < N ? 16 : 0);                                \
    }                                                                        \
} while (0)

    LOAD_STAGE(0, 0); CP_COMMIT();
    LOAD_STAGE(1, 1); CP_COMMIT();

    // ldmatrix per-thread offsets (byte offsets within tile, pre-swizzle parts)
    const int a_row = (lane & 15);            // + wm + mt*16
    const int a_ku  = (lane >> 4) * 16;       // byte
    const int b_row = ((lane >> 4) & 1) * 8 + (lane & 7);  // + wn + pr*16
    const int b_ku  = ((lane >> 3) & 1) * 16;

    for (int kt = 0; kt < KT; ++kt) {
        const int s = kt % 3;
        CP_WAIT1();
        __syncthreads();
        if (kt + 2 < KT) LOAD_STAGE(kt + 2, (kt + 2) % 3);
        CP_COMMIT();

        const uint32_t stA = sbase + s * TSTAGE_B;
        const uint32_t stB = stA + 16384;
#pragma unroll
        for (int ks = 0; ks < 4; ++ks) {
            uint32_t a[4][4], b[4][2];
#pragma unroll
            for (int mt = 0; mt < 4; ++mt) {
                uint32_t off = (uint32_t)((wm + mt * 16 + a_row) * 128 + ks * 32 + a_ku);
                ldsm4(a[mt][0], a[mt][1], a[mt][2], a[mt][3], stA + SW128(off));
            }
#pragma unroll
            for (int pr = 0; pr < 2; ++pr) {
                uint32_t off = (uint32_t)((wn + pr * 16 + b_row) * 128 + ks * 32 + b_ku);
                uint32_t r0, r1, r2, r3;
                ldsm4(r0, r1, r2, r3, stB + SW128(off));
                b[pr * 2][0] = r0; b[pr * 2][1] = r1;
                b[pr * 2 + 1][0] = r2; b[pr * 2 + 1][1] = r3;
            }
#pragma unroll
            for (int mt = 0; mt < 4; ++mt)
#pragma unroll
                for (int nt = 0; nt < 4; ++nt)
                    mma16816(c[mt][nt], a[mt], b[nt]);
        }
    }

    // epilogue
#pragma unroll
    for (int mt = 0; mt < 4; ++mt) {
        int r0 = bm + wm + mt * 16 + (lane >> 2);
#pragma unroll
        for (int nt = 0; nt < 4; ++nt) {
            int col = bn + wn + nt * 8 + (lane & 3) * 2;
            if (col < N) {
                float2 v0 = make_float2(c[mt][nt][0], c[mt][nt][1]);
                float2 v1 = make_float2(c[mt][nt][2], c[mt][nt][3]);
                *(float2*)&C[(size_t)r0 * ldc + col] = v0;
                *(float2*)&C[(size_t)(r0 + 8) * ldc + col] = v1;
            }
        }
    }
}

// ---------------- fp32 -> bf16 hi/lo split with K-stacking ----------------
__global__ void split_bf16_kernel(const float* __restrict__ src,
                                  __nv_bfloat16* __restrict__ dst,
                                  int K, int isA, long long total4)
{
    long long t = (long long)blockIdx.x * blockDim.x + threadIdx.x;
    if (t >= total4) return;
    int K4 = K >> 2;
    long long m = t / K4;
    int k = (int)(t % K4) << 2;
    float4 a = *(const float4*)(src + m * K + k);
    float av[4] = {a.x, a.y, a.z, a.w};
    __nv_bfloat16 h[4], l[4];
#pragma unroll
    for (int i = 0; i < 4; ++i) {
        h[i] = __float2bfloat16(av[i]);
        l[i] = __float2bfloat16(av[i] - __bfloat162float(h[i]));
    }
    __nv_bfloat162 h01, h23, l01, l23;
    h01.x = h[0]; h01.y = h[1]; h23.x = h[2]; h23.y = h[3];
    l01.x = l[0]; l01.y = l[1]; l23.x = l[2]; l23.y = l[3];
    uint2 vh, vl;
    vh.x = *(uint32_t*)&h01; vh.y = *(uint32_t*)&h23;
    vl.x = *(uint32_t*)&l01; vl.y = *(uint32_t*)&l23;
    __nv_bfloat16* row = dst + m * 3 * (long long)K;
    *(uint2*)(row + k)         = vh;
    *(uint2*)(row + K + k)     = isA ? vl : vh;
    *(uint2*)(row + 2 * K + k) = isA ? vh : vl;
}

// ---------------- depthwise causal conv (K=4) + bias + silu ----------------
__global__ void conv_silu_kernel(const float* __restrict__ proj,
                                 const float* __restrict__ cw,
                                 const float* __restrict__ cb,
                                 float* __restrict__ xBC)
{
    int idx = blockIdx.x * blockDim.x + threadIdx.x;
    if (idx >= BL * CONVDIM) return;
    int ch = idx % CONVDIM;
    int bl = idx / CONVDIM;
    int l  = bl % LSEQ;
    float4 w = *(const float4*)&cw[ch * 4];
    float acc = cb[ch];
    const float* base = proj + (size_t)bl * PROJDIM + INTERD + ch;
    if (l >= 3) {
        acc += w.x * base[-3 * PROJDIM] + w.y * base[-2 * PROJDIM]
             + w.z * base[-1 * PROJDIM] + w.w * base[0];
    } else {
        float wk[4] = {w.x, w.y, w.z, w.w};
        for (int k = 3 - l; k < 4; ++k) acc += wk[k] * base[(k - 3) * PROJDIM];
    }
    xBC[idx] = acc / (1.f + expf(-acc));
}

// ---------------- softplus(dt+bias), per-chunk inclusive cumsum of dA ----------------
__global__ void dt_acum_kernel(const float* __restrict__ proj,
                               const float* __restrict__ dt_bias,
                               const float* __restrict__ A_log,
                               float* __restrict__ dtv,
                               float* __restrict__ Acum)
{
    int cc = blockIdx.x, h = blockIdx.y, b = blockIdx.z;
    int i  = threadIdx.x;
    int l  = cc * CSIZE + i;
    float d  = proj[(size_t)(b * LSEQ + l) * PROJDIM + INTERD + CONVDIM + h] + dt_bias[h];
    float sp = (d > 20.f) ? d : log1pf(expf(d));
    dtv[(size_t)(b * LSEQ + l) * NHEADS + h] = sp;
    float dA = sp * (-expf(A_log[h]));
    __shared__ float sbuf[CSIZE];
    sbuf[i] = dA;
    __syncthreads();
    for (int off = 1; off < CSIZE; off <<= 1) {
        float v = sbuf[i];
        if (i >= off) v += sbuf[i - off];
        __syncthreads();
        sbuf[i] = v;
        __syncthreads();
    }
    Acum[(((size_t)b * NHEADS + h) * NCHUNK + cc) * CSIZE + i] = sbuf[i];
}

// ---------------- generic NT SGEMM (small CB gemm only) ----------------
__global__ __launch_bounds__(256) void sgemm_nt(
    const float* __restrict__ A, const float* __restrict__ B, float* __restrict__ C,
    int M, int N, int K, int lda, int ldb, int ldc,
    long long sA, long long sB, long long sC)
{
    A += (long long)blockIdx.z * sA;
    B += (long long)blockIdx.z * sB;
    C += (long long)blockIdx.z * sC;
    const int bm = blockIdx.y * 128, bn = blockIdx.x * 128;
    __shared__ float As[16][128];
    __shared__ float Bs[16][128];
    const int tid = threadIdx.x;
    const int lr = tid >> 2;
    const int lc = (tid & 3) << 2;
    const int tx = tid & 15, ty = tid >> 4;

    float acc[8][8];
#pragma unroll
    for (int i = 0; i < 8; ++i)
#pragma unroll
        for (int j = 0; j < 8; ++j) acc[i][j] = 0.f;

    for (int k0 = 0; k0 < K; k0 += 16) {
#pragma unroll
        for (int r = 0; r < 2; ++r) {
            int row = lr + r * 64;
            int gr  = bm + row;
            float4 v = make_float4(0.f, 0.f, 0.f, 0.f);
            if (gr < M) v = *(const float4*)&A[(long long)gr * lda + k0 + lc];
            As[lc + 0][row] = v.x; As[lc + 1][row] = v.y;
            As[lc + 2][row] = v.z; As[lc + 3][row] = v.w;
        }
#pragma unroll
        for (int r = 0; r < 2; ++r) {
            int row = lr + r * 64;
            int gr  = bn + row;
            float4 v = make_float4(0.f, 0.f, 0.f, 0.f);
            if (gr < N) v = *(const float4*)&B[(long long)gr * ldb + k0 + lc];
            Bs[lc + 0][row] = v.x; Bs[lc + 1][row] = v.y;
            Bs[lc + 2][row] = v.z; Bs[lc + 3][row] = v.w;
        }
        __syncthreads();
#pragma unroll
        for (int k = 0; k < 16; ++k) {
            float a[8], b[8];
            *(float4*)&a[0] = *(const float4*)&As[k][ty * 8];
            *(float4*)&a[4] = *(const float4*)&As[k][ty * 8 + 4];
            *(float4*)&b[0] = *(const float4*)&Bs[k][tx * 8];
            *(float4*)&b[4] = *(const float4*)&Bs[k][tx * 8 + 4];
#pragma unroll
            for (int ii = 0; ii < 8; ++ii)
#pragma unroll
                for (int jj = 0; jj < 8; ++jj) acc[ii][jj] += a[ii] * b[jj];
        }
        __syncthreads();
    }
#pragma unroll
    for (int ii = 0; ii < 8; ++ii) {
        int gr = bm + ty * 8 + ii;
        if (gr >= M) continue;
#pragma unroll
        for (int jj = 0; jj < 8; ++jj) {
            int gc = bn + tx * 8 + jj;
            if (gc < N) C[(long long)gr * ldc + gc] = acc[ii][jj];
        }
    }
}

// ---------------- per (b,h,chunk): states[p,n] = sum_j w_j * x[j,p] * B[j,n] ----------------
__global__ __launch_bounds__(256) void states_kernel(
    const float* __restrict__ xBC, const float* __restrict__ dtv,
    const float* __restrict__ Acum, float* __restrict__ states)
{
    int cc = blockIdx.x, h = blockIdx.y, b = blockIdx.z;
    int tid = threadIdx.x;
    int tn = tid & 15, tp = tid >> 4;
    __shared__ float Bs[16][128];
    __shared__ float wxs[16][64];
    const float* Ab = Acum + (((size_t)b * NHEADS + h) * NCHUNK + cc) * CSIZE;
    float AcLast = Ab[CSIZE - 1];
    float acc[4][8];
#pragma unroll
    for (int p = 0; p < 4; ++p)
#pragma unroll
        for (int n = 0; n < 8; ++n) acc[p][n] = 0.f;
    int l0 = b * LSEQ + cc * CSIZE;
    for (int jt = 0; jt < CSIZE; jt += 16) {
#pragma unroll
        for (int r = 0; r < 2; ++r) {
            int f  = tid + r * 256;
            int jr = f >> 5;
            int n4 = f & 31;
            *(float4*)&Bs[jr][n4 * 4] =
                *(const float4*)&xBC[(size_t)(l0 + jt + jr) * CONVDIM + INTERD + n4 * 4];
        }
        {
            int jr = tid >> 4, p4 = tid & 15;
            int j  = jt + jr;
            float w = expf(AcLast - Ab[j]) * dtv[(size_t)(l0 + j) * NHEADS + h];
            float4 xv = *(const float4*)&xBC[(size_t)(l0 + j) * CONVDIM + h * HDIM + p4 * 4];
            xv.x *= w; xv.y *= w; xv.z *= w; xv.w *= w;
            *(float4*)&wxs[jr][p4 * 4] = xv;
        }
        __syncthreads();
#pragma unroll
        for (int j = 0; j < 16; ++j) {
            float bx[8], px[4];
            *(float4*)&bx[0] = *(const float4*)&Bs[j][tn * 8];
            *(float4*)&bx[4] = *(const float4*)&Bs[j][tn * 8 + 4];
            *(float4*)&px[0] = *(const float4*)&wxs[j][tp * 4];
#pragma unroll
            for (int p = 0; p < 4; ++p)
#pragma unroll
                for (int n = 0; n < 8; ++n) acc[p][n] += px[p] * bx[n];
        }
        __syncthreads();
    }
    float* so = states + (((size_t)b * NCHUNK + cc) * NHEADS + h) * (HDIM * NSTATE);
#pragma unroll
    for (int p = 0; p < 4; ++p) {
#pragma unroll
        for (int n = 0; n < 8; n += 4) {
            float4 v = make_float4(acc[p][n], acc[p][n + 1], acc[p][n + 2], acc[p][n + 3]);
            *(float4*)&so[(tp * 4 + p) * NSTATE + tn * 8 + n] = v;
        }
    }
}

// ---------------- inter-chunk recurrence (scan over 8 chunks) ----------------
__global__ void scan_kernel(const float* __restrict__ states,
                            const float* __restrict__ Acum,
                            float* __restrict__ prev)
{
    int h = blockIdx.x, b = blockIdx.y, tid = threadIdx.x;
    float carry[32];
#pragma unroll
    for (int t = 0; t < 32; ++t) carry[t] = 0.f;
    for (int cc = 0; cc < NCHUNK; ++cc) {
        float cd = expf(Acum[(((size_t)b * NHEADS + h) * NCHUNK + cc) * CSIZE + CSIZE - 1]);
        size_t base = (((size_t)b * NCHUNK + cc) * NHEADS + h) * (HDIM * NSTATE);
#pragma unroll
        for (int t = 0; t < 32; ++t) {
            size_t idx = base + tid + t * 256;
            prev[idx]  = carry[t];
            carry[t]   = cd * carry[t] + states[idx];
        }
    }
}

// ---------------- per (b,h,chunk): Ydiag + Yoff + D*x -> Y ----------------
__global__ __launch_bounds__(256) void y_kernel(
    const float* __restrict__ xBC, const float* __restrict__ dtv,
    const float* __restrict__ Acum, const float* __restrict__ CB,
    const float* __restrict__ prev, const float* __restrict__ Dp,
    float* __restrict__ Y)
{
    int cc = blockIdx.x, h = blockIdx.y, b = blockIdx.z;
    int i  = threadIdx.x;
    __shared__ float dts[CSIZE], Ac[CSIZE];
    __shared__ float xs[16][64];
    __shared__ float prevs[HDIM * NSTATE];
    int l0 = b * LSEQ + cc * CSIZE;
    dts[i] = dtv[(size_t)(l0 + i) * NHEADS + h];
    Ac[i]  = Acum[(((size_t)b * NHEADS + h) * NCHUNK + cc) * CSIZE + i];
    __syncthreads();
    float Ai = Ac[i];
    float y[64];
#pragma unroll
    for (int p = 0; p < 64; ++p) y[p] = 0.f;
    const float* CBrow = CB + (((size_t)b * NCHUNK + cc) * CSIZE + i) * CSIZE;

    for (int jt = 0; jt < CSIZE; jt += 16) {
        {
            int jr = threadIdx.x >> 4, p4 = threadIdx.x & 15;
            *(float4*)&xs[jr][p4 * 4] =
                *(const float4*)&xBC[(size_t)(l0 + jt + jr) * CONVDIM + h * HDIM + p4 * 4];
        }
        __syncthreads();
        if (i >= jt) {
            int jmax = i - jt + 1;
            if (jmax > 16) jmax = 16;
            for (int jl = 0; jl < jmax; ++jl) {
                int j = jt + jl;
                float coef = CBrow[j] * expf(Ai - Ac[j]) * dts[j];
#pragma unroll
                for (int p4 = 0; p4 < 16; ++p4) {
                    float4 xv = *(const float4*)&xs[jl][p4 * 4];
                    y[p4 * 4 + 0] += coef * xv.x;
                    y[p4 * 4 + 1] += coef * xv.y;
                    y[p4 * 4 + 2] += coef * xv.z;
                    y[p4 * 4 + 3] += coef * xv.w;
                }
            }
        }
        __syncthreads();
    }

    {
        const float4* src =
            (const float4*)(prev + (((size_t)b * NCHUNK + cc) * NHEADS + h) * (HDIM * NSTATE));
        float4* dst = (float4*)prevs;
        for (int f = threadIdx.x; f < (HDIM * NSTATE) / 4; f += 256) dst[f] = src[f];
    }
    __syncthreads();
    float eAi = expf(Ai);
    const float* Crow = xBC + (size_t)(l0 + i) * CONVDIM + INTERD + NSTATE;
    for (int nt = 0; nt < NSTATE; nt += 8) {
        float cf[8];
#pragma unroll
        for (int q = 0; q < 8; ++q) cf[q] = eAi * Crow[nt + q];
#pragma unroll
        for (int p = 0; p < 64; ++p) {
            const float* pr = &prevs[p * NSTATE + nt];
            float4 v0 = *(const float4*)pr;
            float4 v1 = *(const float4*)(pr + 4);
            y[p] += cf[0] * v0.x + cf[1] * v0.y + cf[2] * v0.z + cf[3] * v0.w
                  + cf[4] * v1.x + cf[5] * v1.y + cf[6] * v1.z + cf[7] * v1.w;
        }
    }

    float Dh = Dp[h];
    float* yo = Y + (size_t)(l0 + i) * INTERD + h * HDIM;
    const float* xr = xBC + (size_t)(l0 + i) * CONVDIM + h * HDIM;
#pragma unroll
    for (int p4 = 0; p4 < 16; ++p4) {
        float4 xv = *(const float4*)&xr[p4 * 4];
        float4 ov;
        ov.x = y[p4 * 4 + 0] + Dh * xv.x;
        ov.y = y[p4 * 4 + 1] + Dh * xv.y;
        ov.z = y[p4 * 4 + 2] + Dh * xv.z;
        ov.w = y[p4 * 4 + 3] + Dh * xv.w;
        *(float4*)&yo[p4 * 4] = ov;
    }
}

// ---------------- gate (silu) + RMSNorm -> bf16 hi/lo stacked Y2 ----------------
__global__ void gate_rms_kernel(const float* __restrict__ proj,
                                const float* __restrict__ norm_w,
                                const float* __restrict__ Y,
                                __nv_bfloat16* __restrict__ Y2)
{
    int row = blockIdx.x, tid = threadIdx.x;
    const float* gr = proj + (size_t)row * PROJDIM;
    const float* yr = Y + (size_t)row * INTERD;
    float yv[16];
    float ss = 0.f;
#pragma unroll
    for (int t = 0; t < 16; ++t) {
        int e = tid + t * 256;
        float g = gr[e];
        float v = yr[e] * (g / (1.f + expf(-g)));
        yv[t] = v;
        ss += v * v;
    }
    __shared__ float red[8];
#pragma unroll
    for (int o = 16; o > 0; o >>= 1) ss += __shfl_xor_sync(0xffffffff, ss, o);
    if ((tid & 31) == 0) red[tid >> 5] = ss;
    __syncthreads();
    float tot = 0.f;
#pragma unroll
    for (int w = 0; w < 8; ++w) tot += red[w];
    float scale = rsqrtf(tot / (float)INTERD + EPSV);
    __nv_bfloat16* y2r = Y2 + (size_t)row * 3 * INTERD;
#pragma unroll
    for (int t = 0; t < 16; ++t) {
        int e = tid + t * 256;
        float v = yv[t] * scale * norm_w[e];
        __nv_bfloat16 h = __float2bfloat16(v);
        __nv_bfloat16 l = __float2bfloat16(v - __bfloat162float(h));
        y2r[e] = h;
        y2r[INTERD + e] = l;
        y2r[2 * INTERD + e] = h;
    }
}

// ---------------- launch ----------------
extern "C" void kernel_launch(void* const* d_in, const int* in_sizes, int n_in,
                              void* d_out, int out_size)
{
    const float* hs      = (const float*)d_in[0];
    const float* W_in    = (const float*)d_in[1];
    const float* conv_w  = (const float*)d_in[2];
    const float* conv_b  = (const float*)d_in[3];
    const float* dt_bias = (const float*)d_in[4];
    const float* A_log   = (const float*)d_in[5];
    const float* Dp      = (const float*)d_in[6];
    const float* norm_w  = (const float*)d_in[7];
    const float* W_out   = (const float*)d_in[8];
    float* out = (float*)d_out;

    float *proj, *xBC, *dtv, *Acum, *CB, *states, *prev, *Y;
    __nv_bfloat16 *A2, *Win2, *Y2, *Wout2;
    cudaGetSymbolAddress((void**)&proj,   g_proj);
    cudaGetSymbolAddress((void**)&xBC,    g_xBC);
    cudaGetSymbolAddress((void**)&dtv,    g_dtv);
    cudaGetSymbolAddress((void**)&Acum,   g_Acum);
    cudaGetSymbolAddress((void**)&CB,     g_CB);
    cudaGetSymbolAddress((void**)&states, g_states);
    cudaGetSymbolAddress((void**)&prev,   g_prev);
    cudaGetSymbolAddress((void**)&Y,      g_Y);
    cudaGetSymbolAddress((void**)&A2,     g_A2);
    cudaGetSymbolAddress((void**)&Win2,   g_Win2);
    cudaGetSymbolAddress((void**)&Y2,     g_Y2);
    cudaGetSymbolAddress((void**)&Wout2,  g_Wout2);

    cudaFuncSetAttribute(gemm_bf16_mma,
                         cudaFuncAttributeMaxDynamicSharedMemorySize, TSMEM);

    // 0) split fp32 -> bf16 hi/lo (K-stacked)
    {
        long long t4;
        t4 = (long long)BL * DMODEL / 4;
        split_bf16_kernel<<<(unsigned)((t4 + 255) / 256), 256>>>(hs, A2, DMODEL, 1, t4);
        t4 = (long long)PROJDIM * DMODEL / 4;
        split_bf16_kernel<<<(unsigned)((t4 + 255) / 256), 256>>>(W_in, Win2, DMODEL, 0, t4);
        t4 = (long long)DMODEL * INTERD / 4;
        split_bf16_kernel<<<(unsigned)((t4 + 255) / 256), 256>>>(W_out, Wout2, INTERD, 0, t4);
    }

    // 1) proj = hs @ W_in^T via mma.sync bf16 split-K (K'=6144)
    gemm_bf16_mma<<<dim3(BL / 128, (PROJDIM + 127) / 128), 256, TSMEM>>>(
        A2, Win2, proj, BL, PROJDIM, 3 * DMODEL, PROJDIM);

    // 2) depthwise causal conv + silu -> xBC
    {
        int total = BL * CONVDIM;
        conv_silu_kernel<<<(total + 255) / 256, 256>>>(proj, conv_w, conv_b, xBC);
    }

    // 3) softplus(dt) + per-chunk cumsum of dA
    dt_acum_kernel<<<dim3(NCHUNK, NHEADS, BATCH), CSIZE>>>(proj, dt_bias, A_log, dtv, Acum);

    // 4) CB[b,c,i,j] = C_i . B_j  (shared across all heads, G=1)
    sgemm_nt<<<dim3(2, 2, BATCH * NCHUNK), 256>>>(
        xBC + (INTERD + NSTATE), xBC + INTERD, CB,
        CSIZE, CSIZE, NSTATE, CONVDIM, CONVDIM, CSIZE,
        (long long)CSIZE * CONVDIM, (long long)CSIZE * CONVDIM, (long long)CSIZE * CSIZE);

    // 5) per-chunk states
    states_kernel<<<dim3(NCHUNK, NHEADS, BATCH), 256>>>(xBC, dtv, Acum, states);

    // 6) inter-chunk scan -> prev
    scan_kernel<<<dim3(NHEADS, BATCH), 256>>>(states, Acum, prev);

    // 7) Ydiag + Yoff + D*x -> Y
    y_kernel<<<dim3(NCHUNK, NHEADS, BATCH), CSIZE>>>(xBC, dtv, Acum, CB, prev, Dp, Y);

    // 8) gate + RMSNorm -> Y2 (bf16 hi/lo stacked)
    gate_rms_kernel<<<BL, 256>>>(proj, norm_w, Y, Y2);

    // 9) out = Y @ W_out^T via mma.sync bf16 split-K (K'=12288)
    gemm_bf16_mma<<<dim3(BL / 128, DMODEL / 128), 256, TSMEM>>>(
        Y2, Wout2, out, BL, DMODEL, 3 * INTERD, DMODEL);
}

// round 4
// speedup vs baseline: 2.9490x; 1.3105x over previous
#include <cuda_runtime.h>
#include <cuda_fp16.h>
#include <cstdint>

// ---------------- problem constants ----------------
#define BATCH    2
#define LSEQ     2048
#define DMODEL   2048
#define INTERD   4096
#define NHEADS   64
#define HDIM     64
#define NSTATE   128
#define KCONV    4
#define CSIZE    256
#define NCHUNK   (LSEQ / CSIZE)                 // 8
#define CONVDIM  (INTERD + 2 * NSTATE)          // 4352
#define PROJDIM  (INTERD + CONVDIM + NHEADS)    // 8512
#define BL       (BATCH * LSEQ)                 // 4096
#define EPSV     1e-5f

// ---------------- device scratch (static; no allocs allowed) ----------------
__device__ float g_proj  [(size_t)BL * PROJDIM];
__device__ float g_xBC   [(size_t)BL * CONVDIM];
__device__ float g_dtv   [(size_t)BL * NHEADS];
__device__ float g_Acum  [(size_t)BATCH * NHEADS * NCHUNK * CSIZE];
__device__ float g_CB    [(size_t)BATCH * NCHUNK * CSIZE * CSIZE];
__device__ float g_states[(size_t)BATCH * NCHUNK * NHEADS * HDIM * NSTATE];
__device__ float g_prev  [(size_t)BATCH * NCHUNK * NHEADS * HDIM * NSTATE];
__device__ float g_Y     [(size_t)BL * INTERD];
// fp16 split-K operands (A side: [hi, lo]; B side: [hi, hi]; K' = 2K)
__device__ __half g_A2   [(size_t)BL * 2 * DMODEL];
__device__ __half g_Win2 [(size_t)PROJDIM * 2 * DMODEL];
__device__ __half g_Y2   [(size_t)BL * 2 * INTERD];
__device__ __half g_Wout2[(size_t)DMODEL * 2 * INTERD];

// =====================================================================
// mma.sync fp16 GEMM machinery (plain sm_103-target-safe PTX only)
// =====================================================================
__device__ __forceinline__ uint32_t smem_u32(const void* p) {
    return (uint32_t)__cvta_generic_to_shared(p);
}
#define SW128(o) ((o) ^ (((o) >> 3) & 0x70))

__device__ __forceinline__ void cp_async16(uint32_t d, const void* g, int sz) {
    asm volatile("cp.async.cg.shared.global [%0], [%1], 16, %2;"
                 :: "r"(d), "l"(g), "r"(sz) : "memory");
}
#define CP_COMMIT() asm volatile("cp.async.commit_group;" ::: "memory")
#define CP_WAIT2()  asm volatile("cp.async.wait_group 2;" ::: "memory")

__device__ __forceinline__ void ldsm4(uint32_t& r0, uint32_t& r1, uint32_t& r2,
                                      uint32_t& r3, uint32_t a) {
    asm volatile("ldmatrix.sync.aligned.m8n8.x4.shared.b16 {%0,%1,%2,%3}, [%4];"
                 : "=r"(r0), "=r"(r1), "=r"(r2), "=r"(r3) : "r"(a));
}
__device__ __forceinline__ void mma16816(float* c, const uint32_t* a, const uint32_t* b) {
    asm volatile(
        "mma.sync.aligned.m16n8k16.row.col.f32.f16.f16.f32 "
        "{%0,%1,%2,%3}, {%4,%5,%6,%7}, {%8,%9}, {%0,%1,%2,%3};"
        : "+f"(c[0]), "+f"(c[1]), "+f"(c[2]), "+f"(c[3])
        : "r"(a[0]), "r"(a[1]), "r"(a[2]), "r"(a[3]), "r"(b[0]), "r"(b[1]));
}

// C[M,N] = A[M,K]*B[N,K]^T, fp32 accum. BM=128, BN=256, BK=64, 4 stages, 256 thr.
#define TSTAGE_B (128 * 128 + 256 * 128)     // 49152
#define TNSTG    4
#define TSMEM    (TNSTG * TSTAGE_B)          // 196608

__global__ void __launch_bounds__(256, 1) gemm_fp16_mma(
    const __half* __restrict__ A, const __half* __restrict__ Bm,
    float* __restrict__ C, int M, int N, int K, int ldc)
{
    extern __shared__ __align__(1024) char smem[];
    const uint32_t sbase = smem_u32(smem);
    const int tid  = threadIdx.x;
    const int wid  = tid >> 5, lane = tid & 31;
    const int bm   = blockIdx.x * 128, bn = blockIdx.y * 256;
    const int wm   = (wid & 1) * 64;          // 2 warps over M
    const int wn   = (wid >> 1) * 64;         // 4 warps over N
    const int KT   = K >> 6;

    const int lr = tid >> 3;                  // 0..31
    const int lu = tid & 7;                   // 16B unit in 128B row

    float c[4][8][4];
#pragma unroll
    for (int mt = 0; mt < 4; ++mt)
#pragma unroll
        for (int nt = 0; nt < 8; ++nt)
#pragma unroll
            for (int q = 0; q < 4; ++q) c[mt][nt][q] = 0.f;

#define LOAD_STAGE(kt, s) do {                                               \
    uint32_t st_ = sbase + (s) * TSTAGE_B;                                   \
    _Pragma("unroll")                                                        \
    for (int i_ = 0; i_ < 4; ++i_) {                                         \
        int r_ = lr + i_ * 32;                                               \
        uint32_t d_ = st_ + SW128((uint32_t)(r_ * 128 + lu * 16));           \
        const void* g_ = (const char*)A +                                    \
            (((size_t)(bm + r_) * K + (size_t)(kt) * 64 + lu * 8) << 1);     \
        cp_async16(d_, g_, 16);                                              \
    }                                                                        \
    _Pragma("unroll")                                                        \
    for (int i_ = 0; i_ < 8; ++i_) {                                         \
        int r_ = lr + i_ * 32;                                               \
        int gn_ = bn + r_;                                                   \
        uint32_t d_ = st_ + 16384 + SW128((uint32_t)(r_ * 128 + lu * 16));   \
        const void* g_ = (const char*)Bm +                                   \
            (((size_t)gn_ * K + (size_t)(kt) * 64 + lu * 8) << 1);           \
        cp_async16(d_, g_, gn_ < N ? 16 : 0);                                \
    }                                                                        \
} while (0)

    LOAD_STAGE(0, 0); CP_COMMIT();
    LOAD_STAGE(1, 1); CP_COMMIT();
    LOAD_STAGE(2, 2); CP_COMMIT();

    const int a_row = (lane & 15);
    const int a_ku  = (lane >> 4) * 16;
    const int b_row = ((lane >> 4) & 1) * 8 + (lane & 7);
    const int b_ku  = ((lane >> 3) & 1) * 16;

    for (int kt = 0; kt < KT; ++kt) {
        const int s = kt & 3;
        CP_WAIT2();
        __syncthreads();
        if (kt + 3 < KT) LOAD_STAGE(kt + 3, (kt + 3) & 3);
        CP_COMMIT();

        const uint32_t stA = sbase + s * TSTAGE_B;
        const uint32_t stB = stA + 16384;
#pragma unroll
        for (int ks = 0; ks < 4; ++ks) {
            uint32_t a[4][4], b[8][2];
#pragma unroll
            for (int mt = 0; mt < 4; ++mt) {
                uint32_t off = (uint32_t)((wm + mt * 16 + a_row) * 128 + ks * 32 + a_ku);
                ldsm4(a[mt][0], a[mt][1], a[mt][2], a[mt][3], stA + SW128(off));
            }
#pragma unroll
            for (int pr = 0; pr < 4; ++pr) {
                uint32_t off = (uint32_t)((wn + pr * 16 + b_row) * 128 + ks * 32 + b_ku);
                uint32_t r0, r1, r2, r3;
                ldsm4(r0, r1, r2, r3, stB + SW128(off));
                b[pr * 2][0] = r0; b[pr * 2][1] = r1;
                b[pr * 2 + 1][0] = r2; b[pr * 2 + 1][1] = r3;
            }
#pragma unroll
            for (int mt = 0; mt < 4; ++mt)
#pragma unroll
                for (int nt = 0; nt < 8; ++nt)
                    mma16816(c[mt][nt], a[mt], b[nt]);
        }
    }

    // epilogue
#pragma unroll
    for (int mt = 0; mt < 4; ++mt) {
        int r0 = bm + wm + mt * 16 + (lane >> 2);
#pragma unroll
        for (int nt = 0; nt < 8; ++nt) {
            int col = bn + wn + nt * 8 + (lane & 3) * 2;
            if (col < N) {
                float2 v0 = make_float2(c[mt][nt][0], c[mt][nt][1]);
                float2 v1 = make_float2(c[mt][nt][2], c[mt][nt][3]);
                *(float2*)&C[(size_t)r0 * ldc + col] = v0;
                *(float2*)&C[(size_t)(r0 + 8) * ldc + col] = v1;
            }
        }
    }
}

// ---------------- fp32 -> fp16 hi/lo split with K-stacking ----------------
// dst[m, 0:K)  = hi(src);  dst[m, K:2K) = isA ? lo(src) : hi(src)
__global__ void split_fp16_kernel(const float* __restrict__ src,
                                  __half* __restrict__ dst,
                                  int K, int isA, long long total4)
{
    long long t = (long long)blockIdx.x * blockDim.x + threadIdx.x;
    if (t >= total4) return;
    int K4 = K >> 2;
    long long m = t / K4;
    int k = (int)(t % K4) << 2;
    float4 a = *(const float4*)(src + m * K + k);
    float av[4] = {a.x, a.y, a.z, a.w};
    __half h[4], l[4];
#pragma unroll
    for (int i = 0; i < 4; ++i) {
        h[i] = __float2half(av[i]);
        l[i] = __float2half(av[i] - __half2float(h[i]));
    }
    uint2 vh, vl;
    vh.x = ((uint32_t)*(uint16_t*)&h[1] << 16) | *(uint16_t*)&h[0];
    vh.y = ((uint32_t)*(uint16_t*)&h[3] << 16) | *(uint16_t*)&h[2];
    vl.x = ((uint32_t)*(uint16_t*)&l[1] << 16) | *(uint16_t*)&l[0];
    vl.y = ((uint32_t)*(uint16_t*)&l[3] << 16) | *(uint16_t*)&l[2];
    __half* row = dst + m * 2 * (long long)K;
    *(uint2*)(row + k)     = vh;
    *(uint2*)(row + K + k) = isA ? vl : vh;
}

// ---------------- depthwise causal conv (K=4) + bias + silu ----------------
__global__ void conv_silu_kernel(const float* __restrict__ proj,
                                 const float* __restrict__ cw,
                                 const float* __restrict__ cb,
                                 float* __restrict__ xBC)
{
    int idx = blockIdx.x * blockDim.x + threadIdx.x;
    if (idx >= BL * CONVDIM) return;
    int ch = idx % CONVDIM;
    int bl = idx / CONVDIM;
    int l  = bl % LSEQ;
    float4 w = *(const float4*)&cw[ch * 4];
    float acc = cb[ch];
    const float* base = proj + (size_t)bl * PROJDIM + INTERD + ch;
    if (l >= 3) {
        acc += w.x * base[-3 * PROJDIM] + w.y * base[-2 * PROJDIM]
             + w.z * base[-1 * PROJDIM] + w.w * base[0];
    } else {
        float wk[4] = {w.x, w.y, w.z, w.w};
        for (int k = 3 - l; k < 4; ++k) acc += wk[k] * base[(k - 3) * PROJDIM];
    }
    xBC[idx] = acc / (1.f + expf(-acc));
}

// ---------------- softplus(dt+bias), per-chunk inclusive cumsum of dA ----------------
__global__ void dt_acum_kernel(const float* __restrict__ proj,
                               const float* __restrict__ dt_bias,
                               const float* __restrict__ A_log,
                               float* __restrict__ dtv,
                               float* __restrict__ Acum)
{
    int cc = blockIdx.x, h = blockIdx.y, b = blockIdx.z;
    int i  = threadIdx.x;
    int l  = cc * CSIZE + i;
    float d  = proj[(size_t)(b * LSEQ + l) * PROJDIM + INTERD + CONVDIM + h] + dt_bias[h];
    float sp = (d > 20.f) ? d : log1pf(expf(d));
    dtv[(size_t)(b * LSEQ + l) * NHEADS + h] = sp;
    float dA = sp * (-expf(A_log[h]));
    __shared__ float sbuf[CSIZE];
    sbuf[i] = dA;
    __syncthreads();
    for (int off = 1; off < CSIZE; off <<= 1) {
        float v = sbuf[i];
        if (i >= off) v += sbuf[i - off];
        __syncthreads();
        sbuf[i] = v;
        __syncthreads();
    }
    Acum[(((size_t)b * NHEADS + h) * NCHUNK + cc) * CSIZE + i] = sbuf[i];
}

// ---------------- generic NT SGEMM (small CB gemm only) ----------------
__global__ __launch_bounds__(256) void sgemm_nt(
    const float* __restrict__ A, const float* __restrict__ B, float* __restrict__ C,
    int M, int N, int K, int lda, int ldb, int ldc,
    long long sA, long long sB, long long sC)
{
    A += (long long)blockIdx.z * sA;
    B += (long long)blockIdx.z * sB;
    C += (long long)blockIdx.z * sC;
    const int bm = blockIdx.y * 128, bn = blockIdx.x * 128;
    __shared__ float As[16][128];
    __shared__ float Bs[16][128];
    const int tid = threadIdx.x;
    const int lr = tid >> 2;
    const int lc = (tid & 3) << 2;
    const int tx = tid & 15, ty = tid >> 4;

    float acc[8][8];
#pragma unroll
    for (int i = 0; i < 8; ++i)
#pragma unroll
        for (int j = 0; j < 8; ++j) acc[i][j] = 0.f;

    for (int k0 = 0; k0 < K; k0 += 16) {
#pragma unroll
        for (int r = 0; r < 2; ++r) {
            int row = lr + r * 64;
            int gr  = bm + row;
            float4 v = make_float4(0.f, 0.f, 0.f, 0.f);
            if (gr < M) v = *(const float4*)&A[(long long)gr * lda + k0 + lc];
            As[lc + 0][row] = v.x; As[lc + 1][row] = v.y;
            As[lc + 2][row] = v.z; As[lc + 3][row] = v.w;
        }
#pragma unroll
        for (int r = 0; r < 2; ++r) {
            int row = lr + r * 64;
            int gr  = bn + row;
            float4 v = make_float4(0.f, 0.f, 0.f, 0.f);
            if (gr < N) v = *(const float4*)&B[(long long)gr * ldb + k0 + lc];
            Bs[lc + 0][row] = v.x; Bs[lc + 1][row] = v.y;
            Bs[lc + 2][row] = v.z; Bs[lc + 3][row] = v.w;
        }
        __syncthreads();
#pragma unroll
        for (int k = 0; k < 16; ++k) {
            float a[8], b[8];
            *(float4*)&a[0] = *(const float4*)&As[k][ty * 8];
            *(float4*)&a[4] = *(const float4*)&As[k][ty * 8 + 4];
            *(float4*)&b[0] = *(const float4*)&Bs[k][tx * 8];
            *(float4*)&b[4] = *(const float4*)&Bs[k][tx * 8 + 4];
#pragma unroll
            for (int ii = 0; ii < 8; ++ii)
#pragma unroll
                for (int jj = 0; jj < 8; ++jj) acc[ii][jj] += a[ii] * b[jj];
        }
        __syncthreads();
    }
#pragma unroll
    for (int ii = 0; ii < 8; ++ii) {
        int gr = bm + ty * 8 + ii;
        if (gr >= M) continue;
#pragma unroll
        for (int jj = 0; jj < 8; ++jj) {
            int gc = bn + tx * 8 + jj;
            if (gc < N) C[(long long)gr * ldc + gc] = acc[ii][jj];
        }
    }
}

// ---------------- per (b,h,chunk): states[p,n] = sum_j w_j * x[j,p] * B[j,n] ----------------
__global__ __launch_bounds__(256) void states_kernel(
    const float* __restrict__ xBC, const float* __restrict__ dtv,
    const float* __restrict__ Acum, float* __restrict__ states)
{
    int cc = blockIdx.x, h = blockIdx.y, b = blockIdx.z;
    int tid = threadIdx.x;
    int tn = tid & 15, tp = tid >> 4;
    __shared__ float Bs[16][128];
    __shared__ float wxs[16][64];
    const float* Ab = Acum + (((size_t)b * NHEADS + h) * NCHUNK + cc) * CSIZE;
    float AcLast = Ab[CSIZE - 1];
    float acc[4][8];
#pragma unroll
    for (int p = 0; p < 4; ++p)
#pragma unroll
        for (int n = 0; n < 8; ++n) acc[p][n] = 0.f;
    int l0 = b * LSEQ + cc * CSIZE;
    for (int jt = 0; jt < CSIZE; jt += 16) {
#pragma unroll
        for (int r = 0; r < 2; ++r) {
            int f  = tid + r * 256;
            int jr = f >> 5;
            int n4 = f & 31;
            *(float4*)&Bs[jr][n4 * 4] =
                *(const float4*)&xBC[(size_t)(l0 + jt + jr) * CONVDIM + INTERD + n4 * 4];
        }
        {
            int jr = tid >> 4, p4 = tid & 15;
            int j  = jt + jr;
            float w = expf(AcLast - Ab[j]) * dtv[(size_t)(l0 + j) * NHEADS + h];
            float4 xv = *(const float4*)&xBC[(size_t)(l0 + j) * CONVDIM + h * HDIM + p4 * 4];
            xv.x *= w; xv.y *= w; xv.z *= w; xv.w *= w;
            *(float4*)&wxs[jr][p4 * 4] = xv;
        }
        __syncthreads();
#pragma unroll
        for (int j = 0; j < 16; ++j) {
            float bx[8], px[4];
            *(float4*)&bx[0] = *(const float4*)&Bs[j][tn * 8];
            *(float4*)&bx[4] = *(const float4*)&Bs[j][tn * 8 + 4];
            *(float4*)&px[0] = *(const float4*)&wxs[j][tp * 4];
#pragma unroll
            for (int p = 0; p < 4; ++p)
#pragma unroll
                for (int n = 0; n < 8; ++n) acc[p][n] += px[p] * bx[n];
        }
        __syncthreads();
    }
    float* so = states + (((size_t)b * NCHUNK + cc) * NHEADS + h) * (HDIM * NSTATE);
#pragma unroll
    for (int p = 0; p < 4; ++p) {
#pragma unroll
        for (int n = 0; n < 8; n += 4) {
            float4 v = make_float4(acc[p][n], acc[p][n + 1], acc[p][n + 2], acc[p][n + 3]);
            *(float4*)&so[(tp * 4 + p) * NSTATE + tn * 8 + n] = v;
        }
    }
}

// ---------------- inter-chunk recurrence (scan over 8 chunks) ----------------
__global__ void scan_kernel(const float* __restrict__ states,
                            const float* __restrict__ Acum,
                            float* __restrict__ prev)
{
    int h = blockIdx.x, b = blockIdx.y, tid = threadIdx.x;
    float carry[32];
#pragma unroll
    for (int t = 0; t < 32; ++t) carry[t] = 0.f;
    for (int cc = 0; cc < NCHUNK; ++cc) {
        float cd = expf(Acum[(((size_t)b * NHEADS + h) * NCHUNK + cc) * CSIZE + CSIZE - 1]);
        size_t base = (((size_t)b * NCHUNK + cc) * NHEADS + h) * (HDIM * NSTATE);
#pragma unroll
        for (int t = 0; t < 32; ++t) {
            size_t idx = base + tid + t * 256;
            prev[idx]  = carry[t];
            carry[t]   = cd * carry[t] + states[idx];
        }
    }
}

// ---------------- per (b,h,chunk): Ydiag + Yoff + D*x -> Y ----------------
__global__ __launch_bounds__(256) void y_kernel(
    const float* __restrict__ xBC, const float* __restrict__ dtv,
    const float* __restrict__ Acum, const float* __restrict__ CB,
    const float* __restrict__ prev, const float* __restrict__ Dp,
    float* __restrict__ Y)
{
    int cc = blockIdx.x, h = blockIdx.y, b = blockIdx.z;
    int i  = threadIdx.x;
    __shared__ float dts[CSIZE], Ac[CSIZE];
    __shared__ float xs[16][64];
    __shared__ float prevs[HDIM * NSTATE];
    int l0 = b * LSEQ + cc * CSIZE;
    dts[i] = dtv[(size_t)(l0 + i) * NHEADS + h];
    Ac[i]  = Acum[(((size_t)b * NHEADS + h) * NCHUNK + cc) * CSIZE + i];
    __syncthreads();
    float Ai = Ac[i];
    float y[64];
#pragma unroll
    for (int p = 0; p < 64; ++p) y[p] = 0.f;
    const float* CBrow = CB + (((size_t)b * NCHUNK + cc) * CSIZE + i) * CSIZE;

    for (int jt = 0; jt < CSIZE; jt += 16) {
        {
            int jr = threadIdx.x >> 4, p4 = threadIdx.x & 15;
            *(float4*)&xs[jr][p4 * 4] =
                *(const float4*)&xBC[(size_t)(l0 + jt + jr) * CONVDIM + h * HDIM + p4 * 4];
        }
        __syncthreads();
        if (i >= jt) {
            int jmax = i - jt + 1;
            if (jmax > 16) jmax = 16;
            for (int jl = 0; jl < jmax; ++jl) {
                int j = jt + jl;
                float coef = CBrow[j] * expf(Ai - Ac[j]) * dts[j];
#pragma unroll
                for (int p4 = 0; p4 < 16; ++p4) {
                    float4 xv = *(const float4*)&xs[jl][p4 * 4];
                    y[p4 * 4 + 0] += coef * xv.x;
                    y[p4 * 4 + 1] += coef * xv.y;
                    y[p4 * 4 + 2] += coef * xv.z;
                    y[p4 * 4 + 3] += coef * xv.w;
                }
            }
        }
        __syncthreads();
    }

    {
        const float4* src =
            (const float4*)(prev + (((size_t)b * NCHUNK + cc) * NHEADS + h) * (HDIM * NSTATE));
        float4* dst = (float4*)prevs;
        for (int f = threadIdx.x; f < (HDIM * NSTATE) / 4; f += 256) dst[f] = src[f];
    }
    __syncthreads();
    float eAi = expf(Ai);
    const float* Crow = xBC + (size_t)(l0 + i) * CONVDIM + INTERD + NSTATE;
    for (int nt = 0; nt < NSTATE; nt += 8) {
        float cf[8];
#pragma unroll
        for (int q = 0; q < 8; ++q) cf[q] = eAi * Crow[nt + q];
#pragma unroll
        for (int p = 0; p < 64; ++p) {
            const float* pr = &prevs[p * NSTATE + nt];
            float4 v0 = *(const float4*)pr;
            float4 v1 = *(const float4*)(pr + 4);
            y[p] += cf[0] * v0.x + cf[1] * v0.y + cf[2] * v0.z + cf[3] * v0.w
                  + cf[4] * v1.x + cf[5] * v1.y + cf[6] * v1.z + cf[7] * v1.w;
        }
    }

    float Dh = Dp[h];
    float* yo = Y + (size_t)(l0 + i) * INTERD + h * HDIM;
    const float* xr = xBC + (size_t)(l0 + i) * CONVDIM + h * HDIM;
#pragma unroll
    for (int p4 = 0; p4 < 16; ++p4) {
        float4 xv = *(const float4*)&xr[p4 * 4];
        float4 ov;
        ov.x = y[p4 * 4 + 0] + Dh * xv.x;
        ov.y = y[p4 * 4 + 1] + Dh * xv.y;
        ov.z = y[p4 * 4 + 2] + Dh * xv.z;
        ov.w = y[p4 * 4 + 3] + Dh * xv.w;
        *(float4*)&yo[p4 * 4] = ov;
    }
}

// ---------------- gate (silu) + RMSNorm -> fp16 hi/lo stacked Y2 ----------------
__global__ void gate_rms_kernel(const float* __restrict__ proj,
                                const float* __restrict__ norm_w,
                                const float* __restrict__ Y,
                                __half* __restrict__ Y2)
{
    int row = blockIdx.x, tid = threadIdx.x;
    const float* gr = proj + (size_t)row * PROJDIM;
    const float* yr = Y + (size_t)row * INTERD;
    float yv[16];
    float ss = 0.f;
#pragma unroll
    for (int t = 0; t < 16; ++t) {
        int e = tid + t * 256;
        float g = gr[e];
        float v = yr[e] * (g / (1.f + expf(-g)));
        yv[t] = v;
        ss += v * v;
    }
    __shared__ float red[8];
#pragma unroll
    for (int o = 16; o > 0; o >>= 1) ss += __shfl_xor_sync(0xffffffff, ss, o);
    if ((tid & 31) == 0) red[tid >> 5] = ss;
    __syncthreads();
    float tot = 0.f;
#pragma unroll
    for (int w = 0; w < 8; ++w) tot += red[w];
    float scale = rsqrtf(tot / (float)INTERD + EPSV);
    __half* y2r = Y2 + (size_t)row * 2 * INTERD;
#pragma unroll
    for (int t = 0; t < 16; ++t) {
        int e = tid + t * 256;
        float v = yv[t] * scale * norm_w[e];
        __half h = __float2half(v);
        __half l = __float2half(v - __half2float(h));
        y2r[e] = h;
        y2r[INTERD + e] = l;
    }
}

// ---------------- launch ----------------
extern "C" void kernel_launch(void* const* d_in, const int* in_sizes, int n_in,
                              void* d_out, int out_size)
{
    const float* hs      = (const float*)d_in[0];
    const float* W_in    = (const float*)d_in[1];
    const float* conv_w  = (const float*)d_in[2];
    const float* conv_b  = (const float*)d_in[3];
    const float* dt_bias = (const float*)d_in[4];
    const float* A_log   = (const float*)d_in[5];
    const float* Dp      = (const float*)d_in[6];
    const float* norm_w  = (const float*)d_in[7];
    const float* W_out   = (const float*)d_in[8];
    float* out = (float*)d_out;

    float *proj, *xBC, *dtv, *Acum, *CB, *states, *prev, *Y;
    __half *A2, *Win2, *Y2, *Wout2;
    cudaGetSymbolAddress((void**)&proj,   g_proj);
    cudaGetSymbolAddress((void**)&xBC,    g_xBC);
    cudaGetSymbolAddress((void**)&dtv,    g_dtv);
    cudaGetSymbolAddress((void**)&Acum,   g_Acum);
    cudaGetSymbolAddress((void**)&CB,     g_CB);
    cudaGetSymbolAddress((void**)&states, g_states);
    cudaGetSymbolAddress((void**)&prev,   g_prev);
    cudaGetSymbolAddress((void**)&Y,      g_Y);
    cudaGetSymbolAddress((void**)&A2,     g_A2);
    cudaGetSymbolAddress((void**)&Win2,   g_Win2);
    cudaGetSymbolAddress((void**)&Y2,     g_Y2);
    cudaGetSymbolAddress((void**)&Wout2,  g_Wout2);

    cudaFuncSetAttribute(gemm_fp16_mma,
                         cudaFuncAttributeMaxDynamicSharedMemorySize, TSMEM);

    // 0) split fp32 -> fp16 hi/lo (K-stacked, 2 terms)
    {
        long long t4;
        t4 = (long long)BL * DMODEL / 4;
        split_fp16_kernel<<<(unsigned)((t4 + 255) / 256), 256>>>(hs, A2, DMODEL, 1, t4);
        t4 = (long long)PROJDIM * DMODEL / 4;
        split_fp16_kernel<<<(unsigned)((t4 + 255) / 256), 256>>>(W_in, Win2, DMODEL, 0, t4);
        t4 = (long long)DMODEL * INTERD / 4;
        split_fp16_kernel<<<(unsigned)((t4 + 255) / 256), 256>>>(W_out, Wout2, INTERD, 0, t4);
    }

    // 1) proj = hs @ W_in^T via mma.sync fp16 split-K (K'=4096)
    gemm_fp16_mma<<<dim3(BL / 128, (PROJDIM + 255) / 256), 256, TSMEM>>>(
        A2, Win2, proj, BL, PROJDIM, 2 * DMODEL, PROJDIM);

    // 2) depthwise causal conv + silu -> xBC
    {
        int total = BL * CONVDIM;
        conv_silu_kernel<<<(total + 255) / 256, 256>>>(proj, conv_w, conv_b, xBC);
    }

    // 3) softplus(dt) + per-chunk cumsum of dA
    dt_acum_kernel<<<dim3(NCHUNK, NHEADS, BATCH), CSIZE>>>(proj, dt_bias, A_log, dtv, Acum);

    // 4) CB[b,c,i,j] = C_i . B_j  (shared across all heads, G=1)
    sgemm_nt<<<dim3(2, 2, BATCH * NCHUNK), 256>>>(
        xBC + (INTERD + NSTATE), xBC + INTERD, CB,
        CSIZE, CSIZE, NSTATE, CONVDIM, CONVDIM, CSIZE,
        (long long)CSIZE * CONVDIM, (long long)CSIZE * CONVDIM, (long long)CSIZE * CSIZE);

    // 5) per-chunk states
    states_kernel<<<dim3(NCHUNK, NHEADS, BATCH), 256>>>(xBC, dtv, Acum, states);

    // 6) inter-chunk scan -> prev
    scan_kernel<<<dim3(NHEADS, BATCH), 256>>>(states, Acum, prev);

    // 7) Ydiag + Yoff + D*x -> Y
    y_kernel<<<dim3(NCHUNK, NHEADS, BATCH), CSIZE>>>(xBC, dtv, Acum, CB, prev, Dp, Y);

    // 8) gate + RMSNorm -> Y2 (fp16 hi/lo stacked)
    gate_rms_kernel<<<BL, 256>>>(proj, norm_w, Y, Y2);

    // 9) out = Y @ W_out^T via mma.sync fp16 split-K (K'=8192)
    gemm_fp16_mma<<<dim3(BL / 128, DMODEL / 256), 256, TSMEM>>>(
        Y2, Wout2, out, BL, DMODEL, 2 * INTERD, DMODEL);
}

// round 5
// speedup vs baseline: 3.9598x; 1.3428x over previous
#include <cuda_runtime.h>
#include <cuda_fp16.h>
#include <cstdint>

// ---------------- problem constants ----------------
#define BATCH    2
#define LSEQ     2048
#define DMODEL   2048
#define INTERD   4096
#define NHEADS   64
#define HDIM     64
#define NSTATE   128
#define KCONV    4
#define CSIZE    256
#define NCHUNK   (LSEQ / CSIZE)                 // 8
#define CONVDIM  (INTERD + 2 * NSTATE)          // 4352
#define PROJDIM  (INTERD + CONVDIM + NHEADS)    // 8512
#define BL       (BATCH * LSEQ)                 // 4096
#define EPSV     1e-5f

// ---------------- device scratch (static; no allocs allowed) ----------------
__device__ float g_proj  [(size_t)BL * PROJDIM];
__device__ float g_xBC   [(size_t)BL * CONVDIM];
__device__ float g_dtv   [(size_t)BL * NHEADS];
__device__ float g_Acum  [(size_t)BATCH * NHEADS * NCHUNK * CSIZE];
__device__ float g_CB    [(size_t)BATCH * NCHUNK * CSIZE * CSIZE];
__device__ float g_states[(size_t)BATCH * NCHUNK * NHEADS * HDIM * NSTATE];
__device__ float g_prev  [(size_t)BATCH * NCHUNK * NHEADS * HDIM * NSTATE];
__device__ float g_Y     [(size_t)BL * INTERD];
// plain fp16 operands (no split-K emulation)
__device__ __half g_A2   [(size_t)BL * DMODEL];
__device__ __half g_Win2 [(size_t)PROJDIM * DMODEL];
__device__ __half g_Y2   [(size_t)BL * INTERD];
__device__ __half g_Wout2[(size_t)DMODEL * INTERD];

// =====================================================================
// mma.sync fp16 GEMM machinery (plain sm_103-target-safe PTX only)
// =====================================================================
__device__ __forceinline__ uint32_t smem_u32(const void* p) {
    return (uint32_t)__cvta_generic_to_shared(p);
}
#define SW128(o) ((o) ^ (((o) >> 3) & 0x70))

__device__ __forceinline__ void cp_async16(uint32_t d, const void* g, int sz) {
    asm volatile("cp.async.cg.shared.global [%0], [%1], 16, %2;"
                 :: "r"(d), "l"(g), "r"(sz) : "memory");
}
#define CP_COMMIT() asm volatile("cp.async.commit_group;" ::: "memory")
#define CP_WAIT2()  asm volatile("cp.async.wait_group 2;" ::: "memory")

__device__ __forceinline__ void ldsm4(uint32_t& r0, uint32_t& r1, uint32_t& r2,
                                      uint32_t& r3, uint32_t a) {
    asm volatile("ldmatrix.sync.aligned.m8n8.x4.shared.b16 {%0,%1,%2,%3}, [%4];"
                 : "=r"(r0), "=r"(r1), "=r"(r2), "=r"(r3) : "r"(a));
}
__device__ __forceinline__ void mma16816(float* c, const uint32_t* a, const uint32_t* b) {
    asm volatile(
        "mma.sync.aligned.m16n8k16.row.col.f32.f16.f16.f32 "
        "{%0,%1,%2,%3}, {%4,%5,%6,%7}, {%8,%9}, {%0,%1,%2,%3};"
        : "+f"(c[0]), "+f"(c[1]), "+f"(c[2]), "+f"(c[3])
        : "r"(a[0]), "r"(a[1]), "r"(a[2]), "r"(a[3]), "r"(b[0]), "r"(b[1]));
}

// C[M,N] = A[M,K]*B[N,K]^T, fp32 accum. BM=128, BN=256, BK=64, 4 stages, 256 thr.
#define TSTAGE_B (128 * 128 + 256 * 128)     // 49152
#define TNSTG    4
#define TSMEM    (TNSTG * TSTAGE_B)          // 196608

__global__ void __launch_bounds__(256, 1) gemm_fp16_mma(
    const __half* __restrict__ A, const __half* __restrict__ Bm,
    float* __restrict__ C, int M, int N, int K, int ldc)
{
    extern __shared__ __align__(1024) char smem[];
    const uint32_t sbase = smem_u32(smem);
    const int tid  = threadIdx.x;
    const int wid  = tid >> 5, lane = tid & 31;
    const int bm   = blockIdx.x * 128, bn = blockIdx.y * 256;
    const int wm   = (wid & 1) * 64;          // 2 warps over M
    const int wn   = (wid >> 1) * 64;         // 4 warps over N
    const int KT   = K >> 6;

    const int lr = tid >> 3;                  // 0..31
    const int lu = tid & 7;                   // 16B unit in 128B row

    float c[4][8][4];
#pragma unroll
    for (int mt = 0; mt < 4; ++mt)
#pragma unroll
        for (int nt = 0; nt < 8; ++nt)
#pragma unroll
            for (int q = 0; q < 4; ++q) c[mt][nt][q] = 0.f;

#define LOAD_STAGE(kt, s) do {                                               \
    uint32_t st_ = sbase + (s) * TSTAGE_B;                                   \
    _Pragma("unroll")                                                        \
    for (int i_ = 0; i_ < 4; ++i_) {                                         \
        int r_ = lr + i_ * 32;                                               \
        uint32_t d_ = st_ + SW128((uint32_t)(r_ * 128 + lu * 16));           \
        const void* g_ = (const char*)A +                                    \
            (((size_t)(bm + r_) * K + (size_t)(kt) * 64 + lu * 8) << 1);     \
        cp_async16(d_, g_, 16);                                              \
    }                                                                        \
    _Pragma("unroll")                                                        \
    for (int i_ = 0; i_ < 8; ++i_) {                                         \
        int r_ = lr + i_ * 32;                                               \
        int gn_ = bn + r_;                                                   \
        uint32_t d_ = st_ + 16384 + SW128((uint32_t)(r_ * 128 + lu * 16));   \
        const void* g_ = (const char*)Bm +                                   \
            (((size_t)gn_ * K + (size_t)(kt) * 64 + lu * 8) << 1);           \
        cp_async16(d_, g_, gn_ < N ? 16 : 0);                                \
    }                                                                        \
} while (0)

    LOAD_STAGE(0, 0); CP_COMMIT();
    LOAD_STAGE(1, 1); CP_COMMIT();
    LOAD_STAGE(2, 2); CP_COMMIT();

    const int a_row = (lane & 15);
    const int a_ku  = (lane >> 4) * 16;
    const int b_row = ((lane >> 4) & 1) * 8 + (lane & 7);
    const int b_ku  = ((lane >> 3) & 1) * 16;

    for (int kt = 0; kt < KT; ++kt) {
        const int s = kt & 3;
        CP_WAIT2();
        __syncthreads();
        if (kt + 3 < KT) LOAD_STAGE(kt + 3, (kt + 3) & 3);
        CP_COMMIT();

        const uint32_t stA = sbase + s * TSTAGE_B;
        const uint32_t stB = stA + 16384;
#pragma unroll
        for (int ks = 0; ks < 4; ++ks) {
            uint32_t a[4][4], b[8][2];
#pragma unroll
            for (int mt = 0; mt < 4; ++mt) {
                uint32_t off = (uint32_t)((wm + mt * 16 + a_row) * 128 + ks * 32 + a_ku);
                ldsm4(a[mt][0], a[mt][1], a[mt][2], a[mt][3], stA + SW128(off));
            }
#pragma unroll
            for (int pr = 0; pr < 4; ++pr) {
                uint32_t off = (uint32_t)((wn + pr * 16 + b_row) * 128 + ks * 32 + b_ku);
                uint32_t r0, r1, r2, r3;
                ldsm4(r0, r1, r2, r3, stB + SW128(off));
                b[pr * 2][0] = r0; b[pr * 2][1] = r1;
                b[pr * 2 + 1][0] = r2; b[pr * 2 + 1][1] = r3;
            }
#pragma unroll
            for (int mt = 0; mt < 4; ++mt)
#pragma unroll
                for (int nt = 0; nt < 8; ++nt)
                    mma16816(c[mt][nt], a[mt], b[nt]);
        }
    }

    // epilogue
#pragma unroll
    for (int mt = 0; mt < 4; ++mt) {
        int r0 = bm + wm + mt * 16 + (lane >> 2);
#pragma unroll
        for (int nt = 0; nt < 8; ++nt) {
            int col = bn + wn + nt * 8 + (lane & 3) * 2;
            if (col < N) {
                float2 v0 = make_float2(c[mt][nt][0], c[mt][nt][1]);
                float2 v1 = make_float2(c[mt][nt][2], c[mt][nt][3]);
                *(float2*)&C[(size_t)r0 * ldc + col] = v0;
                *(float2*)&C[(size_t)(r0 + 8) * ldc + col] = v1;
            }
        }
    }
}

// ---------------- fp32 -> fp16 convert ----------------
__global__ void cvt_fp16_kernel(const float* __restrict__ src,
                                __half* __restrict__ dst, long long total4)
{
    long long t = (long long)blockIdx.x * blockDim.x + threadIdx.x;
    if (t >= total4) return;
    float4 a = *(const float4*)(src + t * 4);
    __half h[4];
    h[0] = __float2half(a.x); h[1] = __float2half(a.y);
    h[2] = __float2half(a.z); h[3] = __float2half(a.w);
    uint2 v;
    v.x = ((uint32_t)*(uint16_t*)&h[1] << 16) | *(uint16_t*)&h[0];
    v.y = ((uint32_t)*(uint16_t*)&h[3] << 16) | *(uint16_t*)&h[2];
    *(uint2*)(dst + t * 4) = v;
}

// ---------------- depthwise causal conv (K=4) + bias + silu ----------------
__global__ void conv_silu_kernel(const float* __restrict__ proj,
                                 const float* __restrict__ cw,
                                 const float* __restrict__ cb,
                                 float* __restrict__ xBC)
{
    int idx = blockIdx.x * blockDim.x + threadIdx.x;
    if (idx >= BL * CONVDIM) return;
    int ch = idx % CONVDIM;
    int bl = idx / CONVDIM;
    int l  = bl % LSEQ;
    float4 w = *(const float4*)&cw[ch * 4];
    float acc = cb[ch];
    const float* base = proj + (size_t)bl * PROJDIM + INTERD + ch;
    if (l >= 3) {
        acc += w.x * base[-3 * PROJDIM] + w.y * base[-2 * PROJDIM]
             + w.z * base[-1 * PROJDIM] + w.w * base[0];
    } else {
        float wk[4] = {w.x, w.y, w.z, w.w};
        for (int k = 3 - l; k < 4; ++k) acc += wk[k] * base[(k - 3) * PROJDIM];
    }
    xBC[idx] = acc / (1.f + expf(-acc));
}

// ---------------- softplus(dt+bias), per-chunk inclusive cumsum of dA ----------------
__global__ void dt_acum_kernel(const float* __restrict__ proj,
                               const float* __restrict__ dt_bias,
                               const float* __restrict__ A_log,
                               float* __restrict__ dtv,
                               float* __restrict__ Acum)
{
    int cc = blockIdx.x, h = blockIdx.y, b = blockIdx.z;
    int i  = threadIdx.x;
    int l  = cc * CSIZE + i;
    float d  = proj[(size_t)(b * LSEQ + l) * PROJDIM + INTERD + CONVDIM + h] + dt_bias[h];
    float sp = (d > 20.f) ? d : log1pf(expf(d));
    dtv[(size_t)(b * LSEQ + l) * NHEADS + h] = sp;
    float dA = sp * (-expf(A_log[h]));
    __shared__ float sbuf[CSIZE];
    sbuf[i] = dA;
    __syncthreads();
    for (int off = 1; off < CSIZE; off <<= 1) {
        float v = sbuf[i];
        if (i >= off) v += sbuf[i - off];
        __syncthreads();
        sbuf[i] = v;
        __syncthreads();
    }
    Acum[(((size_t)b * NHEADS + h) * NCHUNK + cc) * CSIZE + i] = sbuf[i];
}

// ---------------- generic NT SGEMM (small CB gemm only) ----------------
__global__ __launch_bounds__(256) void sgemm_nt(
    const float* __restrict__ A, const float* __restrict__ B, float* __restrict__ C,
    int M, int N, int K, int lda, int ldb, int ldc,
    long long sA, long long sB, long long sC)
{
    A += (long long)blockIdx.z * sA;
    B += (long long)blockIdx.z * sB;
    C += (long long)blockIdx.z * sC;
    const int bm = blockIdx.y * 128, bn = blockIdx.x * 128;
    __shared__ float As[16][128];
    __shared__ float Bs[16][128];
    const int tid = threadIdx.x;
    const int lr = tid >> 2;
    const int lc = (tid & 3) << 2;
    const int tx = tid & 15, ty = tid >> 4;

    float acc[8][8];
#pragma unroll
    for (int i = 0; i < 8; ++i)
#pragma unroll
        for (int j = 0; j < 8; ++j) acc[i][j] = 0.f;

    for (int k0 = 0; k0 < K; k0 += 16) {
#pragma unroll
        for (int r = 0; r < 2; ++r) {
            int row = lr + r * 64;
            int gr  = bm + row;
            float4 v = make_float4(0.f, 0.f, 0.f, 0.f);
            if (gr < M) v = *(const float4*)&A[(long long)gr * lda + k0 + lc];
            As[lc + 0][row] = v.x; As[lc + 1][row] = v.y;
            As[lc + 2][row] = v.z; As[lc + 3][row] = v.w;
        }
#pragma unroll
        for (int r = 0; r < 2; ++r) {
            int row = lr + r * 64;
            int gr  = bn + row;
            float4 v = make_float4(0.f, 0.f, 0.f, 0.f);
            if (gr < N) v = *(const float4*)&B[(long long)gr * ldb + k0 + lc];
            Bs[lc + 0][row] = v.x; Bs[lc + 1][row] = v.y;
            Bs[lc + 2][row] = v.z; Bs[lc + 3][row] = v.w;
        }
        __syncthreads();
#pragma unroll
        for (int k = 0; k < 16; ++k) {
            float a[8], b[8];
            *(float4*)&a[0] = *(const float4*)&As[k][ty * 8];
            *(float4*)&a[4] = *(const float4*)&As[k][ty * 8 + 4];
            *(float4*)&b[0] = *(const float4*)&Bs[k][tx * 8];
            *(float4*)&b[4] = *(const float4*)&Bs[k][tx * 8 + 4];
#pragma unroll
            for (int ii = 0; ii < 8; ++ii)
#pragma unroll
                for (int jj = 0; jj < 8; ++jj) acc[ii][jj] += a[ii] * b[jj];
        }
        __syncthreads();
    }
#pragma unroll
    for (int ii = 0; ii < 8; ++ii) {
        int gr = bm + ty * 8 + ii;
        if (gr >= M) continue;
#pragma unroll
        for (int jj = 0; jj < 8; ++jj) {
            int gc = bn + tx * 8 + jj;
            if (gc < N) C[(long long)gr * ldc + gc] = acc[ii][jj];
        }
    }
}

// ---------------- per (b,h,chunk): states[p,n] = sum_j w_j * x[j,p] * B[j,n] ----------------
__global__ __launch_bounds__(256) void states_kernel(
    const float* __restrict__ xBC, const float* __restrict__ dtv,
    const float* __restrict__ Acum, float* __restrict__ states)
{
    int cc = blockIdx.x, h = blockIdx.y, b = blockIdx.z;
    int tid = threadIdx.x;
    int tn = tid & 15, tp = tid >> 4;
    __shared__ float Bs[16][128];
    __shared__ float wxs[16][64];
    const float* Ab = Acum + (((size_t)b * NHEADS + h) * NCHUNK + cc) * CSIZE;
    float AcLast = Ab[CSIZE - 1];
    float acc[4][8];
#pragma unroll
    for (int p = 0; p < 4; ++p)
#pragma unroll
        for (int n = 0; n < 8; ++n) acc[p][n] = 0.f;
    int l0 = b * LSEQ + cc * CSIZE;
    for (int jt = 0; jt < CSIZE; jt += 16) {
#pragma unroll
        for (int r = 0; r < 2; ++r) {
            int f  = tid + r * 256;
            int jr = f >> 5;
            int n4 = f & 31;
            *(float4*)&Bs[jr][n4 * 4] =
                *(const float4*)&xBC[(size_t)(l0 + jt + jr) * CONVDIM + INTERD + n4 * 4];
        }
        {
            int jr = tid >> 4, p4 = tid & 15;
            int j  = jt + jr;
            float w = expf(AcLast - Ab[j]) * dtv[(size_t)(l0 + j) * NHEADS + h];
            float4 xv = *(const float4*)&xBC[(size_t)(l0 + j) * CONVDIM + h * HDIM + p4 * 4];
            xv.x *= w; xv.y *= w; xv.z *= w; xv.w *= w;
            *(float4*)&wxs[jr][p4 * 4] = xv;
        }
        __syncthreads();
#pragma unroll
        for (int j = 0; j < 16; ++j) {
            float bx[8], px[4];
            *(float4*)&bx[0] = *(const float4*)&Bs[j][tn * 8];
            *(float4*)&bx[4] = *(const float4*)&Bs[j][tn * 8 + 4];
            *(float4*)&px[0] = *(const float4*)&wxs[j][tp * 4];
#pragma unroll
            for (int p = 0; p < 4; ++p)
#pragma unroll
                for (int n = 0; n < 8; ++n) acc[p][n] += px[p] * bx[n];
        }
        __syncthreads();
    }
    float* so = states + (((size_t)b * NCHUNK + cc) * NHEADS + h) * (HDIM * NSTATE);
#pragma unroll
    for (int p = 0; p < 4; ++p) {
#pragma unroll
        for (int n = 0; n < 8; n += 4) {
            float4 v = make_float4(acc[p][n], acc[p][n + 1], acc[p][n + 2], acc[p][n + 3]);
            *(float4*)&so[(tp * 4 + p) * NSTATE + tn * 8 + n] = v;
        }
    }
}

// ---------------- inter-chunk recurrence (scan over 8 chunks) ----------------
__global__ void scan_kernel(const float* __restrict__ states,
                            const float* __restrict__ Acum,
                            float* __restrict__ prev)
{
    int h = blockIdx.x, b = blockIdx.y, tid = threadIdx.x;
    float carry[32];
#pragma unroll
    for (int t = 0; t < 32; ++t) carry[t] = 0.f;
    for (int cc = 0; cc < NCHUNK; ++cc) {
        float cd = expf(Acum[(((size_t)b * NHEADS + h) * NCHUNK + cc) * CSIZE + CSIZE - 1]);
        size_t base = (((size_t)b * NCHUNK + cc) * NHEADS + h) * (HDIM * NSTATE);
#pragma unroll
        for (int t = 0; t < 32; ++t) {
            size_t idx = base + tid + t * 256;
            prev[idx]  = carry[t];
            carry[t]   = cd * carry[t] + states[idx];
        }
    }
}

// ---------------- per (b,h,chunk): Ydiag + Yoff + D*x -> Y ----------------
__global__ __launch_bounds__(256) void y_kernel(
    const float* __restrict__ xBC, const float* __restrict__ dtv,
    const float* __restrict__ Acum, const float* __restrict__ CB,
    const float* __restrict__ prev, const float* __restrict__ Dp,
    float* __restrict__ Y)
{
    int cc = blockIdx.x, h = blockIdx.y, b = blockIdx.z;
    int i  = threadIdx.x;
    __shared__ float dts[CSIZE], Ac[CSIZE];
    __shared__ float xs[16][64];
    __shared__ float prevs[HDIM * NSTATE];
    int l0 = b * LSEQ + cc * CSIZE;
    dts[i] = dtv[(size_t)(l0 + i) * NHEADS + h];
    Ac[i]  = Acum[(((size_t)b * NHEADS + h) * NCHUNK + cc) * CSIZE + i];
    __syncthreads();
    float Ai = Ac[i];
    float y[64];
#pragma unroll
    for (int p = 0; p < 64; ++p) y[p] = 0.f;
    const float* CBrow = CB + (((size_t)b * NCHUNK + cc) * CSIZE + i) * CSIZE;

    for (int jt = 0; jt < CSIZE; jt += 16) {
        {
            int jr = threadIdx.x >> 4, p4 = threadIdx.x & 15;
            *(float4*)&xs[jr][p4 * 4] =
                *(const float4*)&xBC[(size_t)(l0 + jt + jr) * CONVDIM + h * HDIM + p4 * 4];
        }
        __syncthreads();
        if (i >= jt) {
            int jmax = i - jt + 1;
            if (jmax > 16) jmax = 16;
            for (int jl = 0; jl < jmax; ++jl) {
                int j = jt + jl;
                float coef = CBrow[j] * expf(Ai - Ac[j]) * dts[j];
#pragma unroll
                for (int p4 = 0; p4 < 16; ++p4) {
                    float4 xv = *(const float4*)&xs[jl][p4 * 4];
                    y[p4 * 4 + 0] += coef * xv.x;
                    y[p4 * 4 + 1] += coef * xv.y;
                    y[p4 * 4 + 2] += coef * xv.z;
                    y[p4 * 4 + 3] += coef * xv.w;
                }
            }
        }
        __syncthreads();
    }

    {
        const float4* src =
            (const float4*)(prev + (((size_t)b * NCHUNK + cc) * NHEADS + h) * (HDIM * NSTATE));
        float4* dst = (float4*)prevs;
        for (int f = threadIdx.x; f < (HDIM * NSTATE) / 4; f += 256) dst[f] = src[f];
    }
    __syncthreads();
    float eAi = expf(Ai);
    const float* Crow = xBC + (size_t)(l0 + i) * CONVDIM + INTERD + NSTATE;
    for (int nt = 0; nt < NSTATE; nt += 8) {
        float cf[8];
#pragma unroll
        for (int q = 0; q < 8; ++q) cf[q] = eAi * Crow[nt + q];
#pragma unroll
        for (int p = 0; p < 64; ++p) {
            const float* pr = &prevs[p * NSTATE + nt];
            float4 v0 = *(const float4*)pr;
            float4 v1 = *(const float4*)(pr + 4);
            y[p] += cf[0] * v0.x + cf[1] * v0.y + cf[2] * v0.z + cf[3] * v0.w
                  + cf[4] * v1.x + cf[5] * v1.y + cf[6] * v1.z + cf[7] * v1.w;
        }
    }

    float Dh = Dp[h];
    float* yo = Y + (size_t)(l0 + i) * INTERD + h * HDIM;
    const float* xr = xBC + (size_t)(l0 + i) * CONVDIM + h * HDIM;
#pragma unroll
    for (int p4 = 0; p4 < 16; ++p4) {
        float4 xv = *(const float4*)&xr[p4 * 4];
        float4 ov;
        ov.x = y[p4 * 4 + 0] + Dh * xv.x;
        ov.y = y[p4 * 4 + 1] + Dh * xv.y;
        ov.z = y[p4 * 4 + 2] + Dh * xv.z;
        ov.w = y[p4 * 4 + 3] + Dh * xv.w;
        *(float4*)&yo[p4 * 4] = ov;
    }
}

// ---------------- gate (silu) + RMSNorm -> fp16 Y2 ----------------
__global__ void gate_rms_kernel(const float* __restrict__ proj,
                                const float* __restrict__ norm_w,
                                const float* __restrict__ Y,
                                __half* __restrict__ Y2)
{
    int row = blockIdx.x, tid = threadIdx.x;
    const float* gr = proj + (size_t)row * PROJDIM;
    const float* yr = Y + (size_t)row * INTERD;
    float yv[16];
    float ss = 0.f;
#pragma unroll
    for (int t = 0; t < 16; ++t) {
        int e = tid + t * 256;
        float g = gr[e];
        float v = yr[e] * (g / (1.f + expf(-g)));
        yv[t] = v;
        ss += v * v;
    }
    __shared__ float red[8];
#pragma unroll
    for (int o = 16; o > 0; o >>= 1) ss += __shfl_xor_sync(0xffffffff, ss, o);
    if ((tid & 31) == 0) red[tid >> 5] = ss;
    __syncthreads();
    float tot = 0.f;
#pragma unroll
    for (int w = 0; w < 8; ++w) tot += red[w];
    float scale = rsqrtf(tot / (float)INTERD + EPSV);
    __half* y2r = Y2 + (size_t)row * INTERD;
#pragma unroll
    for (int t = 0; t < 16; ++t) {
        int e = tid + t * 256;
        y2r[e] = __float2half(yv[t] * scale * norm_w[e]);
    }
}

// ---------------- launch ----------------
extern "C" void kernel_launch(void* const* d_in, const int* in_sizes, int n_in,
                              void* d_out, int out_size)
{
    const float* hs      = (const float*)d_in[0];
    const float* W_in    = (const float*)d_in[1];
    const float* conv_w  = (const float*)d_in[2];
    const float* conv_b  = (const float*)d_in[3];
    const float* dt_bias = (const float*)d_in[4];
    const float* A_log   = (const float*)d_in[5];
    const float* Dp      = (const float*)d_in[6];
    const float* norm_w  = (const float*)d_in[7];
    const float* W_out   = (const float*)d_in[8];
    float* out = (float*)d_out;

    float *proj, *xBC, *dtv, *Acum, *CB, *states, *prev, *Y;
    __half *A2, *Win2, *Y2, *Wout2;
    cudaGetSymbolAddress((void**)&proj,   g_proj);
    cudaGetSymbolAddress((void**)&xBC,    g_xBC);
    cudaGetSymbolAddress((void**)&dtv,    g_dtv);
    cudaGetSymbolAddress((void**)&Acum,   g_Acum);
    cudaGetSymbolAddress((void**)&CB,     g_CB);
    cudaGetSymbolAddress((void**)&states, g_states);
    cudaGetSymbolAddress((void**)&prev,   g_prev);
    cudaGetSymbolAddress((void**)&Y,      g_Y);
    cudaGetSymbolAddress((void**)&A2,     g_A2);
    cudaGetSymbolAddress((void**)&Win2,   g_Win2);
    cudaGetSymbolAddress((void**)&Y2,     g_Y2);
    cudaGetSymbolAddress((void**)&Wout2,  g_Wout2);

    cudaFuncSetAttribute(gemm_fp16_mma,
                         cudaFuncAttributeMaxDynamicSharedMemorySize, TSMEM);

    // 0) convert fp32 -> fp16
    {
        long long t4;
        t4 = (long long)BL * DMODEL / 4;
        cvt_fp16_kernel<<<(unsigned)((t4 + 255) / 256), 256>>>(hs, A2, t4);
        t4 = (long long)PROJDIM * DMODEL / 4;
        cvt_fp16_kernel<<<(unsigned)((t4 + 255) / 256), 256>>>(W_in, Win2, t4);
        t4 = (long long)DMODEL * INTERD / 4;
        cvt_fp16_kernel<<<(unsigned)((t4 + 255) / 256), 256>>>(W_out, Wout2, t4);
    }

    // 1) proj = hs @ W_in^T via mma.sync fp16 (K=2048)
    gemm_fp16_mma<<<dim3(BL / 128, (PROJDIM + 255) / 256), 256, TSMEM>>>(
        A2, Win2, proj, BL, PROJDIM, DMODEL, PROJDIM);

    // 2) depthwise causal conv + silu -> xBC
    {
        int total = BL * CONVDIM;
        conv_silu_kernel<<<(total + 255) / 256, 256>>>(proj, conv_w, conv_b, xBC);
    }

    // 3) softplus(dt) + per-chunk cumsum of dA
    dt_acum_kernel<<<dim3(NCHUNK, NHEADS, BATCH), CSIZE>>>(proj, dt_bias, A_log, dtv, Acum);

    // 4) CB[b,c,i,j] = C_i . B_j  (shared across all heads, G=1)
    sgemm_nt<<<dim3(2, 2, BATCH * NCHUNK), 256>>>(
        xBC + (INTERD + NSTATE), xBC + INTERD, CB,
        CSIZE, CSIZE, NSTATE, CONVDIM, CONVDIM, CSIZE,
        (long long)CSIZE * CONVDIM, (long long)CSIZE * CONVDIM, (long long)CSIZE * CSIZE);

    // 5) per-chunk states
    states_kernel<<<dim3(NCHUNK, NHEADS, BATCH), 256>>>(xBC, dtv, Acum, states);

    // 6) inter-chunk scan -> prev
    scan_kernel<<<dim3(NHEADS, BATCH), 256>>>(states, Acum, prev);

    // 7) Ydiag + Yoff + D*x -> Y
    y_kernel<<<dim3(NCHUNK, NHEADS, BATCH), CSIZE>>>(xBC, dtv, Acum, CB, prev, Dp, Y);

    // 8) gate + RMSNorm -> Y2 (fp16)
    gate_rms_kernel<<<BL, 256>>>(proj, norm_w, Y, Y2);

    // 9) out = Y @ W_out^T via mma.sync fp16 (K=4096)
    gemm_fp16_mma<<<dim3(BL / 128, DMODEL / 256), 256, TSMEM>>>(
        Y2, Wout2, out, BL, DMODEL, INTERD, DMODEL);
}

// round 6
// speedup vs baseline: 6.4434x; 1.6272x over previous
#include <cuda_runtime.h>
#include <cuda_fp16.h>
#include <cstdint>

// ---------------- problem constants ----------------
#define BATCH    2
#define LSEQ     2048
#define DMODEL   2048
#define INTERD   4096
#define NHEADS   64
#define HDIM     64
#define NSTATE   128
#define KCONV    4
#define CSIZE    256
#define NCHUNK   (LSEQ / CSIZE)                 // 8
#define CONVDIM  (INTERD + 2 * NSTATE)          // 4352
#define PROJDIM  (INTERD + CONVDIM + NHEADS)    // 8512
#define BL       (BATCH * LSEQ)                 // 4096
#define EPSV     1e-5f

// ---------------- device scratch (static; no allocs allowed) ----------------
__device__ float g_proj  [(size_t)BL * PROJDIM];
__device__ float g_xBC   [(size_t)BL * CONVDIM];
__device__ float g_dtv   [(size_t)BL * NHEADS];
__device__ float g_Acum  [(size_t)BATCH * NHEADS * NCHUNK * CSIZE];
__device__ float g_CB    [(size_t)BATCH * NCHUNK * CSIZE * CSIZE];
__device__ float g_states[(size_t)BATCH * NCHUNK * NHEADS * HDIM * NSTATE];
__device__ __half g_prevh[(size_t)BATCH * NCHUNK * NHEADS * HDIM * NSTATE];
__device__ float g_Y     [(size_t)BL * INTERD];
// plain fp16 operands
__device__ __half g_A2   [(size_t)BL * DMODEL];
__device__ __half g_Win2 [(size_t)PROJDIM * DMODEL];
__device__ __half g_Y2   [(size_t)BL * INTERD];
__device__ __half g_Wout2[(size_t)DMODEL * INTERD];

// =====================================================================
// common mma helpers
// =====================================================================
__device__ __forceinline__ uint32_t smem_u32(const void* p) {
    return (uint32_t)__cvta_generic_to_shared(p);
}
#define SW128(o) ((o) ^ (((o) >> 3) & 0x70))
#define SW256(o) ((o) ^ (((o) >> 4) & 0x70))

__device__ __forceinline__ void cp_async16(uint32_t d, const void* g, int sz) {
    asm volatile("cp.async.cg.shared.global [%0], [%1], 16, %2;"
                 :: "r"(d), "l"(g), "r"(sz) : "memory");
}
#define CP_COMMIT() asm volatile("cp.async.commit_group;" ::: "memory")
#define CP_WAIT2()  asm volatile("cp.async.wait_group 2;" ::: "memory")

__device__ __forceinline__ void ldsm4(uint32_t& r0, uint32_t& r1, uint32_t& r2,
                                      uint32_t& r3, uint32_t a) {
    asm volatile("ldmatrix.sync.aligned.m8n8.x4.shared.b16 {%0,%1,%2,%3}, [%4];"
                 : "=r"(r0), "=r"(r1), "=r"(r2), "=r"(r3) : "r"(a));
}
__device__ __forceinline__ void ldsm4t(uint32_t& r0, uint32_t& r1, uint32_t& r2,
                                       uint32_t& r3, uint32_t a) {
    asm volatile("ldmatrix.sync.aligned.m8n8.x4.trans.shared.b16 {%0,%1,%2,%3}, [%4];"
                 : "=r"(r0), "=r"(r1), "=r"(r2), "=r"(r3) : "r"(a));
}
__device__ __forceinline__ void mma16816(float* c, const uint32_t* a, const uint32_t* b) {
    asm volatile(
        "mma.sync.aligned.m16n8k16.row.col.f32.f16.f16.f32 "
        "{%0,%1,%2,%3}, {%4,%5,%6,%7}, {%8,%9}, {%0,%1,%2,%3};"
        : "+f"(c[0]), "+f"(c[1]), "+f"(c[2]), "+f"(c[3])
        : "r"(a[0]), "r"(a[1]), "r"(a[2]), "r"(a[3]), "r"(b[0]), "r"(b[1]));
}

__device__ __forceinline__ uint4 pack8h(const float* v) {
    __half h[8];
#pragma unroll
    for (int e = 0; e < 8; ++e) h[e] = __float2half(v[e]);
    uint4 r;
    r.x = ((uint32_t)*(uint16_t*)&h[1] << 16) | *(uint16_t*)&h[0];
    r.y = ((uint32_t)*(uint16_t*)&h[3] << 16) | *(uint16_t*)&h[2];
    r.z = ((uint32_t)*(uint16_t*)&h[5] << 16) | *(uint16_t*)&h[4];
    r.w = ((uint32_t)*(uint16_t*)&h[7] << 16) | *(uint16_t*)&h[6];
    return r;
}

// =====================================================================
// big fp16 GEMM (unchanged from R5, proven)
// =====================================================================
#define TSTAGE_B (128 * 128 + 256 * 128)     // 49152
#define TNSTG    4
#define TSMEM    (TNSTG * TSTAGE_B)          // 196608

__global__ void __launch_bounds__(256, 1) gemm_fp16_mma(
    const __half* __restrict__ A, const __half* __restrict__ Bm,
    float* __restrict__ C, int M, int N, int K, int ldc)
{
    extern __shared__ __align__(1024) char smem[];
    const uint32_t sbase = smem_u32(smem);
    const int tid  = threadIdx.x;
    const int wid  = tid >> 5, lane = tid & 31;
    const int bm   = blockIdx.x * 128, bn = blockIdx.y * 256;
    const int wm   = (wid & 1) * 64;
    const int wn   = (wid >> 1) * 64;
    const int KT   = K >> 6;

    const int lr = tid >> 3;
    const int lu = tid & 7;

    float c[4][8][4];
#pragma unroll
    for (int mt = 0; mt < 4; ++mt)
#pragma unroll
        for (int nt = 0; nt < 8; ++nt)
#pragma unroll
            for (int q = 0; q < 4; ++q) c[mt][nt][q] = 0.f;

#define LOAD_STAGE(kt, s) do {                                               \
    uint32_t st_ = sbase + (s) * TSTAGE_B;                                   \
    _Pragma("unroll")                                                        \
    for (int i_ = 0; i_ < 4; ++i_) {                                         \
        int r_ = lr + i_ * 32;                                               \
        uint32_t d_ = st_ + SW128((uint32_t)(r_ * 128 + lu * 16));           \
        const void* g_ = (const char*)A +                                    \
            (((size_t)(bm + r_) * K + (size_t)(kt) * 64 + lu * 8) << 1);     \
        cp_async16(d_, g_, 16);                                              \
    }                                                                        \
    _Pragma("unroll")                                                        \
    for (int i_ = 0; i_ < 8; ++i_) {                                         \
        int r_ = lr + i_ * 32;                                               \
        int gn_ = bn + r_;                                                   \
        uint32_t d_ = st_ + 16384 + SW128((uint32_t)(r_ * 128 + lu * 16));   \
        const void* g_ = (const char*)Bm +                                   \
            (((size_t)gn_ * K + (size_t)(kt) * 64 + lu * 8) << 1);           \
        cp_async16(d_, g_, gn_ < N ? 16 : 0);                                \
    }                                                                        \
} while (0)

    LOAD_STAGE(0, 0); CP_COMMIT();
    LOAD_STAGE(1, 1); CP_COMMIT();
    LOAD_STAGE(2, 2); CP_COMMIT();

    const int a_row = (lane & 15);
    const int a_ku  = (lane >> 4) * 16;
    const int b_row = ((lane >> 4) & 1) * 8 + (lane & 7);
    const int b_ku  = ((lane >> 3) & 1) * 16;

    for (int kt = 0; kt < KT; ++kt) {
        const int s = kt & 3;
        CP_WAIT2();
        __syncthreads();
        if (kt + 3 < KT) LOAD_STAGE(kt + 3, (kt + 3) & 3);
        CP_COMMIT();

        const uint32_t stA = sbase + s * TSTAGE_B;
        const uint32_t stB = stA + 16384;
#pragma unroll
        for (int ks = 0; ks < 4; ++ks) {
            uint32_t a[4][4], b[8][2];
#pragma unroll
            for (int mt = 0; mt < 4; ++mt) {
                uint32_t off = (uint32_t)((wm + mt * 16 + a_row) * 128 + ks * 32 + a_ku);
                ldsm4(a[mt][0], a[mt][1], a[mt][2], a[mt][3], stA + SW128(off));
            }
#pragma unroll
            for (int pr = 0; pr < 4; ++pr) {
                uint32_t off = (uint32_t)((wn + pr * 16 + b_row) * 128 + ks * 32 + b_ku);
                uint32_t r0, r1, r2, r3;
                ldsm4(r0, r1, r2, r3, stB + SW128(off));
                b[pr * 2][0] = r0; b[pr * 2][1] = r1;
                b[pr * 2 + 1][0] = r2; b[pr * 2 + 1][1] = r3;
            }
#pragma unroll
            for (int mt = 0; mt < 4; ++mt)
#pragma unroll
                for (int nt = 0; nt < 8; ++nt)
                    mma16816(c[mt][nt], a[mt], b[nt]);
        }
    }

#pragma unroll
    for (int mt = 0; mt < 4; ++mt) {
        int r0 = bm + wm + mt * 16 + (lane >> 2);
#pragma unroll
        for (int nt = 0; nt < 8; ++nt) {
            int col = bn + wn + nt * 8 + (lane & 3) * 2;
            if (col < N) {
                float2 v0 = make_float2(c[mt][nt][0], c[mt][nt][1]);
                float2 v1 = make_float2(c[mt][nt][2], c[mt][nt][3]);
                *(float2*)&C[(size_t)r0 * ldc + col] = v0;
                *(float2*)&C[(size_t)(r0 + 8) * ldc + col] = v1;
            }
        }
    }
}

// ---------------- fp32 -> fp16 convert ----------------
__global__ void cvt_fp16_kernel(const float* __restrict__ src,
                                __half* __restrict__ dst, long long total4)
{
    long long t = (long long)blockIdx.x * blockDim.x + threadIdx.x;
    if (t >= total4) return;
    float4 a = *(const float4*)(src + t * 4);
    __half h[4];
    h[0] = __float2half(a.x); h[1] = __float2half(a.y);
    h[2] = __float2half(a.z); h[3] = __float2half(a.w);
    uint2 v;
    v.x = ((uint32_t)*(uint16_t*)&h[1] << 16) | *(uint16_t*)&h[0];
    v.y = ((uint32_t)*(uint16_t*)&h[3] << 16) | *(uint16_t*)&h[2];
    *(uint2*)(dst + t * 4) = v;
}

// ---------------- depthwise causal conv (K=4) + bias + silu ----------------
__global__ void conv_silu_kernel(const float* __restrict__ proj,
                                 const float* __restrict__ cw,
                                 const float* __restrict__ cb,
                                 float* __restrict__ xBC)
{
    int idx = blockIdx.x * blockDim.x + threadIdx.x;
    if (idx >= BL * CONVDIM) return;
    int ch = idx % CONVDIM;
    int bl = idx / CONVDIM;
    int l  = bl % LSEQ;
    float4 w = *(const float4*)&cw[ch * 4];
    float acc = cb[ch];
    const float* base = proj + (size_t)bl * PROJDIM + INTERD + ch;
    if (l >= 3) {
        acc += w.x * base[-3 * PROJDIM] + w.y * base[-2 * PROJDIM]
             + w.z * base[-1 * PROJDIM] + w.w * base[0];
    } else {
        float wk[4] = {w.x, w.y, w.z, w.w};
        for (int k = 3 - l; k < 4; ++k) acc += wk[k] * base[(k - 3) * PROJDIM];
    }
    xBC[idx] = acc / (1.f + __expf(-acc));
}

// ---------------- softplus(dt+bias), per-chunk inclusive cumsum ----------------
__global__ void dt_acum_kernel(const float* __restrict__ proj,
                               const float* __restrict__ dt_bias,
                               const float* __restrict__ A_log,
                               float* __restrict__ dtv,
                               float* __restrict__ Acum)
{
    int cc = blockIdx.x, h = blockIdx.y, b = blockIdx.z;
    int i  = threadIdx.x;
    int l  = cc * CSIZE + i;
    float d  = proj[(size_t)(b * LSEQ + l) * PROJDIM + INTERD + CONVDIM + h] + dt_bias[h];
    float sp = (d > 20.f) ? d : log1pf(expf(d));
    dtv[(size_t)(b * LSEQ + l) * NHEADS + h] = sp;
    float dA = sp * (-expf(A_log[h]));
    __shared__ float sbuf[CSIZE];
    sbuf[i] = dA;
    __syncthreads();
    for (int off = 1; off < CSIZE; off <<= 1) {
        float v = sbuf[i];
        if (i >= off) v += sbuf[i - off];
        __syncthreads();
        sbuf[i] = v;
        __syncthreads();
    }
    Acum[(((size_t)b * NHEADS + h) * NCHUNK + cc) * CSIZE + i] = sbuf[i];
}

// ---------------- generic NT SGEMM (CB gemm only) ----------------
__global__ __launch_bounds__(256) void sgemm_nt(
    const float* __restrict__ A, const float* __restrict__ B, float* __restrict__ C,
    int M, int N, int K, int lda, int ldb, int ldc,
    long long sA, long long sB, long long sC)
{
    A += (long long)blockIdx.z * sA;
    B += (long long)blockIdx.z * sB;
    C += (long long)blockIdx.z * sC;
    const int bm = blockIdx.y * 128, bn = blockIdx.x * 128;
    __shared__ float As[16][128];
    __shared__ float Bs[16][128];
    const int tid = threadIdx.x;
    const int lr = tid >> 2;
    const int lc = (tid & 3) << 2;
    const int tx = tid & 15, ty = tid >> 4;

    float acc[8][8];
#pragma unroll
    for (int i = 0; i < 8; ++i)
#pragma unroll
        for (int j = 0; j < 8; ++j) acc[i][j] = 0.f;

    for (int k0 = 0; k0 < K; k0 += 16) {
#pragma unroll
        for (int r = 0; r < 2; ++r) {
            int row = lr + r * 64;
            int gr  = bm + row;
            float4 v = make_float4(0.f, 0.f, 0.f, 0.f);
            if (gr < M) v = *(const float4*)&A[(long long)gr * lda + k0 + lc];
            As[lc + 0][row] = v.x; As[lc + 1][row] = v.y;
            As[lc + 2][row] = v.z; As[lc + 3][row] = v.w;
        }
#pragma unroll
        for (int r = 0; r < 2; ++r) {
            int row = lr + r * 64;
            int gr  = bn + row;
            float4 v = make_float4(0.f, 0.f, 0.f, 0.f);
            if (gr < N) v = *(const float4*)&B[(long long)gr * ldb + k0 + lc];
            Bs[lc + 0][row] = v.x; Bs[lc + 1][row] = v.y;
            Bs[lc + 2][row] = v.z; Bs[lc + 3][row] = v.w;
        }
        __syncthreads();
#pragma unroll
        for (int k = 0; k < 16; ++k) {
            float a[8], b[8];
            *(float4*)&a[0] = *(const float4*)&As[k][ty * 8];
            *(float4*)&a[4] = *(const float4*)&As[k][ty * 8 + 4];
            *(float4*)&b[0] = *(const float4*)&Bs[k][tx * 8];
            *(float4*)&b[4] = *(const float4*)&Bs[k][tx * 8 + 4];
#pragma unroll
            for (int ii = 0; ii < 8; ++ii)
#pragma unroll
                for (int jj = 0; jj < 8; ++jj) acc[ii][jj] += a[ii] * b[jj];
        }
        __syncthreads();
    }
#pragma unroll
    for (int ii = 0; ii < 8; ++ii) {
        int gr = bm + ty * 8 + ii;
        if (gr >= M) continue;
#pragma unroll
        for (int jj = 0; jj < 8; ++jj) {
            int gc = bn + tx * 8 + jj;
            if (gc < N) C[(long long)gr * ldc + gc] = acc[ii][jj];
        }
    }
}

// =====================================================================
// states via mma: states[p,n] = sum_j (w_j x[j,p]) * B[j,n]
// per (cc,h,b) block, 128 threads / 4 warps. M=64(p), N=128(n), K=256(j).
// =====================================================================
#define SSM_SMEM (16384 + 32768 + 512)
__global__ void __launch_bounds__(128) states_mma(
    const float* __restrict__ xBC, const float* __restrict__ dtv,
    const float* __restrict__ Acum, float* __restrict__ states)
{
    extern __shared__ __align__(1024) char sm[];
    __half* Xw = (__half*)sm;                 // [128 j][64 p]  16KB (128B rows)
    __half* Bs = (__half*)(sm + 16384);       // [128 j][128 n] 32KB (256B rows)
    float*  wv = (float*)(sm + 49152);        // [128]
    const uint32_t sX = smem_u32(Xw), sB = smem_u32(Bs);

    const int cc = blockIdx.x, h = blockIdx.y, b = blockIdx.z;
    const int tid = threadIdx.x, wid = tid >> 5, lane = tid & 31;
    const float* Ab = Acum + (((size_t)b * NHEADS + h) * NCHUNK + cc) * CSIZE;
    const float AcLast = Ab[CSIZE - 1];
    const int l0 = b * LSEQ + cc * CSIZE;

    float c[4][4][4];
#pragma unroll
    for (int mt = 0; mt < 4; ++mt)
#pragma unroll
        for (int nt = 0; nt < 4; ++nt)
#pragma unroll
            for (int q = 0; q < 4; ++q) c[mt][nt][q] = 0.f;

    for (int jt = 0; jt < CSIZE; jt += 128) {
        wv[tid] = __expf(AcLast - Ab[jt + tid]) * dtv[(size_t)(l0 + jt + tid) * NHEADS + h];
        __syncthreads();
        // stage Xw: w_j * x[j][p], fp16, SW128
#pragma unroll
        for (int it = 0; it < 8; ++it) {
            int u = tid + it * 128;
            int j = u >> 3, cu = u & 7;
            const float* src = &xBC[(size_t)(l0 + jt + j) * CONVDIM + h * HDIM + cu * 8];
            float w = wv[j];
            float v[8];
            float4 v0 = *(const float4*)src, v1 = *(const float4*)(src + 4);
            v[0] = v0.x * w; v[1] = v0.y * w; v[2] = v0.z * w; v[3] = v0.w * w;
            v[4] = v1.x * w; v[5] = v1.y * w; v[6] = v1.z * w; v[7] = v1.w * w;
            *(uint4*)((char*)Xw + SW128((uint32_t)(j * 128 + cu * 16))) = pack8h(v);
        }
        // stage Bs: B[j][n], fp16, SW256
#pragma unroll
        for (int it = 0; it < 16; ++it) {
            int u = tid + it * 128;
            int j = u >> 4, cu = u & 15;
            const float* src = &xBC[(size_t)(l0 + jt + j) * CONVDIM + INTERD + cu * 8];
            float v[8];
            float4 v0 = *(const float4*)src, v1 = *(const float4*)(src + 4);
            v[0] = v0.x; v[1] = v0.y; v[2] = v0.z; v[3] = v0.w;
            v[4] = v1.x; v[5] = v1.y; v[6] = v1.z; v[7] = v1.w;
            *(uint4*)((char*)Bs + SW256((uint32_t)(j * 256 + cu * 16))) = pack8h(v);
        }
        __syncthreads();
#pragma unroll
        for (int ks = 0; ks < 8; ++ks) {
            uint32_t a[4][4], bf[4][2];
#pragma unroll
            for (int mt = 0; mt < 4; ++mt) {
                int row = ks * 16 + ((lane >> 4) & 1) * 8 + (lane & 7);
                int col = mt * 16 + ((lane >> 3) & 1) * 8;
                ldsm4t(a[mt][0], a[mt][1], a[mt][2], a[mt][3],
                       sX + SW128((uint32_t)(row * 128 + col * 2)));
            }
#pragma unroll
            for (int nt2 = 0; nt2 < 2; ++nt2) {
                int row = ks * 16 + ((lane >> 3) & 1) * 8 + (lane & 7);
                int col = wid * 32 + nt2 * 16 + (lane >> 4) * 8;
                uint32_t r0, r1, r2, r3;
                ldsm4t(r0, r1, r2, r3, sB + SW256((uint32_t)(row * 256 + col * 2)));
                bf[nt2 * 2][0] = r0; bf[nt2 * 2][1] = r1;
                bf[nt2 * 2 + 1][0] = r2; bf[nt2 * 2 + 1][1] = r3;
            }
#pragma unroll
            for (int mt = 0; mt < 4; ++mt)
#pragma unroll
                for (int nt = 0; nt < 4; ++nt)
                    mma16816(c[mt][nt], a[mt], bf[nt]);
        }
        __syncthreads();
    }
    float* so = states + (((size_t)b * NCHUNK + cc) * NHEADS + h) * (HDIM * NSTATE);
#pragma unroll
    for (int mt = 0; mt < 4; ++mt) {
        int p0 = mt * 16 + (lane >> 2);
#pragma unroll
        for (int nt = 0; nt < 4; ++nt) {
            int n = wid * 32 + nt * 8 + (lane & 3) * 2;
            *(float2*)&so[p0 * NSTATE + n] = make_float2(c[mt][nt][0], c[mt][nt][1]);
            *(float2*)&so[(p0 + 8) * NSTATE + n] = make_float2(c[mt][nt][2], c[mt][nt][3]);
        }
    }
}

// ---------------- inter-chunk recurrence -> fp16 prev ----------------
__global__ void scan_kernel(const float* __restrict__ states,
                            const float* __restrict__ Acum,
                            __half* __restrict__ prevh)
{
    int h = blockIdx.x, b = blockIdx.y, tid = threadIdx.x;
    float carry[32];
#pragma unroll
    for (int t = 0; t < 32; ++t) carry[t] = 0.f;
    for (int cc = 0; cc < NCHUNK; ++cc) {
        float cd = expf(Acum[(((size_t)b * NHEADS + h) * NCHUNK + cc) * CSIZE + CSIZE - 1]);
        size_t base = (((size_t)b * NCHUNK + cc) * NHEADS + h) * (HDIM * NSTATE);
#pragma unroll
        for (int t = 0; t < 32; ++t) {
            size_t idx = base + tid + t * 256;
            prevh[idx] = __float2half(carry[t]);
            carry[t]   = cd * carry[t] + states[idx];
        }
    }
}

// =====================================================================
// Y via mma: Y[i,p] = M @ X + Ce @ prev^T + D*x
// per (cc,h,b) block, 256 threads / 8 warps. M=256(i), N=64(p).
// =====================================================================
__global__ void __launch_bounds__(256) y_mma(
    const float* __restrict__ xBC, const float* __restrict__ dtv,
    const float* __restrict__ Acum, const float* __restrict__ CB,
    const __half* __restrict__ prevh, const float* __restrict__ Dp,
    float* __restrict__ Y)
{
    __shared__ float Ac[CSIZE], dts[CSIZE], rowf[CSIZE], eA[CSIZE], colf[64];
    __shared__ __align__(1024) __half Ms[CSIZE * 64];   // 32KB, [i][64] 128B rows
    __shared__ __align__(1024) __half Xs[64 * 64];      // 8KB,  [j|p][64] 128B rows
    const uint32_t sM = smem_u32(Ms), sXs = smem_u32(Xs);

    const int cc = blockIdx.x, h = blockIdx.y, b = blockIdx.z;
    const int tid = threadIdx.x, wid = tid >> 5, lane = tid & 31;
    const int wm = (wid & 3) * 64;     // 4 warps over i
    const int wn = (wid >> 2) * 32;    // 2 warps over p
    const int l0 = b * LSEQ + cc * CSIZE;

    Ac[tid]  = Acum[(((size_t)b * NHEADS + h) * NCHUNK + cc) * CSIZE + tid];
    dts[tid] = dtv[(size_t)(l0 + tid) * NHEADS + h];
    __syncthreads();
    eA[tid] = __expf(Ac[tid]);

    const float* CBb = CB + ((size_t)b * NCHUNK + cc) * CSIZE * CSIZE;

    float c[4][4][4];
#pragma unroll
    for (int mt = 0; mt < 4; ++mt)
#pragma unroll
        for (int nt = 0; nt < 4; ++nt)
#pragma unroll
            for (int q = 0; q < 4; ++q) c[mt][nt][q] = 0.f;

    // ---- Ydiag: 4 j-tiles of 64 ----
    for (int jt = 0; jt < CSIZE; jt += 64) {
        float A_ref = Ac[jt + 63];
        if (tid < 64) colf[tid] = __expf(A_ref - Ac[jt + tid]) * dts[jt + tid];
        rowf[tid] = __expf(Ac[tid] - A_ref);   // valid (<=1) only for tid >= jt+64
        __syncthreads();
        // build M tile [256][64] fp16
#pragma unroll
        for (int it = 0; it < 8; ++it) {
            int u = tid + it * 256;
            int i = u >> 3, cu = u & 7;
            float v[8];
            if (i < jt) {
#pragma unroll
                for (int e = 0; e < 8; ++e) v[e] = 0.f;
            } else if (i >= jt + 64) {
                const float* cbp = &CBb[(size_t)i * CSIZE + jt + cu * 8];
                float rf = rowf[i];
#pragma unroll
                for (int e = 0; e < 8; ++e) v[e] = cbp[e] * rf * colf[cu * 8 + e];
            } else {
                const float* cbp = &CBb[(size_t)i * CSIZE + jt + cu * 8];
#pragma unroll
                for (int e = 0; e < 8; ++e) {
                    int j = jt + cu * 8 + e;
                    v[e] = (j <= i) ? cbp[e] * __expf(Ac[i] - Ac[j]) * dts[j] : 0.f;
                }
            }
            *(uint4*)((char*)Ms + SW128((uint32_t)(i * 128 + cu * 16))) = pack8h(v);
        }
        // stage X tile [64 j][64 p] fp16
#pragma unroll
        for (int it = 0; it < 2; ++it) {
            int u = tid + it * 256;
            int j = u >> 3, cu = u & 7;
            const float* src = &xBC[(size_t)(l0 + jt + j) * CONVDIM + h * HDIM + cu * 8];
            float v[8];
            float4 v0 = *(const float4*)src, v1 = *(const float4*)(src + 4);
            v[0] = v0.x; v[1] = v0.y; v[2] = v0.z; v[3] = v0.w;
            v[4] = v1.x; v[5] = v1.y; v[6] = v1.z; v[7] = v1.w;
            *(uint4*)((char*)Xs + SW128((uint32_t)(j * 128 + cu * 16))) = pack8h(v);
        }
        __syncthreads();
#pragma unroll
        for (int ks = 0; ks < 4; ++ks) {
            uint32_t a[4][4], bf[4][2];
#pragma unroll
            for (int mt = 0; mt < 4; ++mt) {
                int row = wm + mt * 16 + (lane & 15);
                int kb  = ks * 32 + (lane >> 4) * 16;
                ldsm4(a[mt][0], a[mt][1], a[mt][2], a[mt][3],
                      sM + SW128((uint32_t)(row * 128 + kb)));
            }
#pragma unroll
            for (int nt2 = 0; nt2 < 2; ++nt2) {
                int row = ks * 16 + ((lane >> 3) & 1) * 8 + (lane & 7);
                int col = wn + nt2 * 16 + (lane >> 4) * 8;
                uint32_t r0, r1, r2, r3;
                ldsm4t(r0, r1, r2, r3, sXs + SW128((uint32_t)(row * 128 + col * 2)));
                bf[nt2 * 2][0] = r0; bf[nt2 * 2][1] = r1;
                bf[nt2 * 2 + 1][0] = r2; bf[nt2 * 2 + 1][1] = r3;
            }
#pragma unroll
            for (int mt = 0; mt < 4; ++mt)
#pragma unroll
                for (int nt = 0; nt < 4; ++nt)
                    mma16816(c[mt][nt], a[mt], bf[nt]);
        }
        __syncthreads();
    }

    // ---- Yoff: 2 n-tiles of 64 (K = NSTATE) ----
    const __half* pvb = prevh + (((size_t)b * NCHUNK + cc) * NHEADS + h) * (HDIM * NSTATE);
    for (int nt0 = 0; nt0 < NSTATE; nt0 += 64) {
        // stage Ce [256][64] = C[i][n]*eA[i]
#pragma unroll
        for (int it = 0; it < 8; ++it) {
            int u = tid + it * 256;
            int i = u >> 3, cu = u & 7;
            const float* src = &xBC[(size_t)(l0 + i) * CONVDIM + INTERD + NSTATE + nt0 + cu * 8];
            float ea = eA[i];
            float v[8];
            float4 v0 = *(const float4*)src, v1 = *(const float4*)(src + 4);
            v[0] = v0.x * ea; v[1] = v0.y * ea; v[2] = v0.z * ea; v[3] = v0.w * ea;
            v[4] = v1.x * ea; v[5] = v1.y * ea; v[6] = v1.z * ea; v[7] = v1.w * ea;
            *(uint4*)((char*)Ms + SW128((uint32_t)(i * 128 + cu * 16))) = pack8h(v);
        }
        // stage prev tile [64 p][64 n] fp16 (direct copy)
#pragma unroll
        for (int it = 0; it < 2; ++it) {
            int u = tid + it * 256;
            int p = u >> 3, cu = u & 7;
            uint4 v = *(const uint4*)(pvb + (size_t)p * NSTATE + nt0 + cu * 8);
            *(uint4*)((char*)Xs + SW128((uint32_t)(p * 128 + cu * 16))) = v;
        }
        __syncthreads();
#pragma unroll
        for (int ks = 0; ks < 4; ++ks) {
            uint32_t a[4][4], bf[4][2];
#pragma unroll
            for (int mt = 0; mt < 4; ++mt) {
                int row = wm + mt * 16 + (lane & 15);
                int kb  = ks * 32 + (lane >> 4) * 16;
                ldsm4(a[mt][0], a[mt][1], a[mt][2], a[mt][3],
                      sM + SW128((uint32_t)(row * 128 + kb)));
            }
#pragma unroll
            for (int nt2 = 0; nt2 < 2; ++nt2) {
                int prow = wn + nt2 * 16 + ((lane >> 4) & 1) * 8 + (lane & 7);
                int kb   = ks * 32 + ((lane >> 3) & 1) * 16;
                uint32_t r0, r1, r2, r3;
                ldsm4(r0, r1, r2, r3, sXs + SW128((uint32_t)(prow * 128 + kb)));
                bf[nt2 * 2][0] = r0; bf[nt2 * 2][1] = r1;
                bf[nt2 * 2 + 1][0] = r2; bf[nt2 * 2 + 1][1] = r3;
            }
#pragma unroll
            for (int mt = 0; mt < 4; ++mt)
#pragma unroll
                for (int nt = 0; nt < 4; ++nt)
                    mma16816(c[mt][nt], a[mt], bf[nt]);
        }
        __syncthreads();
    }

    // ---- epilogue: + D*x, write Y ----
    float Dh = Dp[h];
#pragma unroll
    for (int mt = 0; mt < 4; ++mt) {
        int i0 = wm + mt * 16 + (lane >> 2);
#pragma unroll
        for (int nt = 0; nt < 4; ++nt) {
            int p = wn + nt * 8 + (lane & 3) * 2;
#pragma unroll
            for (int half = 0; half < 2; ++half) {
                int i = i0 + half * 8;
                float2 xv = *(const float2*)&xBC[(size_t)(l0 + i) * CONVDIM + h * HDIM + p];
                float2 ov;
                ov.x = c[mt][nt][half * 2 + 0] + Dh * xv.x;
                ov.y = c[mt][nt][half * 2 + 1] + Dh * xv.y;
                *(float2*)&Y[(size_t)(l0 + i) * INTERD + h * HDIM + p] = ov;
            }
        }
    }
}

// ---------------- gate (silu) + RMSNorm -> fp16 Y2 ----------------
__global__ void gate_rms_kernel(const float* __restrict__ proj,
                                const float* __restrict__ norm_w,
                                const float* __restrict__ Y,
                                __half* __restrict__ Y2)
{
    int row = blockIdx.x, tid = threadIdx.x;
    const float* gr = proj + (size_t)row * PROJDIM;
    const float* yr = Y + (size_t)row * INTERD;
    float yv[16];
    float ss = 0.f;
#pragma unroll
    for (int t = 0; t < 16; ++t) {
        int e = tid + t * 256;
        float g = gr[e];
        float v = yr[e] * (g / (1.f + __expf(-g)));
        yv[t] = v;
        ss += v * v;
    }
    __shared__ float red[8];
#pragma unroll
    for (int o = 16; o > 0; o >>= 1) ss += __shfl_xor_sync(0xffffffff, ss, o);
    if ((tid & 31) == 0) red[tid >> 5] = ss;
    __syncthreads();
    float tot = 0.f;
#pragma unroll
    for (int w = 0; w < 8; ++w) tot += red[w];
    float scale = rsqrtf(tot / (float)INTERD + EPSV);
    __half* y2r = Y2 + (size_t)row * INTERD;
#pragma unroll
    for (int t = 0; t < 16; ++t) {
        int e = tid + t * 256;
        y2r[e] = __float2half(yv[t] * scale * norm_w[e]);
    }
}

// ---------------- launch ----------------
extern "C" void kernel_launch(void* const* d_in, const int* in_sizes, int n_in,
                              void* d_out, int out_size)
{
    const float* hs      = (const float*)d_in[0];
    const float* W_in    = (const float*)d_in[1];
    const float* conv_w  = (const float*)d_in[2];
    const float* conv_b  = (const float*)d_in[3];
    const float* dt_bias = (const float*)d_in[4];
    const float* A_log   = (const float*)d_in[5];
    const float* Dp      = (const float*)d_in[6];
    const float* norm_w  = (const float*)d_in[7];
    const float* W_out   = (const float*)d_in[8];
    float* out = (float*)d_out;

    float *proj, *xBC, *dtv, *Acum, *CB, *states, *Y;
    __half *prevh, *A2, *Win2, *Y2, *Wout2;
    cudaGetSymbolAddress((void**)&proj,   g_proj);
    cudaGetSymbolAddress((void**)&xBC,    g_xBC);
    cudaGetSymbolAddress((void**)&dtv,    g_dtv);
    cudaGetSymbolAddress((void**)&Acum,   g_Acum);
    cudaGetSymbolAddress((void**)&CB,     g_CB);
    cudaGetSymbolAddress((void**)&states, g_states);
    cudaGetSymbolAddress((void**)&prevh,  g_prevh);
    cudaGetSymbolAddress((void**)&Y,      g_Y);
    cudaGetSymbolAddress((void**)&A2,     g_A2);
    cudaGetSymbolAddress((void**)&Win2,   g_Win2);
    cudaGetSymbolAddress((void**)&Y2,     g_Y2);
    cudaGetSymbolAddress((void**)&Wout2,  g_Wout2);

    cudaFuncSetAttribute(gemm_fp16_mma,
                         cudaFuncAttributeMaxDynamicSharedMemorySize, TSMEM);
    cudaFuncSetAttribute(states_mma,
                         cudaFuncAttributeMaxDynamicSharedMemorySize, SSM_SMEM);

    // 0) convert fp32 -> fp16
    {
        long long t4;
        t4 = (long long)BL * DMODEL / 4;
        cvt_fp16_kernel<<<(unsigned)((t4 + 255) / 256), 256>>>(hs, A2, t4);
        t4 = (long long)PROJDIM * DMODEL / 4;
        cvt_fp16_kernel<<<(unsigned)((t4 + 255) / 256), 256>>>(W_in, Win2, t4);
        t4 = (long long)DMODEL * INTERD / 4;
        cvt_fp16_kernel<<<(unsigned)((t4 + 255) / 256), 256>>>(W_out, Wout2, t4);
    }

    // 1) proj = hs @ W_in^T
    gemm_fp16_mma<<<dim3(BL / 128, (PROJDIM + 255) / 256), 256, TSMEM>>>(
        A2, Win2, proj, BL, PROJDIM, DMODEL, PROJDIM);

    // 2) conv + silu
    {
        int total = BL * CONVDIM;
        conv_silu_kernel<<<(total + 255) / 256, 256>>>(proj, conv_w, conv_b, xBC);
    }

    // 3) softplus(dt) + cumsum
    dt_acum_kernel<<<dim3(NCHUNK, NHEADS, BATCH), CSIZE>>>(proj, dt_bias, A_log, dtv, Acum);

    // 4) CB = C . B^T (fp32, shared across heads)
    sgemm_nt<<<dim3(2, 2, BATCH * NCHUNK), 256>>>(
        xBC + (INTERD + NSTATE), xBC + INTERD, CB,
        CSIZE, CSIZE, NSTATE, CONVDIM, CONVDIM, CSIZE,
        (long long)CSIZE * CONVDIM, (long long)CSIZE * CONVDIM, (long long)CSIZE * CSIZE);

    // 5) states via mma
    states_mma<<<dim3(NCHUNK, NHEADS, BATCH), 128, SSM_SMEM>>>(xBC, dtv, Acum, states);

    // 6) scan -> fp16 prev
    scan_kernel<<<dim3(NHEADS, BATCH), 256>>>(states, Acum, prevh);

    // 7) Y via mma (Ydiag + Yoff + D*x)
    y_mma<<<dim3(NCHUNK, NHEADS, BATCH), 256>>>(xBC, dtv, Acum, CB, prevh, Dp, Y);

    // 8) gate + RMSNorm -> fp16
    gate_rms_kernel<<<BL, 256>>>(proj, norm_w, Y, Y2);

    // 9) out = Y @ W_out^T
    gemm_fp16_mma<<<dim3(BL / 128, DMODEL / 256), 256, TSMEM>>>(
        Y2, Wout2, out, BL, DMODEL, INTERD, DMODEL);
}

// round 7
// speedup vs baseline: 6.4489x; 1.0009x over previous
#include <cuda_runtime.h>
#include <cuda_fp16.h>
#include <cstdint>

// ---------------- problem constants ----------------
#define BATCH    2
#define LSEQ     2048
#define DMODEL   2048
#define INTERD   4096
#define NHEADS   64
#define HDIM     64
#define NSTATE   128
#define KCONV    4
#define CSIZE    256
#define NCHUNK   (LSEQ / CSIZE)                 // 8
#define CONVDIM  (INTERD + 2 * NSTATE)          // 4352
#define PROJDIM  (INTERD + CONVDIM + NHEADS)    // 8512
#define BL       (BATCH * LSEQ)                 // 4096
#define EPSV     1e-5f

// ---------------- device scratch (static; no allocs allowed) ----------------
__device__ float g_proj  [(size_t)BL * PROJDIM];
__device__ float g_xBC   [(size_t)BL * CONVDIM];
__device__ float g_dtv   [(size_t)BL * NHEADS];
__device__ float g_Acum  [(size_t)BATCH * NHEADS * NCHUNK * CSIZE];
__device__ float g_CB    [(size_t)BATCH * NCHUNK * CSIZE * CSIZE];
__device__ float g_states[(size_t)BATCH * NCHUNK * NHEADS * HDIM * NSTATE];
__device__ __half g_prevh[(size_t)BATCH * NCHUNK * NHEADS * HDIM * NSTATE];
__device__ float g_Y     [(size_t)BL * INTERD];
// plain fp16 operands
__device__ __half g_A2   [(size_t)BL * DMODEL];
__device__ __half g_Win2 [(size_t)PROJDIM * DMODEL];
__device__ __half g_Y2   [(size_t)BL * INTERD];
__device__ __half g_Wout2[(size_t)DMODEL * INTERD];

// =====================================================================
// common mma helpers
// =====================================================================
__device__ __forceinline__ uint32_t smem_u32(const void* p) {
    return (uint32_t)__cvta_generic_to_shared(p);
}
#define SW128(o) ((o) ^ (((o) >> 3) & 0x70))
#define SW256(o) ((o) ^ (((o) >> 4) & 0x70))

__device__ __forceinline__ void cp_async16(uint32_t d, const void* g, int sz) {
    asm volatile("cp.async.cg.shared.global [%0], [%1], 16, %2;"
                 :: "r"(d), "l"(g), "r"(sz) : "memory");
}
#define CP_COMMIT() asm volatile("cp.async.commit_group;" ::: "memory")
#define CP_WAIT2()  asm volatile("cp.async.wait_group 2;" ::: "memory")

__device__ __forceinline__ void ldsm4(uint32_t& r0, uint32_t& r1, uint32_t& r2,
                                      uint32_t& r3, uint32_t a) {
    asm volatile("ldmatrix.sync.aligned.m8n8.x4.shared.b16 {%0,%1,%2,%3}, [%4];"
                 : "=r"(r0), "=r"(r1), "=r"(r2), "=r"(r3) : "r"(a));
}
__device__ __forceinline__ void ldsm4t(uint32_t& r0, uint32_t& r1, uint32_t& r2,
                                       uint32_t& r3, uint32_t a) {
    asm volatile("ldmatrix.sync.aligned.m8n8.x4.trans.shared.b16 {%0,%1,%2,%3}, [%4];"
                 : "=r"(r0), "=r"(r1), "=r"(r2), "=r"(r3) : "r"(a));
}
__device__ __forceinline__ void mma16816(float* c, const uint32_t* a, const uint32_t* b) {
    asm volatile(
        "mma.sync.aligned.m16n8k16.row.col.f32.f16.f16.f32 "
        "{%0,%1,%2,%3}, {%4,%5,%6,%7}, {%8,%9}, {%0,%1,%2,%3};"
        : "+f"(c[0]), "+f"(c[1]), "+f"(c[2]), "+f"(c[3])
        : "r"(a[0]), "r"(a[1]), "r"(a[2]), "r"(a[3]), "r"(b[0]), "r"(b[1]));
}

__device__ __forceinline__ uint4 pack8h(const float* v) {
    __half h[8];
#pragma unroll
    for (int e = 0; e < 8; ++e) h[e] = __float2half(v[e]);
    uint4 r;
    r.x = ((uint32_t)*(uint16_t*)&h[1] << 16) | *(uint16_t*)&h[0];
    r.y = ((uint32_t)*(uint16_t*)&h[3] << 16) | *(uint16_t*)&h[2];
    r.z = ((uint32_t)*(uint16_t*)&h[5] << 16) | *(uint16_t*)&h[4];
    r.w = ((uint32_t)*(uint16_t*)&h[7] << 16) | *(uint16_t*)&h[6];
    return r;
}

// =====================================================================
// big fp16 GEMM: 512 threads, 16 warps (warp tile 64x32), 4-stage ring
// =====================================================================
#define TSTAGE_B (128 * 128 + 256 * 128)     // 49152
#define TNSTG    4
#define TSMEM    (TNSTG * TSTAGE_B)          // 196608

__global__ void __launch_bounds__(512, 1) gemm_fp16_mma(
    const __half* __restrict__ A, const __half* __restrict__ Bm,
    float* __restrict__ C, int M, int N, int K, int ldc)
{
    extern __shared__ __align__(1024) char smem[];
    const uint32_t sbase = smem_u32(smem);
    const int tid  = threadIdx.x;
    const int wid  = tid >> 5, lane = tid & 31;
    const int bm   = blockIdx.x * 128, bn = blockIdx.y * 256;
    const int wm   = (wid & 1) * 64;          // 2 warps over M
    const int wn   = (wid >> 1) * 32;         // 8 warps over N
    const int KT   = K >> 6;

    float c[4][4][4];
#pragma unroll
    for (int mt = 0; mt < 4; ++mt)
#pragma unroll
        for (int nt = 0; nt < 4; ++nt)
#pragma unroll
            for (int q = 0; q < 4; ++q) c[mt][nt][q] = 0.f;

#define LOAD_STAGE(kt, s) do {                                               \
    uint32_t st_ = sbase + (s) * TSTAGE_B;                                   \
    _Pragma("unroll")                                                        \
    for (int i_ = 0; i_ < 2; ++i_) {                                         \
        int u_ = tid + i_ * 512;                                             \
        int r_ = u_ >> 3, lu_ = u_ & 7;                                      \
        uint32_t d_ = st_ + SW128((uint32_t)(r_ * 128 + lu_ * 16));          \
        const void* g_ = (const char*)A +                                    \
            (((size_t)(bm + r_) * K + (size_t)(kt) * 64 + lu_ * 8) << 1);    \
        cp_async16(d_, g_, 16);                                              \
    }                                                                        \
    _Pragma("unroll")                                                        \
    for (int i_ = 0; i_ < 4; ++i_) {                                         \
        int u_ = tid + i_ * 512;                                             \
        int r_ = u_ >> 3, lu_ = u_ & 7;                                      \
        int gn_ = bn + r_;                                                   \
        uint32_t d_ = st_ + 16384 + SW128((uint32_t)(r_ * 128 + lu_ * 16));  \
        const void* g_ = (const char*)Bm +                                   \
            (((size_t)gn_ * K + (size_t)(kt) * 64 + lu_ * 8) << 1);          \
        cp_async16(d_, g_, gn_ < N ? 16 : 0);                                \
    }                                                                        \
} while (0)

    LOAD_STAGE(0, 0); CP_COMMIT();
    LOAD_STAGE(1, 1); CP_COMMIT();
    LOAD_STAGE(2, 2); CP_COMMIT();

    const int a_row = (lane & 15);
    const int a_ku  = (lane >> 4) * 16;
    const int b_row = ((lane >> 4) & 1) * 8 + (lane & 7);
    const int b_ku  = ((lane >> 3) & 1) * 16;

    for (int kt = 0; kt < KT; ++kt) {
        const int s = kt & 3;
        CP_WAIT2();
        __syncthreads();
        if (kt + 3 < KT) LOAD_STAGE(kt + 3, (kt + 3) & 3);
        CP_COMMIT();

        const uint32_t stA = sbase + s * TSTAGE_B;
        const uint32_t stB = stA + 16384;
#pragma unroll
        for (int ks = 0; ks < 4; ++ks) {
            uint32_t a[4][4], b[4][2];
#pragma unroll
            for (int mt = 0; mt < 4; ++mt) {
                uint32_t off = (uint32_t)((wm + mt * 16 + a_row) * 128 + ks * 32 + a_ku);
                ldsm4(a[mt][0], a[mt][1], a[mt][2], a[mt][3], stA + SW128(off));
            }
#pragma unroll
            for (int pr = 0; pr < 2; ++pr) {
                uint32_t off = (uint32_t)((wn + pr * 16 + b_row) * 128 + ks * 32 + b_ku);
                uint32_t r0, r1, r2, r3;
                ldsm4(r0, r1, r2, r3, stB + SW128(off));
                b[pr * 2][0] = r0; b[pr * 2][1] = r1;
                b[pr * 2 + 1][0] = r2; b[pr * 2 + 1][1] = r3;
            }
#pragma unroll
            for (int mt = 0; mt < 4; ++mt)
#pragma unroll
                for (int nt = 0; nt < 4; ++nt)
                    mma16816(c[mt][nt], a[mt], b[nt]);
        }
    }

#pragma unroll
    for (int mt = 0; mt < 4; ++mt) {
        int r0 = bm + wm + mt * 16 + (lane >> 2);
#pragma unroll
        for (int nt = 0; nt < 4; ++nt) {
            int col = bn + wn + nt * 8 + (lane & 3) * 2;
            if (col < N) {
                float2 v0 = make_float2(c[mt][nt][0], c[mt][nt][1]);
                float2 v1 = make_float2(c[mt][nt][2], c[mt][nt][3]);
                *(float2*)&C[(size_t)r0 * ldc + col] = v0;
                *(float2*)&C[(size_t)(r0 + 8) * ldc + col] = v1;
            }
        }
    }
}

// ---------------- fp32 -> fp16 convert ----------------
__global__ void cvt_fp16_kernel(const float* __restrict__ src,
                                __half* __restrict__ dst, long long total4)
{
    long long t = (long long)blockIdx.x * blockDim.x + threadIdx.x;
    if (t >= total4) return;
    float4 a = *(const float4*)(src + t * 4);
    __half h[4];
    h[0] = __float2half(a.x); h[1] = __float2half(a.y);
    h[2] = __float2half(a.z); h[3] = __float2half(a.w);
    uint2 v;
    v.x = ((uint32_t)*(uint16_t*)&h[1] << 16) | *(uint16_t*)&h[0];
    v.y = ((uint32_t)*(uint16_t*)&h[3] << 16) | *(uint16_t*)&h[2];
    *(uint2*)(dst + t * 4) = v;
}

// ---------------- depthwise causal conv (K=4) + bias + silu ----------------
__global__ void conv_silu_kernel(const float* __restrict__ proj,
                                 const float* __restrict__ cw,
                                 const float* __restrict__ cb,
                                 float* __restrict__ xBC)
{
    int idx = blockIdx.x * blockDim.x + threadIdx.x;
    if (idx >= BL * CONVDIM) return;
    int ch = idx % CONVDIM;
    int bl = idx / CONVDIM;
    int l  = bl % LSEQ;
    float4 w = *(const float4*)&cw[ch * 4];
    float acc = cb[ch];
    const float* base = proj + (size_t)bl * PROJDIM + INTERD + ch;
    if (l >= 3) {
        acc += w.x * base[-3 * PROJDIM] + w.y * base[-2 * PROJDIM]
             + w.z * base[-1 * PROJDIM] + w.w * base[0];
    } else {
        float wk[4] = {w.x, w.y, w.z, w.w};
        for (int k = 3 - l; k < 4; ++k) acc += wk[k] * base[(k - 3) * PROJDIM];
    }
    xBC[idx] = acc / (1.f + __expf(-acc));
}

// ---------------- softplus(dt+bias), per-chunk inclusive cumsum ----------------
__global__ void dt_acum_kernel(const float* __restrict__ proj,
                               const float* __restrict__ dt_bias,
                               const float* __restrict__ A_log,
                               float* __restrict__ dtv,
                               float* __restrict__ Acum)
{
    int cc = blockIdx.x, h = blockIdx.y, b = blockIdx.z;
    int i  = threadIdx.x;
    int l  = cc * CSIZE + i;
    float d  = proj[(size_t)(b * LSEQ + l) * PROJDIM + INTERD + CONVDIM + h] + dt_bias[h];
    float sp = (d > 20.f) ? d : log1pf(expf(d));
    dtv[(size_t)(b * LSEQ + l) * NHEADS + h] = sp;
    float dA = sp * (-expf(A_log[h]));
    __shared__ float sbuf[CSIZE];
    sbuf[i] = dA;
    __syncthreads();
    for (int off = 1; off < CSIZE; off <<= 1) {
        float v = sbuf[i];
        if (i >= off) v += sbuf[i - off];
        __syncthreads();
        sbuf[i] = v;
        __syncthreads();
    }
    Acum[(((size_t)b * NHEADS + h) * NCHUNK + cc) * CSIZE + i] = sbuf[i];
}

// ---------------- generic NT SGEMM (CB gemm only) ----------------
__global__ __launch_bounds__(256) void sgemm_nt(
    const float* __restrict__ A, const float* __restrict__ B, float* __restrict__ C,
    int M, int N, int K, int lda, int ldb, int ldc,
    long long sA, long long sB, long long sC)
{
    A += (long long)blockIdx.z * sA;
    B += (long long)blockIdx.z * sB;
    C += (long long)blockIdx.z * sC;
    const int bm = blockIdx.y * 128, bn = blockIdx.x * 128;
    __shared__ float As[16][128];
    __shared__ float Bs[16][128];
    const int tid = threadIdx.x;
    const int lr = tid >> 2;
    const int lc = (tid & 3) << 2;
    const int tx = tid & 15, ty = tid >> 4;

    float acc[8][8];
#pragma unroll
    for (int i = 0; i < 8; ++i)
#pragma unroll
        for (int j = 0; j < 8; ++j) acc[i][j] = 0.f;

    for (int k0 = 0; k0 < K; k0 += 16) {
#pragma unroll
        for (int r = 0; r < 2; ++r) {
            int row = lr + r * 64;
            int gr  = bm + row;
            float4 v = make_float4(0.f, 0.f, 0.f, 0.f);
            if (gr < M) v = *(const float4*)&A[(long long)gr * lda + k0 + lc];
            As[lc + 0][row] = v.x; As[lc + 1][row] = v.y;
            As[lc + 2][row] = v.z; As[lc + 3][row] = v.w;
        }
#pragma unroll
        for (int r = 0; r < 2; ++r) {
            int row = lr + r * 64;
            int gr  = bn + row;
            float4 v = make_float4(0.f, 0.f, 0.f, 0.f);
            if (gr < N) v = *(const float4*)&B[(long long)gr * ldb + k0 + lc];
            Bs[lc + 0][row] = v.x; Bs[lc + 1][row] = v.y;
            Bs[lc + 2][row] = v.z; Bs[lc + 3][row] = v.w;
        }
        __syncthreads();
#pragma unroll
        for (int k = 0; k < 16; ++k) {
            float a[8], b[8];
            *(float4*)&a[0] = *(const float4*)&As[k][ty * 8];
            *(float4*)&a[4] = *(const float4*)&As[k][ty * 8 + 4];
            *(float4*)&b[0] = *(const float4*)&Bs[k][tx * 8];
            *(float4*)&b[4] = *(const float4*)&Bs[k][tx * 8 + 4];
#pragma unroll
            for (int ii = 0; ii < 8; ++ii)
#pragma unroll
                for (int jj = 0; jj < 8; ++jj) acc[ii][jj] += a[ii] * b[jj];
        }
        __syncthreads();
    }
#pragma unroll
    for (int ii = 0; ii < 8; ++ii) {
        int gr = bm + ty * 8 + ii;
        if (gr >= M) continue;
#pragma unroll
        for (int jj = 0; jj < 8; ++jj) {
            int gc = bn + tx * 8 + jj;
            if (gc < N) C[(long long)gr * ldc + gc] = acc[ii][jj];
        }
    }
}

// =====================================================================
// states via mma: states[p,n] = sum_j (w_j x[j,p]) * B[j,n]
// =====================================================================
#define SSM_SMEM (16384 + 32768 + 512)
__global__ void __launch_bounds__(128) states_mma(
    const float* __restrict__ xBC, const float* __restrict__ dtv,
    const float* __restrict__ Acum, float* __restrict__ states)
{
    extern __shared__ __align__(1024) char sm[];
    __half* Xw = (__half*)sm;
    __half* Bs = (__half*)(sm + 16384);
    float*  wv = (float*)(sm + 49152);
    const uint32_t sX = smem_u32(Xw), sB = smem_u32(Bs);

    const int cc = blockIdx.x, h = blockIdx.y, b = blockIdx.z;
    const int tid = threadIdx.x, wid = tid >> 5, lane = tid & 31;
    const float* Ab = Acum + (((size_t)b * NHEADS + h) * NCHUNK + cc) * CSIZE;
    const float AcLast = Ab[CSIZE - 1];
    const int l0 = b * LSEQ + cc * CSIZE;

    float c[4][4][4];
#pragma unroll
    for (int mt = 0; mt < 4; ++mt)
#pragma unroll
        for (int nt = 0; nt < 4; ++nt)
#pragma unroll
            for (int q = 0; q < 4; ++q) c[mt][nt][q] = 0.f;

    for (int jt = 0; jt < CSIZE; jt += 128) {
        wv[tid] = __expf(AcLast - Ab[jt + tid]) * dtv[(size_t)(l0 + jt + tid) * NHEADS + h];
        __syncthreads();
#pragma unroll
        for (int it = 0; it < 8; ++it) {
            int u = tid + it * 128;
            int j = u >> 3, cu = u & 7;
            const float* src = &xBC[(size_t)(l0 + jt + j) * CONVDIM + h * HDIM + cu * 8];
            float w = wv[j];
            float v[8];
            float4 v0 = *(const float4*)src, v1 = *(const float4*)(src + 4);
            v[0] = v0.x * w; v[1] = v0.y * w; v[2] = v0.z * w; v[3] = v0.w * w;
            v[4] = v1.x * w; v[5] = v1.y * w; v[6] = v1.z * w; v[7] = v1.w * w;
            *(uint4*)((char*)Xw + SW128((uint32_t)(j * 128 + cu * 16))) = pack8h(v);
        }
#pragma unroll
        for (int it = 0; it < 16; ++it) {
            int u = tid + it * 128;
            int j = u >> 4, cu = u & 15;
            const float* src = &xBC[(size_t)(l0 + jt + j) * CONVDIM + INTERD + cu * 8];
            float v[8];
            float4 v0 = *(const float4*)src, v1 = *(const float4*)(src + 4);
            v[0] = v0.x; v[1] = v0.y; v[2] = v0.z; v[3] = v0.w;
            v[4] = v1.x; v[5] = v1.y; v[6] = v1.z; v[7] = v1.w;
            *(uint4*)((char*)Bs + SW256((uint32_t)(j * 256 + cu * 16))) = pack8h(v);
        }
        __syncthreads();
#pragma unroll
        for (int ks = 0; ks < 8; ++ks) {
            uint32_t a[4][4], bf[4][2];
#pragma unroll
            for (int mt = 0; mt < 4; ++mt) {
                int row = ks * 16 + ((lane >> 4) & 1) * 8 + (lane & 7);
                int col = mt * 16 + ((lane >> 3) & 1) * 8;
                ldsm4t(a[mt][0], a[mt][1], a[mt][2], a[mt][3],
                       sX + SW128((uint32_t)(row * 128 + col * 2)));
            }
#pragma unroll
            for (int nt2 = 0; nt2 < 2; ++nt2) {
                int row = ks * 16 + ((lane >> 3) & 1) * 8 + (lane & 7);
                int col = wid * 32 + nt2 * 16 + (lane >> 4) * 8;
                uint32_t r0, r1, r2, r3;
                ldsm4t(r0, r1, r2, r3, sB + SW256((uint32_t)(row * 256 + col * 2)));
                bf[nt2 * 2][0] = r0; bf[nt2 * 2][1] = r1;
                bf[nt2 * 2 + 1][0] = r2; bf[nt2 * 2 + 1][1] = r3;
            }
#pragma unroll
            for (int mt = 0; mt < 4; ++mt)
#pragma unroll
                for (int nt = 0; nt < 4; ++nt)
                    mma16816(c[mt][nt], a[mt], bf[nt]);
        }
        __syncthreads();
    }
    float* so = states + (((size_t)b * NCHUNK + cc) * NHEADS + h) * (HDIM * NSTATE);
#pragma unroll
    for (int mt = 0; mt < 4; ++mt) {
        int p0 = mt * 16 + (lane >> 2);
#pragma unroll
        for (int nt = 0; nt < 4; ++nt) {
            int n = wid * 32 + nt * 8 + (lane & 3) * 2;
            *(float2*)&so[p0 * NSTATE + n] = make_float2(c[mt][nt][0], c[mt][nt][1]);
            *(float2*)&so[(p0 + 8) * NSTATE + n] = make_float2(c[mt][nt][2], c[mt][nt][3]);
        }
    }
}

// ---------------- inter-chunk recurrence -> fp16 prev ----------------
__global__ void scan_kernel(const float* __restrict__ states,
                            const float* __restrict__ Acum,
                            __half* __restrict__ prevh)
{
    int h = blockIdx.x, b = blockIdx.y, tid = threadIdx.x;
    float carry[32];
#pragma unroll
    for (int t = 0; t < 32; ++t) carry[t] = 0.f;
    for (int cc = 0; cc < NCHUNK; ++cc) {
        float cd = expf(Acum[(((size_t)b * NHEADS + h) * NCHUNK + cc) * CSIZE + CSIZE - 1]);
        size_t base = (((size_t)b * NCHUNK + cc) * NHEADS + h) * (HDIM * NSTATE);
#pragma unroll
        for (int t = 0; t < 32; ++t) {
            size_t idx = base + tid + t * 256;
            prevh[idx] = __float2half(carry[t]);
            carry[t]   = cd * carry[t] + states[idx];
        }
    }
}

// =====================================================================
// Y via mma: Y[i,p] = M @ X + Ce @ prev^T + D*x
// =====================================================================
__global__ void __launch_bounds__(256) y_mma(
    const float* __restrict__ xBC, const float* __restrict__ dtv,
    const float* __restrict__ Acum, const float* __restrict__ CB,
    const __half* __restrict__ prevh, const float* __restrict__ Dp,
    float* __restrict__ Y)
{
    __shared__ float Ac[CSIZE], dts[CSIZE], rowf[CSIZE], eA[CSIZE], colf[64];
    __shared__ __align__(1024) __half Ms[CSIZE * 64];
    __shared__ __align__(1024) __half Xs[64 * 64];
    const uint32_t sM = smem_u32(Ms), sXs = smem_u32(Xs);

    const int cc = blockIdx.x, h = blockIdx.y, b = blockIdx.z;
    const int tid = threadIdx.x, wid = tid >> 5, lane = tid & 31;
    const int wm = (wid & 3) * 64;
    const int wn = (wid >> 2) * 32;
    const int l0 = b * LSEQ + cc * CSIZE;

    Ac[tid]  = Acum[(((size_t)b * NHEADS + h) * NCHUNK + cc) * CSIZE + tid];
    dts[tid] = dtv[(size_t)(l0 + tid) * NHEADS + h];
    __syncthreads();
    eA[tid] = __expf(Ac[tid]);

    const float* CBb = CB + ((size_t)b * NCHUNK + cc) * CSIZE * CSIZE;

    float c[4][4][4];
#pragma unroll
    for (int mt = 0; mt < 4; ++mt)
#pragma unroll
        for (int nt = 0; nt < 4; ++nt)
#pragma unroll
            for (int q = 0; q < 4; ++q) c[mt][nt][q] = 0.f;

    for (int jt = 0; jt < CSIZE; jt += 64) {
        float A_ref = Ac[jt + 63];
        if (tid < 64) colf[tid] = __expf(A_ref - Ac[jt + tid]) * dts[jt + tid];
        rowf[tid] = __expf(Ac[tid] - A_ref);
        __syncthreads();
#pragma unroll
        for (int it = 0; it < 8; ++it) {
            int u = tid + it * 256;
            int i = u >> 3, cu = u & 7;
            float v[8];
            if (i < jt) {
#pragma unroll
                for (int e = 0; e < 8; ++e) v[e] = 0.f;
            } else if (i >= jt + 64) {
                const float* cbp = &CBb[(size_t)i * CSIZE + jt + cu * 8];
                float rf = rowf[i];
#pragma unroll
                for (int e = 0; e < 8; ++e) v[e] = cbp[e] * rf * colf[cu * 8 + e];
            } else {
                const float* cbp = &CBb[(size_t)i * CSIZE + jt + cu * 8];
#pragma unroll
                for (int e = 0; e < 8; ++e) {
                    int j = jt + cu * 8 + e;
                    v[e] = (j <= i) ? cbp[e] * __expf(Ac[i] - Ac[j]) * dts[j] : 0.f;
                }
            }
            *(uint4*)((char*)Ms + SW128((uint32_t)(i * 128 + cu * 16))) = pack8h(v);
        }
#pragma unroll
        for (int it = 0; it < 2; ++it) {
            int u = tid + it * 256;
            int j = u >> 3, cu = u & 7;
            const float* src = &xBC[(size_t)(l0 + jt + j) * CONVDIM + h * HDIM + cu * 8];
            float v[8];
            float4 v0 = *(const float4*)src, v1 = *(const float4*)(src + 4);
            v[0] = v0.x; v[1] = v0.y; v[2] = v0.z; v[3] = v0.w;
            v[4] = v1.x; v[5] = v1.y; v[6] = v1.z; v[7] = v1.w;
            *(uint4*)((char*)Xs + SW128((uint32_t)(j * 128 + cu * 16))) = pack8h(v);
        }
        __syncthreads();
#pragma unroll
        for (int ks = 0; ks < 4; ++ks) {
            uint32_t a[4][4], bf[4][2];
#pragma unroll
            for (int mt = 0; mt < 4; ++mt) {
                int row = wm + mt * 16 + (lane & 15);
                int kb  = ks * 32 + (lane >> 4) * 16;
                ldsm4(a[mt][0], a[mt][1], a[mt][2], a[mt][3],
                      sM + SW128((uint32_t)(row * 128 + kb)));
            }
#pragma unroll
            for (int nt2 = 0; nt2 < 2; ++nt2) {
                int row = ks * 16 + ((lane >> 3) & 1) * 8 + (lane & 7);
                int col = wn + nt2 * 16 + (lane >> 4) * 8;
                uint32_t r0, r1, r2, r3;
                ldsm4t(r0, r1, r2, r3, sXs + SW128((uint32_t)(row * 128 + col * 2)));
                bf[nt2 * 2][0] = r0; bf[nt2 * 2][1] = r1;
                bf[nt2 * 2 + 1][0] = r2; bf[nt2 * 2 + 1][1] = r3;
            }
#pragma unroll
            for (int mt = 0; mt < 4; ++mt)
#pragma unroll
                for (int nt = 0; nt < 4; ++nt)
                    mma16816(c[mt][nt], a[mt], bf[nt]);
        }
        __syncthreads();
    }

    const __half* pvb = prevh + (((size_t)b * NCHUNK + cc) * NHEADS + h) * (HDIM * NSTATE);
    for (int nt0 = 0; nt0 < NSTATE; nt0 += 64) {
#pragma unroll
        for (int it = 0; it < 8; ++it) {
            int u = tid + it * 256;
            int i = u >> 3, cu = u & 7;
            const float* src = &xBC[(size_t)(l0 + i) * CONVDIM + INTERD + NSTATE + nt0 + cu * 8];
            float ea = eA[i];
            float v[8];
            float4 v0 = *(const float4*)src, v1 = *(const float4*)(src + 4);
            v[0] = v0.x * ea; v[1] = v0.y * ea; v[2] = v0.z * ea; v[3] = v0.w * ea;
            v[4] = v1.x * ea; v[5] = v1.y * ea; v[6] = v1.z * ea; v[7] = v1.w * ea;
            *(uint4*)((char*)Ms + SW128((uint32_t)(i * 128 + cu * 16))) = pack8h(v);
        }
#pragma unroll
        for (int it = 0; it < 2; ++it) {
            int u = tid + it * 256;
            int p = u >> 3, cu = u & 7;
            uint4 v = *(const uint4*)(pvb + (size_t)p * NSTATE + nt0 + cu * 8);
            *(uint4*)((char*)Xs + SW128((uint32_t)(p * 128 + cu * 16))) = v;
        }
        __syncthreads();
#pragma unroll
        for (int ks = 0; ks < 4; ++ks) {
            uint32_t a[4][4], bf[4][2];
#pragma unroll
            for (int mt = 0; mt < 4; ++mt) {
                int row = wm + mt * 16 + (lane & 15);
                int kb  = ks * 32 + (lane >> 4) * 16;
                ldsm4(a[mt][0], a[mt][1], a[mt][2], a[mt][3],
                      sM + SW128((uint32_t)(row * 128 + kb)));
            }
#pragma unroll
            for (int nt2 = 0; nt2 < 2; ++nt2) {
                int prow = wn + nt2 * 16 + ((lane >> 4) & 1) * 8 + (lane & 7);
                int kb   = ks * 32 + ((lane >> 3) & 1) * 16;
                uint32_t r0, r1, r2, r3;
                ldsm4(r0, r1, r2, r3, sXs + SW128((uint32_t)(prow * 128 + kb)));
                bf[nt2 * 2][0] = r0; bf[nt2 * 2][1] = r1;
                bf[nt2 * 2 + 1][0] = r2; bf[nt2 * 2 + 1][1] = r3;
            }
#pragma unroll
            for (int mt = 0; mt < 4; ++mt)
#pragma unroll
                for (int nt = 0; nt < 4; ++nt)
                    mma16816(c[mt][nt], a[mt], bf[nt]);
        }
        __syncthreads();
    }

    float Dh = Dp[h];
#pragma unroll
    for (int mt = 0; mt < 4; ++mt) {
        int i0 = wm + mt * 16 + (lane >> 2);
#pragma unroll
        for (int nt = 0; nt < 4; ++nt) {
            int p = wn + nt * 8 + (lane & 3) * 2;
#pragma unroll
            for (int half = 0; half < 2; ++half) {
                int i = i0 + half * 8;
                float2 xv = *(const float2*)&xBC[(size_t)(l0 + i) * CONVDIM + h * HDIM + p];
                float2 ov;
                ov.x = c[mt][nt][half * 2 + 0] + Dh * xv.x;
                ov.y = c[mt][nt][half * 2 + 1] + Dh * xv.y;
                *(float2*)&Y[(size_t)(l0 + i) * INTERD + h * HDIM + p] = ov;
            }
        }
    }
}

// ---------------- gate (silu) + RMSNorm -> fp16 Y2 ----------------
__global__ void gate_rms_kernel(const float* __restrict__ proj,
                                const float* __restrict__ norm_w,
                                const float* __restrict__ Y,
                                __half* __restrict__ Y2)
{
    int row = blockIdx.x, tid = threadIdx.x;
    const float* gr = proj + (size_t)row * PROJDIM;
    const float* yr = Y + (size_t)row * INTERD;
    float yv[16];
    float ss = 0.f;
#pragma unroll
    for (int t = 0; t < 16; ++t) {
        int e = tid + t * 256;
        float g = gr[e];
        float v = yr[e] * (g / (1.f + __expf(-g)));
        yv[t] = v;
        ss += v * v;
    }
    __shared__ float red[8];
#pragma unroll
    for (int o = 16; o > 0; o >>= 1) ss += __shfl_xor_sync(0xffffffff, ss, o);
    if ((tid & 31) == 0) red[tid >> 5] = ss;
    __syncthreads();
    float tot = 0.f;
#pragma unroll
    for (int w = 0; w < 8; ++w) tot += red[w];
    float scale = rsqrtf(tot / (float)INTERD + EPSV);
    __half* y2r = Y2 + (size_t)row * INTERD;
#pragma unroll
    for (int t = 0; t < 16; ++t) {
        int e = tid + t * 256;
        y2r[e] = __float2half(yv[t] * scale * norm_w[e]);
    }
}

// ---------------- launch ----------------
extern "C" void kernel_launch(void* const* d_in, const int* in_sizes, int n_in,
                              void* d_out, int out_size)
{
    const float* hs      = (const float*)d_in[0];
    const float* W_in    = (const float*)d_in[1];
    const float* conv_w  = (const float*)d_in[2];
    const float* conv_b  = (const float*)d_in[3];
    const float* dt_bias = (const float*)d_in[4];
    const float* A_log   = (const float*)d_in[5];
    const float* Dp      = (const float*)d_in[6];
    const float* norm_w  = (const float*)d_in[7];
    const float* W_out   = (const float*)d_in[8];
    float* out = (float*)d_out;

    float *proj, *xBC, *dtv, *Acum, *CB, *states, *Y;
    __half *prevh, *A2, *Win2, *Y2, *Wout2;
    cudaGetSymbolAddress((void**)&proj,   g_proj);
    cudaGetSymbolAddress((void**)&xBC,    g_xBC);
    cudaGetSymbolAddress((void**)&dtv,    g_dtv);
    cudaGetSymbolAddress((void**)&Acum,   g_Acum);
    cudaGetSymbolAddress((void**)&CB,     g_CB);
    cudaGetSymbolAddress((void**)&states, g_states);
    cudaGetSymbolAddress((void**)&prevh,  g_prevh);
    cudaGetSymbolAddress((void**)&Y,      g_Y);
    cudaGetSymbolAddress((void**)&A2,     g_A2);
    cudaGetSymbolAddress((void**)&Win2,   g_Win2);
    cudaGetSymbolAddress((void**)&Y2,     g_Y2);
    cudaGetSymbolAddress((void**)&Wout2,  g_Wout2);

    cudaFuncSetAttribute(gemm_fp16_mma,
                         cudaFuncAttributeMaxDynamicSharedMemorySize, TSMEM);
    cudaFuncSetAttribute(states_mma,
                         cudaFuncAttributeMaxDynamicSharedMemorySize, SSM_SMEM);

    // 0) convert fp32 -> fp16
    {
        long long t4;
        t4 = (long long)BL * DMODEL / 4;
        cvt_fp16_kernel<<<(unsigned)((t4 + 255) / 256), 256>>>(hs, A2, t4);
        t4 = (long long)PROJDIM * DMODEL / 4;
        cvt_fp16_kernel<<<(unsigned)((t4 + 255) / 256), 256>>>(W_in, Win2, t4);
        t4 = (long long)DMODEL * INTERD / 4;
        cvt_fp16_kernel<<<(unsigned)((t4 + 255) / 256), 256>>>(W_out, Wout2, t4);
    }

    // 1) proj = hs @ W_in^T
    gemm_fp16_mma<<<dim3(BL / 128, (PROJDIM + 255) / 256), 512, TSMEM>>>(
        A2, Win2, proj, BL, PROJDIM, DMODEL, PROJDIM);

    // 2) conv + silu
    {
        int total = BL * CONVDIM;
        conv_silu_kernel<<<(total + 255) / 256, 256>>>(proj, conv_w, conv_b, xBC);
    }

    // 3) softplus(dt) + cumsum
    dt_acum_kernel<<<dim3(NCHUNK, NHEADS, BATCH), CSIZE>>>(proj, dt_bias, A_log, dtv, Acum);

    // 4) CB = C . B^T (fp32, shared across heads)
    sgemm_nt<<<dim3(2, 2, BATCH * NCHUNK), 256>>>(
        xBC + (INTERD + NSTATE), xBC + INTERD, CB,
        CSIZE, CSIZE, NSTATE, CONVDIM, CONVDIM, CSIZE,
        (long long)CSIZE * CONVDIM, (long long)CSIZE * CONVDIM, (long long)CSIZE * CSIZE);

    // 5) states via mma
    states_mma<<<dim3(NCHUNK, NHEADS, BATCH), 128, SSM_SMEM>>>(xBC, dtv, Acum, states);

    // 6) scan -> fp16 prev
    scan_kernel<<<dim3(NHEADS, BATCH), 256>>>(states, Acum, prevh);

    // 7) Y via mma (Ydiag + Yoff + D*x)
    y_mma<<<dim3(NCHUNK, NHEADS, BATCH), 256>>>(xBC, dtv, Acum, CB, prevh, Dp, Y);

    // 8) gate + RMSNorm -> fp16
    gate_rms_kernel<<<BL, 256>>>(proj, norm_w, Y, Y2);

    // 9) out = Y @ W_out^T
    gemm_fp16_mma<<<dim3(BL / 128, DMODEL / 256), 512, TSMEM>>>(
        Y2, Wout2, out, BL, DMODEL, INTERD, DMODEL);
}

// round 8
// speedup vs baseline: 6.8751x; 1.0661x over previous
#include <cuda_runtime.h>
#include <cuda_fp16.h>
#include <cstdint>

// ---------------- problem constants ----------------
#define BATCH    2
#define LSEQ     2048
#define DMODEL   2048
#define INTERD   4096
#define NHEADS   64
#define HDIM     64
#define NSTATE   128
#define KCONV    4
#define CSIZE    256
#define NCHUNK   (LSEQ / CSIZE)                 // 8
#define CONVDIM  (INTERD + 2 * NSTATE)          // 4352
#define PROJDIM  (INTERD + CONVDIM + NHEADS)    // 8512
#define BL       (BATCH * LSEQ)                 // 4096
#define EPSV     1e-5f

// ---------------- device scratch (static; no allocs allowed) ----------------
__device__ __half g_projh[(size_t)BL * PROJDIM];                        // 70 MB
__device__ __half g_xBCh [(size_t)BL * CONVDIM];                        // 35 MB
__device__ float g_dtv   [(size_t)BL * NHEADS];
__device__ float g_Acum  [(size_t)BATCH * NHEADS * NCHUNK * CSIZE];
__device__ float g_CB    [(size_t)BATCH * NCHUNK * CSIZE * CSIZE];
__device__ float g_states[(size_t)BATCH * NCHUNK * NHEADS * HDIM * NSTATE];
__device__ __half g_prevh[(size_t)BATCH * NCHUNK * NHEADS * HDIM * NSTATE];
__device__ float g_Y     [(size_t)BL * INTERD];
__device__ __half g_A2   [(size_t)BL * DMODEL];
__device__ __half g_Win2 [(size_t)PROJDIM * DMODEL];
__device__ __half g_Y2   [(size_t)BL * INTERD];
__device__ __half g_Wout2[(size_t)DMODEL * INTERD];

// =====================================================================
// common mma helpers
// =====================================================================
__device__ __forceinline__ uint32_t smem_u32(const void* p) {
    return (uint32_t)__cvta_generic_to_shared(p);
}
#define SW128(o) ((o) ^ (((o) >> 3) & 0x70))
#define SW256(o) ((o) ^ (((o) >> 4) & 0x70))

__device__ __forceinline__ void cp_async16(uint32_t d, const void* g, int sz) {
    asm volatile("cp.async.cg.shared.global [%0], [%1], 16, %2;"
                 :: "r"(d), "l"(g), "r"(sz) : "memory");
}
#define CP_COMMIT() asm volatile("cp.async.commit_group;" ::: "memory")
#define CP_WAIT2()  asm volatile("cp.async.wait_group 2;" ::: "memory")

__device__ __forceinline__ void ldsm4(uint32_t& r0, uint32_t& r1, uint32_t& r2,
                                      uint32_t& r3, uint32_t a) {
    asm volatile("ldmatrix.sync.aligned.m8n8.x4.shared.b16 {%0,%1,%2,%3}, [%4];"
                 : "=r"(r0), "=r"(r1), "=r"(r2), "=r"(r3) : "r"(a));
}
__device__ __forceinline__ void ldsm4t(uint32_t& r0, uint32_t& r1, uint32_t& r2,
                                       uint32_t& r3, uint32_t a) {
    asm volatile("ldmatrix.sync.aligned.m8n8.x4.trans.shared.b16 {%0,%1,%2,%3}, [%4];"
                 : "=r"(r0), "=r"(r1), "=r"(r2), "=r"(r3) : "r"(a));
}
__device__ __forceinline__ void mma16816(float* c, const uint32_t* a, const uint32_t* b) {
    asm volatile(
        "mma.sync.aligned.m16n8k16.row.col.f32.f16.f16.f32 "
        "{%0,%1,%2,%3}, {%4,%5,%6,%7}, {%8,%9}, {%0,%1,%2,%3};"
        : "+f"(c[0]), "+f"(c[1]), "+f"(c[2]), "+f"(c[3])
        : "r"(a[0]), "r"(a[1]), "r"(a[2]), "r"(a[3]), "r"(b[0]), "r"(b[1]));
}

__device__ __forceinline__ uint4 pack8h(const float* v) {
    __half h[8];
#pragma unroll
    for (int e = 0; e < 8; ++e) h[e] = __float2half(v[e]);
    uint4 r;
    r.x = ((uint32_t)*(uint16_t*)&h[1] << 16) | *(uint16_t*)&h[0];
    r.y = ((uint32_t)*(uint16_t*)&h[3] << 16) | *(uint16_t*)&h[2];
    r.z = ((uint32_t)*(uint16_t*)&h[5] << 16) | *(uint16_t*)&h[4];
    r.w = ((uint32_t)*(uint16_t*)&h[7] << 16) | *(uint16_t*)&h[6];
    return r;
}
__device__ __forceinline__ uint4 mul8h(uint4 v, __half2 w) {
    __half2* p = (__half2*)&v;
    p[0] = __hmul2(p[0], w); p[1] = __hmul2(p[1], w);
    p[2] = __hmul2(p[2], w); p[3] = __hmul2(p[3], w);
    return v;
}

__device__ __forceinline__ void store2(float* p, float a, float b) {
    *(float2*)p = make_float2(a, b);
}
__device__ __forceinline__ void store2(__half* p, float a, float b) {
    __half2 h; h.x = __float2half(a); h.y = __float2half(b);
    *(__half2*)p = h;
}

// =====================================================================
// big fp16 GEMM: 512 threads, templated output type
// =====================================================================
#define TSTAGE_B (128 * 128 + 256 * 128)     // 49152
#define TNSTG    4
#define TSMEM    (TNSTG * TSTAGE_B)          // 196608

template <typename TOUT>
__global__ void __launch_bounds__(512, 1) gemm_fp16_mma(
    const __half* __restrict__ A, const __half* __restrict__ Bm,
    TOUT* __restrict__ C, int M, int N, int K, int ldc)
{
    extern __shared__ __align__(1024) char smem[];
    const uint32_t sbase = smem_u32(smem);
    const int tid  = threadIdx.x;
    const int wid  = tid >> 5, lane = tid & 31;
    const int bm   = blockIdx.x * 128, bn = blockIdx.y * 256;
    const int wm   = (wid & 1) * 64;
    const int wn   = (wid >> 1) * 32;
    const int KT   = K >> 6;

    float c[4][4][4];
#pragma unroll
    for (int mt = 0; mt < 4; ++mt)
#pragma unroll
        for (int nt = 0; nt < 4; ++nt)
#pragma unroll
            for (int q = 0; q < 4; ++q) c[mt][nt][q] = 0.f;

#define LOAD_STAGE(kt, s) do {                                               \
    uint32_t st_ = sbase + (s) * TSTAGE_B;                                   \
    _Pragma("unroll")                                                        \
    for (int i_ = 0; i_ < 2; ++i_) {                                         \
        int u_ = tid + i_ * 512;                                             \
        int r_ = u_ >> 3, lu_ = u_ & 7;                                      \
        uint32_t d_ = st_ + SW128((uint32_t)(r_ * 128 + lu_ * 16));          \
        const void* g_ = (const char*)A +                                    \
            (((size_t)(bm + r_) * K + (size_t)(kt) * 64 + lu_ * 8) << 1);    \
        cp_async16(d_, g_, 16);                                              \
    }                                                                        \
    _Pragma("unroll")                                                        \
    for (int i_ = 0; i_ < 4; ++i_) {                                         \
        int u_ = tid + i_ * 512;                                             \
        int r_ = u_ >> 3, lu_ = u_ & 7;                                      \
        int gn_ = bn + r_;                                                   \
        uint32_t d_ = st_ + 16384 + SW128((uint32_t)(r_ * 128 + lu_ * 16));  \
        const void* g_ = (const char*)Bm +                                   \
            (((size_t)gn_ * K + (size_t)(kt) * 64 + lu_ * 8) << 1);          \
        cp_async16(d_, g_, gn_ < N ? 16 : 0);                                \
    }                                                                        \
} while (0)

    LOAD_STAGE(0, 0); CP_COMMIT();
    LOAD_STAGE(1, 1); CP_COMMIT();
    LOAD_STAGE(2, 2); CP_COMMIT();

    const int a_row = (lane & 15);
    const int a_ku  = (lane >> 4) * 16;
    const int b_row = ((lane >> 4) & 1) * 8 + (lane & 7);
    const int b_ku  = ((lane >> 3) & 1) * 16;

    for (int kt = 0; kt < KT; ++kt) {
        const int s = kt & 3;
        CP_WAIT2();
        __syncthreads();
        if (kt + 3 < KT) LOAD_STAGE(kt + 3, (kt + 3) & 3);
        CP_COMMIT();

        const uint32_t stA = sbase + s * TSTAGE_B;
        const uint32_t stB = stA + 16384;
#pragma unroll
        for (int ks = 0; ks < 4; ++ks) {
            uint32_t a[4][4], b[4][2];
#pragma unroll
            for (int mt = 0; mt < 4; ++mt) {
                uint32_t off = (uint32_t)((wm + mt * 16 + a_row) * 128 + ks * 32 + a_ku);
                ldsm4(a[mt][0], a[mt][1], a[mt][2], a[mt][3], stA + SW128(off));
            }
#pragma unroll
            for (int pr = 0; pr < 2; ++pr) {
                uint32_t off = (uint32_t)((wn + pr * 16 + b_row) * 128 + ks * 32 + b_ku);
                uint32_t r0, r1, r2, r3;
                ldsm4(r0, r1, r2, r3, stB + SW128(off));
                b[pr * 2][0] = r0; b[pr * 2][1] = r1;
                b[pr * 2 + 1][0] = r2; b[pr * 2 + 1][1] = r3;
            }
#pragma unroll
            for (int mt = 0; mt < 4; ++mt)
#pragma unroll
                for (int nt = 0; nt < 4; ++nt)
                    mma16816(c[mt][nt], a[mt], b[nt]);
        }
    }

#pragma unroll
    for (int mt = 0; mt < 4; ++mt) {
        int r0 = bm + wm + mt * 16 + (lane >> 2);
#pragma unroll
        for (int nt = 0; nt < 4; ++nt) {
            int col = bn + wn + nt * 8 + (lane & 3) * 2;
            if (col < N) {
                store2(&C[(size_t)r0 * ldc + col], c[mt][nt][0], c[mt][nt][1]);
                store2(&C[(size_t)(r0 + 8) * ldc + col], c[mt][nt][2], c[mt][nt][3]);
            }
        }
    }
}

// ---------------- fp32 -> fp16 convert ----------------
__global__ void cvt_fp16_kernel(const float* __restrict__ src,
                                __half* __restrict__ dst, long long total4)
{
    long long t = (long long)blockIdx.x * blockDim.x + threadIdx.x;
    if (t >= total4) return;
    float4 a = *(const float4*)(src + t * 4);
    __half h[4];
    h[0] = __float2half(a.x); h[1] = __float2half(a.y);
    h[2] = __float2half(a.z); h[3] = __float2half(a.w);
    uint2 v;
    v.x = ((uint32_t)*(uint16_t*)&h[1] << 16) | *(uint16_t*)&h[0];
    v.y = ((uint32_t)*(uint16_t*)&h[3] << 16) | *(uint16_t*)&h[2];
    *(uint2*)(dst + t * 4) = v;
}

// ---------------- depthwise causal conv (K=4) + bias + silu (fp16 io) ----------------
__global__ void conv_silu_kernel(const __half* __restrict__ projh,
                                 const float* __restrict__ cw,
                                 const float* __restrict__ cb,
                                 __half* __restrict__ xBCh)
{
    int idx = blockIdx.x * blockDim.x + threadIdx.x;
    if (idx >= BL * CONVDIM) return;
    int ch = idx % CONVDIM;
    int bl = idx / CONVDIM;
    int l  = bl % LSEQ;
    float4 w = *(const float4*)&cw[ch * 4];
    float acc = cb[ch];
    const __half* base = projh + (size_t)bl * PROJDIM + INTERD + ch;
    if (l >= 3) {
        acc += w.x * __half2float(base[-3 * PROJDIM])
             + w.y * __half2float(base[-2 * PROJDIM])
             + w.z * __half2float(base[-1 * PROJDIM])
             + w.w * __half2float(base[0]);
    } else {
        float wk[4] = {w.x, w.y, w.z, w.w};
        for (int k = 3 - l; k < 4; ++k)
            acc += wk[k] * __half2float(base[(k - 3) * PROJDIM]);
    }
    xBCh[idx] = __float2half(acc / (1.f + __expf(-acc)));
}

// ---------------- softplus(dt+bias), per-chunk inclusive cumsum ----------------
__global__ void dt_acum_kernel(const __half* __restrict__ projh,
                               const float* __restrict__ dt_bias,
                               const float* __restrict__ A_log,
                               float* __restrict__ dtv,
                               float* __restrict__ Acum)
{
    int cc = blockIdx.x, h = blockIdx.y, b = blockIdx.z;
    int i  = threadIdx.x;
    int l  = cc * CSIZE + i;
    float d  = __half2float(projh[(size_t)(b * LSEQ + l) * PROJDIM + INTERD + CONVDIM + h])
             + dt_bias[h];
    float sp = (d > 20.f) ? d : log1pf(expf(d));
    dtv[(size_t)(b * LSEQ + l) * NHEADS + h] = sp;
    float dA = sp * (-expf(A_log[h]));
    __shared__ float sbuf[CSIZE];
    sbuf[i] = dA;
    __syncthreads();
    for (int off = 1; off < CSIZE; off <<= 1) {
        float v = sbuf[i];
        if (i >= off) v += sbuf[i - off];
        __syncthreads();
        sbuf[i] = v;
        __syncthreads();
    }
    Acum[(((size_t)b * NHEADS + h) * NCHUNK + cc) * CSIZE + i] = sbuf[i];
}

// =====================================================================
// CB via fp16 mma: CB[i,j] = C_i . B_j  (128x128 tile, K=128)
// grid (2,2,BATCH*NCHUNK), 256 threads / 8 warps
// =====================================================================
#define CB_SMEM (2 * 128 * 256)   // 65536 B
__global__ void __launch_bounds__(256) cb_mma(
    const __half* __restrict__ xBCh, float* __restrict__ CB)
{
    extern __shared__ __align__(1024) char sm[];
    __half* Cs = (__half*)sm;                  // [128 i][128 n]  32KB (256B rows)
    __half* Bs = (__half*)(sm + 32768);        // [128 j][128 n]  32KB
    const uint32_t sC = smem_u32(Cs), sB = smem_u32(Bs);

    const int bj = blockIdx.x * 128, bi = blockIdx.y * 128;
    const int bc = blockIdx.z;
    const int b = bc / NCHUNK, cc = bc % NCHUNK;
    const int l0 = b * LSEQ + cc * CSIZE;
    const int tid = threadIdx.x, wid = tid >> 5, lane = tid & 31;
    const int wm = (wid & 1) * 64;   // i
    const int wn = (wid >> 1) * 32;  // j

    // stage C and B tiles (direct fp16 copy)
#pragma unroll
    for (int it = 0; it < 8; ++it) {
        int u = tid + it * 256;
        int r = u >> 4, cu = u & 15;
        uint4 vc = *(const uint4*)&xBCh[(size_t)(l0 + bi + r) * CONVDIM + INTERD + NSTATE + cu * 8];
        uint4 vb = *(const uint4*)&xBCh[(size_t)(l0 + bj + r) * CONVDIM + INTERD + cu * 8];
        *(uint4*)((char*)Cs + SW256((uint32_t)(r * 256 + cu * 16))) = vc;
        *(uint4*)((char*)Bs + SW256((uint32_t)(r * 256 + cu * 16))) = vb;
    }
    __syncthreads();

    float c[4][4][4];
#pragma unroll
    for (int mt = 0; mt < 4; ++mt)
#pragma unroll
        for (int nt = 0; nt < 4; ++nt)
#pragma unroll
            for (int q = 0; q < 4; ++q) c[mt][nt][q] = 0.f;

    const int a_row = (lane & 15);
    const int a_ku  = (lane >> 4) * 16;
    const int b_row = ((lane >> 4) & 1) * 8 + (lane & 7);
    const int b_ku  = ((lane >> 3) & 1) * 16;

#pragma unroll
    for (int ks = 0; ks < 8; ++ks) {
        uint32_t a[4][4], bf[4][2];
#pragma unroll
        for (int mt = 0; mt < 4; ++mt) {
            uint32_t off = (uint32_t)((wm + mt * 16 + a_row) * 256 + ks * 32 + a_ku);
            ldsm4(a[mt][0], a[mt][1], a[mt][2], a[mt][3], sC + SW256(off));
        }
#pragma unroll
        for (int pr = 0; pr < 2; ++pr) {
            uint32_t off = (uint32_t)((wn + pr * 16 + b_row) * 256 + ks * 32 + b_ku);
            uint32_t r0, r1, r2, r3;
            ldsm4(r0, r1, r2, r3, sB + SW256(off));
            bf[pr * 2][0] = r0; bf[pr * 2][1] = r1;
            bf[pr * 2 + 1][0] = r2; bf[pr * 2 + 1][1] = r3;
        }
#pragma unroll
        for (int mt = 0; mt < 4; ++mt)
#pragma unroll
            for (int nt = 0; nt < 4; ++nt)
                mma16816(c[mt][nt], a[mt], bf[nt]);
    }

    float* cbo = CB + (size_t)bc * CSIZE * CSIZE;
#pragma unroll
    for (int mt = 0; mt < 4; ++mt) {
        int gi = bi + wm + mt * 16 + (lane >> 2);
#pragma unroll
        for (int nt = 0; nt < 4; ++nt) {
            int gj = bj + wn + nt * 8 + (lane & 3) * 2;
            *(float2*)&cbo[(size_t)gi * CSIZE + gj] = make_float2(c[mt][nt][0], c[mt][nt][1]);
            *(float2*)&cbo[(size_t)(gi + 8) * CSIZE + gj] = make_float2(c[mt][nt][2], c[mt][nt][3]);
        }
    }
}

// =====================================================================
// states via mma: states[p,n] = sum_j (w_j x[j,p]) * B[j,n]
// =====================================================================
#define SSM_SMEM (16384 + 32768 + 512)
__global__ void __launch_bounds__(128) states_mma(
    const __half* __restrict__ xBCh, const float* __restrict__ dtv,
    const float* __restrict__ Acum, float* __restrict__ states)
{
    extern __shared__ __align__(1024) char sm[];
    __half* Xw = (__half*)sm;
    __half* Bs = (__half*)(sm + 16384);
    float*  wv = (float*)(sm + 49152);
    const uint32_t sX = smem_u32(Xw), sB = smem_u32(Bs);

    const int cc = blockIdx.x, h = blockIdx.y, b = blockIdx.z;
    const int tid = threadIdx.x, wid = tid >> 5, lane = tid & 31;
    const float* Ab = Acum + (((size_t)b * NHEADS + h) * NCHUNK + cc) * CSIZE;
    const float AcLast = Ab[CSIZE - 1];
    const int l0 = b * LSEQ + cc * CSIZE;

    float c[4][4][4];
#pragma unroll
    for (int mt = 0; mt < 4; ++mt)
#pragma unroll
        for (int nt = 0; nt < 4; ++nt)
#pragma unroll
            for (int q = 0; q < 4; ++q) c[mt][nt][q] = 0.f;

    for (int jt = 0; jt < CSIZE; jt += 128) {
        wv[tid] = __expf(AcLast - Ab[jt + tid]) * dtv[(size_t)(l0 + jt + tid) * NHEADS + h];
        __syncthreads();
#pragma unroll
        for (int it = 0; it < 8; ++it) {
            int u = tid + it * 128;
            int j = u >> 3, cu = u & 7;
            uint4 v = *(const uint4*)&xBCh[(size_t)(l0 + jt + j) * CONVDIM + h * HDIM + cu * 8];
            __half2 w2 = __float2half2_rn(wv[j]);
            *(uint4*)((char*)Xw + SW128((uint32_t)(j * 128 + cu * 16))) = mul8h(v, w2);
        }
#pragma unroll
        for (int it = 0; it < 16; ++it) {
            int u = tid + it * 128;
            int j = u >> 4, cu = u & 15;
            uint4 v = *(const uint4*)&xBCh[(size_t)(l0 + jt + j) * CONVDIM + INTERD + cu * 8];
            *(uint4*)((char*)Bs + SW256((uint32_t)(j * 256 + cu * 16))) = v;
        }
        __syncthreads();
#pragma unroll
        for (int ks = 0; ks < 8; ++ks) {
            uint32_t a[4][4], bf[4][2];
#pragma unroll
            for (int mt = 0; mt < 4; ++mt) {
                int row = ks * 16 + ((lane >> 4) & 1) * 8 + (lane & 7);
                int col = mt * 16 + ((lane >> 3) & 1) * 8;
                ldsm4t(a[mt][0], a[mt][1], a[mt][2], a[mt][3],
                       sX + SW128((uint32_t)(row * 128 + col * 2)));
            }
#pragma unroll
            for (int nt2 = 0; nt2 < 2; ++nt2) {
                int row = ks * 16 + ((lane >> 3) & 1) * 8 + (lane & 7);
                int col = wid * 32 + nt2 * 16 + (lane >> 4) * 8;
                uint32_t r0, r1, r2, r3;
                ldsm4t(r0, r1, r2, r3, sB + SW256((uint32_t)(row * 256 + col * 2)));
                bf[nt2 * 2][0] = r0; bf[nt2 * 2][1] = r1;
                bf[nt2 * 2 + 1][0] = r2; bf[nt2 * 2 + 1][1] = r3;
            }
#pragma unroll
            for (int mt = 0; mt < 4; ++mt)
#pragma unroll
                for (int nt = 0; nt < 4; ++nt)
                    mma16816(c[mt][nt], a[mt], bf[nt]);
        }
        __syncthreads();
    }
    float* so = states + (((size_t)b * NCHUNK + cc) * NHEADS + h) * (HDIM * NSTATE);
#pragma unroll
    for (int mt = 0; mt < 4; ++mt) {
        int p0 = mt * 16 + (lane >> 2);
#pragma unroll
        for (int nt = 0; nt < 4; ++nt) {
            int n = wid * 32 + nt * 8 + (lane & 3) * 2;
            *(float2*)&so[p0 * NSTATE + n] = make_float2(c[mt][nt][0], c[mt][nt][1]);
            *(float2*)&so[(p0 + 8) * NSTATE + n] = make_float2(c[mt][nt][2], c[mt][nt][3]);
        }
    }
}

// ---------------- inter-chunk recurrence -> fp16 prev ----------------
__global__ void scan_kernel(const float* __restrict__ states,
                            const float* __restrict__ Acum,
                            __half* __restrict__ prevh)
{
    int h = blockIdx.x, b = blockIdx.y, tid = threadIdx.x;
    float carry[32];
#pragma unroll
    for (int t = 0; t < 32; ++t) carry[t] = 0.f;
    for (int cc = 0; cc < NCHUNK; ++cc) {
        float cd = expf(Acum[(((size_t)b * NHEADS + h) * NCHUNK + cc) * CSIZE + CSIZE - 1]);
        size_t base = (((size_t)b * NCHUNK + cc) * NHEADS + h) * (HDIM * NSTATE);
#pragma unroll
        for (int t = 0; t < 32; ++t) {
            size_t idx = base + tid + t * 256;
            prevh[idx] = __float2half(carry[t]);
            carry[t]   = cd * carry[t] + states[idx];
        }
    }
}

// =====================================================================
// Y via mma: Y[i,p] = M @ X + Ce @ prev^T + D*x
// =====================================================================
__global__ void __launch_bounds__(256) y_mma(
    const __half* __restrict__ xBCh, const float* __restrict__ dtv,
    const float* __restrict__ Acum, const float* __restrict__ CB,
    const __half* __restrict__ prevh, const float* __restrict__ Dp,
    float* __restrict__ Y)
{
    __shared__ float Ac[CSIZE], dts[CSIZE], rowf[CSIZE], eA[CSIZE], colf[64];
    __shared__ __align__(1024) __half Ms[CSIZE * 64];
    __shared__ __align__(1024) __half Xs[64 * 64];
    const uint32_t sM = smem_u32(Ms), sXs = smem_u32(Xs);

    const int cc = blockIdx.x, h = blockIdx.y, b = blockIdx.z;
    const int tid = threadIdx.x, wid = tid >> 5, lane = tid & 31;
    const int wm = (wid & 3) * 64;
    const int wn = (wid >> 2) * 32;
    const int l0 = b * LSEQ + cc * CSIZE;

    Ac[tid]  = Acum[(((size_t)b * NHEADS + h) * NCHUNK + cc) * CSIZE + tid];
    dts[tid] = dtv[(size_t)(l0 + tid) * NHEADS + h];
    __syncthreads();
    eA[tid] = __expf(Ac[tid]);

    const float* CBb = CB + ((size_t)b * NCHUNK + cc) * CSIZE * CSIZE;

    float c[4][4][4];
#pragma unroll
    for (int mt = 0; mt < 4; ++mt)
#pragma unroll
        for (int nt = 0; nt < 4; ++nt)
#pragma unroll
            for (int q = 0; q < 4; ++q) c[mt][nt][q] = 0.f;

    for (int jt = 0; jt < CSIZE; jt += 64) {
        float A_ref = Ac[jt + 63];
        if (tid < 64) colf[tid] = __expf(A_ref - Ac[jt + tid]) * dts[jt + tid];
        rowf[tid] = __expf(Ac[tid] - A_ref);
        __syncthreads();
#pragma unroll
        for (int it = 0; it < 8; ++it) {
            int u = tid + it * 256;
            int i = u >> 3, cu = u & 7;
            float v[8];
            if (i < jt) {
#pragma unroll
                for (int e = 0; e < 8; ++e) v[e] = 0.f;
            } else if (i >= jt + 64) {
                const float* cbp = &CBb[(size_t)i * CSIZE + jt + cu * 8];
                float rf = rowf[i];
#pragma unroll
                for (int e = 0; e < 8; ++e) v[e] = cbp[e] * rf * colf[cu * 8 + e];
            } else {
                const float* cbp = &CBb[(size_t)i * CSIZE + jt + cu * 8];
#pragma unroll
                for (int e = 0; e < 8; ++e) {
                    int j = jt + cu * 8 + e;
                    v[e] = (j <= i) ? cbp[e] * __expf(Ac[i] - Ac[j]) * dts[j] : 0.f;
                }
            }
            *(uint4*)((char*)Ms + SW128((uint32_t)(i * 128 + cu * 16))) = pack8h(v);
        }
#pragma unroll
        for (int it = 0; it < 2; ++it) {
            int u = tid + it * 256;
            int j = u >> 3, cu = u & 7;
            uint4 v = *(const uint4*)&xBCh[(size_t)(l0 + jt + j) * CONVDIM + h * HDIM + cu * 8];
            *(uint4*)((char*)Xs + SW128((uint32_t)(j * 128 + cu * 16))) = v;
        }
        __syncthreads();
#pragma unroll
        for (int ks = 0; ks < 4; ++ks) {
            uint32_t a[4][4], bf[4][2];
#pragma unroll
            for (int mt = 0; mt < 4; ++mt) {
                int row = wm + mt * 16 + (lane & 15);
                int kb  = ks * 32 + (lane >> 4) * 16;
                ldsm4(a[mt][0], a[mt][1], a[mt][2], a[mt][3],
                      sM + SW128((uint32_t)(row * 128 + kb)));
            }
#pragma unroll
            for (int nt2 = 0; nt2 < 2; ++nt2) {
                int row = ks * 16 + ((lane >> 3) & 1) * 8 + (lane & 7);
                int col = wn + nt2 * 16 + (lane >> 4) * 8;
                uint32_t r0, r1, r2, r3;
                ldsm4t(r0, r1, r2, r3, sXs + SW128((uint32_t)(row * 128 + col * 2)));
                bf[nt2 * 2][0] = r0; bf[nt2 * 2][1] = r1;
                bf[nt2 * 2 + 1][0] = r2; bf[nt2 * 2 + 1][1] = r3;
            }
#pragma unroll
            for (int mt = 0; mt < 4; ++mt)
#pragma unroll
                for (int nt = 0; nt < 4; ++nt)
                    mma16816(c[mt][nt], a[mt], bf[nt]);
        }
        __syncthreads();
    }

    const __half* pvb = prevh + (((size_t)b * NCHUNK + cc) * NHEADS + h) * (HDIM * NSTATE);
    for (int nt0 = 0; nt0 < NSTATE; nt0 += 64) {
#pragma unroll
        for (int it = 0; it < 8; ++it) {
            int u = tid + it * 256;
            int i = u >> 3, cu = u & 7;
            uint4 v = *(const uint4*)&xBCh[(size_t)(l0 + i) * CONVDIM + INTERD + NSTATE + nt0 + cu * 8];
            __half2 ea2 = __float2half2_rn(eA[i]);
            *(uint4*)((char*)Ms + SW128((uint32_t)(i * 128 + cu * 16))) = mul8h(v, ea2);
        }
#pragma unroll
        for (int it = 0; it < 2; ++it) {
            int u = tid + it * 256;
            int p = u >> 3, cu = u & 7;
            uint4 v = *(const uint4*)(pvb + (size_t)p * NSTATE + nt0 + cu * 8);
            *(uint4*)((char*)Xs + SW128((uint32_t)(p * 128 + cu * 16))) = v;
        }
        __syncthreads();
#pragma unroll
        for (int ks = 0; ks < 4; ++ks) {
            uint32_t a[4][4], bf[4][2];
#pragma unroll
            for (int mt = 0; mt < 4; ++mt) {
                int row = wm + mt * 16 + (lane & 15);
                int kb  = ks * 32 + (lane >> 4) * 16;
                ldsm4(a[mt][0], a[mt][1], a[mt][2], a[mt][3],
                      sM + SW128((uint32_t)(row * 128 + kb)));
            }
#pragma unroll
            for (int nt2 = 0; nt2 < 2; ++nt2) {
                int prow = wn + nt2 * 16 + ((lane >> 4) & 1) * 8 + (lane & 7);
                int kb   = ks * 32 + ((lane >> 3) & 1) * 16;
                uint32_t r0, r1, r2, r3;
                ldsm4(r0, r1, r2, r3, sXs + SW128((uint32_t)(prow * 128 + kb)));
                bf[nt2 * 2][0] = r0; bf[nt2 * 2][1] = r1;
                bf[nt2 * 2 + 1][0] = r2; bf[nt2 * 2 + 1][1] = r3;
            }
#pragma unroll
            for (int mt = 0; mt < 4; ++mt)
#pragma unroll
                for (int nt = 0; nt < 4; ++nt)
                    mma16816(c[mt][nt], a[mt], bf[nt]);
        }
        __syncthreads();
    }

    float Dh = Dp[h];
#pragma unroll
    for (int mt = 0; mt < 4; ++mt) {
        int i0 = wm + mt * 16 + (lane >> 2);
#pragma unroll
        for (int nt = 0; nt < 4; ++nt) {
            int p = wn + nt * 8 + (lane & 3) * 2;
#pragma unroll
            for (int half = 0; half < 2; ++half) {
                int i = i0 + half * 8;
                __half2 xh = *(const __half2*)&xBCh[(size_t)(l0 + i) * CONVDIM + h * HDIM + p];
                float2 xv = __half22float2(xh);
                float2 ov;
                ov.x = c[mt][nt][half * 2 + 0] + Dh * xv.x;
                ov.y = c[mt][nt][half * 2 + 1] + Dh * xv.y;
                *(float2*)&Y[(size_t)(l0 + i) * INTERD + h * HDIM + p] = ov;
            }
        }
    }
}

// ---------------- gate (silu, fp16 in) + RMSNorm -> fp16 Y2 ----------------
__global__ void gate_rms_kernel(const __half* __restrict__ projh,
                                const float* __restrict__ norm_w,
                                const float* __restrict__ Y,
                                __half* __restrict__ Y2)
{
    int row = blockIdx.x, tid = threadIdx.x;
    const __half* gr = projh + (size_t)row * PROJDIM;
    const float* yr = Y + (size_t)row * INTERD;
    float yv[16];
    float ss = 0.f;
#pragma unroll
    for (int t = 0; t < 16; ++t) {
        int e = tid + t * 256;
        float g = __half2float(gr[e]);
        float v = yr[e] * (g / (1.f + __expf(-g)));
        yv[t] = v;
        ss += v * v;
    }
    __shared__ float red[8];
#pragma unroll
    for (int o = 16; o > 0; o >>= 1) ss += __shfl_xor_sync(0xffffffff, ss, o);
    if ((tid & 31) == 0) red[tid >> 5] = ss;
    __syncthreads();
    float tot = 0.f;
#pragma unroll
    for (int w = 0; w < 8; ++w) tot += red[w];
    float scale = rsqrtf(tot / (float)INTERD + EPSV);
    __half* y2r = Y2 + (size_t)row * INTERD;
#pragma unroll
    for (int t = 0; t < 16; ++t) {
        int e = tid + t * 256;
        y2r[e] = __float2half(yv[t] * scale * norm_w[e]);
    }
}

// ---------------- launch ----------------
extern "C" void kernel_launch(void* const* d_in, const int* in_sizes, int n_in,
                              void* d_out, int out_size)
{
    const float* hs      = (const float*)d_in[0];
    const float* W_in    = (const float*)d_in[1];
    const float* conv_w  = (const float*)d_in[2];
    const float* conv_b  = (const float*)d_in[3];
    const float* dt_bias = (const float*)d_in[4];
    const float* A_log   = (const float*)d_in[5];
    const float* Dp      = (const float*)d_in[6];
    const float* norm_w  = (const float*)d_in[7];
    const float* W_out   = (const float*)d_in[8];
    float* out = (float*)d_out;

    float *dtv, *Acum, *CB, *states, *Y;
    __half *projh, *xBCh, *prevh, *A2, *Win2, *Y2, *Wout2;
    cudaGetSymbolAddress((void**)&projh,  g_projh);
    cudaGetSymbolAddress((void**)&xBCh,   g_xBCh);
    cudaGetSymbolAddress((void**)&dtv,    g_dtv);
    cudaGetSymbolAddress((void**)&Acum,   g_Acum);
    cudaGetSymbolAddress((void**)&CB,     g_CB);
    cudaGetSymbolAddress((void**)&states, g_states);
    cudaGetSymbolAddress((void**)&prevh,  g_prevh);
    cudaGetSymbolAddress((void**)&Y,      g_Y);
    cudaGetSymbolAddress((void**)&A2,     g_A2);
    cudaGetSymbolAddress((void**)&Win2,   g_Win2);
    cudaGetSymbolAddress((void**)&Y2,     g_Y2);
    cudaGetSymbolAddress((void**)&Wout2,  g_Wout2);

    cudaFuncSetAttribute(gemm_fp16_mma<__half>,
                         cudaFuncAttributeMaxDynamicSharedMemorySize, TSMEM);
    cudaFuncSetAttribute(gemm_fp16_mma<float>,
                         cudaFuncAttributeMaxDynamicSharedMemorySize, TSMEM);
    cudaFuncSetAttribute(states_mma,
                         cudaFuncAttributeMaxDynamicSharedMemorySize, SSM_SMEM);
    cudaFuncSetAttribute(cb_mma,
                         cudaFuncAttributeMaxDynamicSharedMemorySize, CB_SMEM);

    // 0) convert fp32 -> fp16
    {
        long long t4;
        t4 = (long long)BL * DMODEL / 4;
        cvt_fp16_kernel<<<(unsigned)((t4 + 255) / 256), 256>>>(hs, A2, t4);
        t4 = (long long)PROJDIM * DMODEL / 4;
        cvt_fp16_kernel<<<(unsigned)((t4 + 255) / 256), 256>>>(W_in, Win2, t4);
        t4 = (long long)DMODEL * INTERD / 4;
        cvt_fp16_kernel<<<(unsigned)((t4 + 255) / 256), 256>>>(W_out, Wout2, t4);
    }

    // 1) proj = hs @ W_in^T  (fp16 output)
    gemm_fp16_mma<__half><<<dim3(BL / 128, (PROJDIM + 255) / 256), 512, TSMEM>>>(
        A2, Win2, projh, BL, PROJDIM, DMODEL, PROJDIM);

    // 2) conv + silu -> fp16 xBC
    {
        int total = BL * CONVDIM;
        conv_silu_kernel<<<(total + 255) / 256, 256>>>(projh, conv_w, conv_b, xBCh);
    }

    // 3) softplus(dt) + cumsum
    dt_acum_kernel<<<dim3(NCHUNK, NHEADS, BATCH), CSIZE>>>(projh, dt_bias, A_log, dtv, Acum);

    // 4) CB = C . B^T via fp16 mma
    cb_mma<<<dim3(2, 2, BATCH * NCHUNK), 256, CB_SMEM>>>(xBCh, CB);

    // 5) states via mma
    states_mma<<<dim3(NCHUNK, NHEADS, BATCH), 128, SSM_SMEM>>>(xBCh, dtv, Acum, states);

    // 6) scan -> fp16 prev
    scan_kernel<<<dim3(NHEADS, BATCH), 256>>>(states, Acum, prevh);

    // 7) Y via mma (Ydiag + Yoff + D*x)
    y_mma<<<dim3(NCHUNK, NHEADS, BATCH), 256>>>(xBCh, dtv, Acum, CB, prevh, Dp, Y);

    // 8) gate + RMSNorm -> fp16
    gate_rms_kernel<<<BL, 256>>>(projh, norm_w, Y, Y2);

    // 9) out = Y @ W_out^T (fp32 output)
    gemm_fp16_mma<float><<<dim3(BL / 128, DMODEL / 256), 512, TSMEM>>>(
        Y2, Wout2, out, BL, DMODEL, INTERD, DMODEL);
}

// round 9
// speedup vs baseline: 6.9248x; 1.0072x over previous
#include <cuda_runtime.h>
#include <cuda_fp16.h>
#include <cstdint>

// ---------------- problem constants ----------------
#define BATCH    2
#define LSEQ     2048
#define DMODEL   2048
#define INTERD   4096
#define NHEADS   64
#define HDIM     64
#define NSTATE   128
#define KCONV    4
#define CSIZE    256
#define NCHUNK   (LSEQ / CSIZE)                 // 8
#define CONVDIM  (INTERD + 2 * NSTATE)          // 4352
#define PROJDIM  (INTERD + CONVDIM + NHEADS)    // 8512
#define BL       (BATCH * LSEQ)                 // 4096
#define EPSV     1e-5f

// ---------------- device scratch (static; no allocs allowed) ----------------
__device__ __half g_projh [(size_t)BL * PROJDIM];
__device__ __half g_xBCh  [(size_t)BL * CONVDIM];
__device__ float g_dtv    [(size_t)BL * NHEADS];
__device__ float g_Acum   [(size_t)BATCH * NHEADS * NCHUNK * CSIZE];
__device__ __half g_CBh   [(size_t)BATCH * NCHUNK * CSIZE * CSIZE];
__device__ __half g_statesh[(size_t)BATCH * NCHUNK * NHEADS * HDIM * NSTATE];
__device__ __half g_prevh [(size_t)BATCH * NCHUNK * NHEADS * HDIM * NSTATE];
__device__ float g_Y      [(size_t)BL * INTERD];
__device__ __half g_A2    [(size_t)BL * DMODEL];
__device__ __half g_Win2  [(size_t)PROJDIM * DMODEL];
__device__ __half g_Y2    [(size_t)BL * INTERD];
__device__ __half g_Wout2 [(size_t)DMODEL * INTERD];

// =====================================================================
// common mma helpers
// =====================================================================
__device__ __forceinline__ uint32_t smem_u32(const void* p) {
    return (uint32_t)__cvta_generic_to_shared(p);
}
#define SW128(o) ((o) ^ (((o) >> 3) & 0x70))
#define SW256(o) ((o) ^ (((o) >> 4) & 0x70))

__device__ __forceinline__ void cp_async16(uint32_t d, const void* g, int sz) {
    asm volatile("cp.async.cg.shared.global [%0], [%1], 16, %2;"
                 :: "r"(d), "l"(g), "r"(sz) : "memory");
}
#define CP_COMMIT() asm volatile("cp.async.commit_group;" ::: "memory")
#define CP_WAIT2()  asm volatile("cp.async.wait_group 2;" ::: "memory")

__device__ __forceinline__ void ldsm4(uint32_t& r0, uint32_t& r1, uint32_t& r2,
                                      uint32_t& r3, uint32_t a) {
    asm volatile("ldmatrix.sync.aligned.m8n8.x4.shared.b16 {%0,%1,%2,%3}, [%4];"
                 : "=r"(r0), "=r"(r1), "=r"(r2), "=r"(r3) : "r"(a));
}
__device__ __forceinline__ void ldsm4t(uint32_t& r0, uint32_t& r1, uint32_t& r2,
                                       uint32_t& r3, uint32_t a) {
    asm volatile("ldmatrix.sync.aligned.m8n8.x4.trans.shared.b16 {%0,%1,%2,%3}, [%4];"
                 : "=r"(r0), "=r"(r1), "=r"(r2), "=r"(r3) : "r"(a));
}
__device__ __forceinline__ void mma16816(float* c, const uint32_t* a, const uint32_t* b) {
    asm volatile(
        "mma.sync.aligned.m16n8k16.row.col.f32.f16.f16.f32 "
        "{%0,%1,%2,%3}, {%4,%5,%6,%7}, {%8,%9}, {%0,%1,%2,%3};"
        : "+f"(c[0]), "+f"(c[1]), "+f"(c[2]), "+f"(c[3])
        : "r"(a[0]), "r"(a[1]), "r"(a[2]), "r"(a[3]), "r"(b[0]), "r"(b[1]));
}

__device__ __forceinline__ uint4 pack8h(const float* v) {
    __half h[8];
#pragma unroll
    for (int e = 0; e < 8; ++e) h[e] = __float2half(v[e]);
    uint4 r;
    r.x = ((uint32_t)*(uint16_t*)&h[1] << 16) | *(uint16_t*)&h[0];
    r.y = ((uint32_t)*(uint16_t*)&h[3] << 16) | *(uint16_t*)&h[2];
    r.z = ((uint32_t)*(uint16_t*)&h[5] << 16) | *(uint16_t*)&h[4];
    r.w = ((uint32_t)*(uint16_t*)&h[7] << 16) | *(uint16_t*)&h[6];
    return r;
}
__device__ __forceinline__ uint4 mul8h(uint4 v, __half2 w) {
    __half2* p = (__half2*)&v;
    p[0] = __hmul2(p[0], w); p[1] = __hmul2(p[1], w);
    p[2] = __hmul2(p[2], w); p[3] = __hmul2(p[3], w);
    return v;
}

__device__ __forceinline__ void store2(float* p, float a, float b) {
    *(float2*)p = make_float2(a, b);
}
__device__ __forceinline__ void store2(__half* p, float a, float b) {
    __half2 h; h.x = __float2half(a); h.y = __float2half(b);
    *(__half2*)p = h;
}

// =====================================================================
// big fp16 GEMM: 512 threads, templated output type (FROZEN from R7/R8)
// =====================================================================
#define TSTAGE_B (128 * 128 + 256 * 128)     // 49152
#define TNSTG    4
#define TSMEM    (TNSTG * TSTAGE_B)          // 196608

template <typename TOUT>
__global__ void __launch_bounds__(512, 1) gemm_fp16_mma(
    const __half* __restrict__ A, const __half* __restrict__ Bm,
    TOUT* __restrict__ C, int M, int N, int K, int ldc)
{
    extern __shared__ __align__(1024) char smem[];
    const uint32_t sbase = smem_u32(smem);
    const int tid  = threadIdx.x;
    const int wid  = tid >> 5, lane = tid & 31;
    const int bm   = blockIdx.x * 128, bn = blockIdx.y * 256;
    const int wm   = (wid & 1) * 64;
    const int wn   = (wid >> 1) * 32;
    const int KT   = K >> 6;

    float c[4][4][4];
#pragma unroll
    for (int mt = 0; mt < 4; ++mt)
#pragma unroll
        for (int nt = 0; nt < 4; ++nt)
#pragma unroll
            for (int q = 0; q < 4; ++q) c[mt][nt][q] = 0.f;

#define LOAD_STAGE(kt, s) do {                                               \
    uint32_t st_ = sbase + (s) * TSTAGE_B;                                   \
    _Pragma("unroll")                                                        \
    for (int i_ = 0; i_ < 2; ++i_) {                                         \
        int u_ = tid + i_ * 512;                                             \
        int r_ = u_ >> 3, lu_ = u_ & 7;                                      \
        uint32_t d_ = st_ + SW128((uint32_t)(r_ * 128 + lu_ * 16));          \
        const void* g_ = (const char*)A +                                    \
            (((size_t)(bm + r_) * K + (size_t)(kt) * 64 + lu_ * 8) << 1);    \
        cp_async16(d_, g_, 16);                                              \
    }                                                                        \
    _Pragma("unroll")                                                        \
    for (int i_ = 0; i_ < 4; ++i_) {                                         \
        int u_ = tid + i_ * 512;                                             \
        int r_ = u_ >> 3, lu_ = u_ & 7;                                      \
        int gn_ = bn + r_;                                                   \
        uint32_t d_ = st_ + 16384 + SW128((uint32_t)(r_ * 128 + lu_ * 16));  \
        const void* g_ = (const char*)Bm +                                   \
            (((size_t)gn_ * K + (size_t)(kt) * 64 + lu_ * 8) << 1);          \
        cp_async16(d_, g_, gn_ < N ? 16 : 0);                                \
    }                                                                        \
} while (0)

    LOAD_STAGE(0, 0); CP_COMMIT();
    LOAD_STAGE(1, 1); CP_COMMIT();
    LOAD_STAGE(2, 2); CP_COMMIT();

    const int a_row = (lane & 15);
    const int a_ku  = (lane >> 4) * 16;
    const int b_row = ((lane >> 4) & 1) * 8 + (lane & 7);
    const int b_ku  = ((lane >> 3) & 1) * 16;

    for (int kt = 0; kt < KT; ++kt) {
        const int s = kt & 3;
        CP_WAIT2();
        __syncthreads();
        if (kt + 3 < KT) LOAD_STAGE(kt + 3, (kt + 3) & 3);
        CP_COMMIT();

        const uint32_t stA = sbase + s * TSTAGE_B;
        const uint32_t stB = stA + 16384;
#pragma unroll
        for (int ks = 0; ks < 4; ++ks) {
            uint32_t a[4][4], b[4][2];
#pragma unroll
            for (int mt = 0; mt < 4; ++mt) {
                uint32_t off = (uint32_t)((wm + mt * 16 + a_row) * 128 + ks * 32 + a_ku);
                ldsm4(a[mt][0], a[mt][1], a[mt][2], a[mt][3], stA + SW128(off));
            }
#pragma unroll
            for (int pr = 0; pr < 2; ++pr) {
                uint32_t off = (uint32_t)((wn + pr * 16 + b_row) * 128 + ks * 32 + b_ku);
                uint32_t r0, r1, r2, r3;
                ldsm4(r0, r1, r2, r3, stB + SW128(off));
                b[pr * 2][0] = r0; b[pr * 2][1] = r1;
                b[pr * 2 + 1][0] = r2; b[pr * 2 + 1][1] = r3;
            }
#pragma unroll
            for (int mt = 0; mt < 4; ++mt)
#pragma unroll
                for (int nt = 0; nt < 4; ++nt)
                    mma16816(c[mt][nt], a[mt], b[nt]);
        }
    }

#pragma unroll
    for (int mt = 0; mt < 4; ++mt) {
        int r0 = bm + wm + mt * 16 + (lane >> 2);
#pragma unroll
        for (int nt = 0; nt < 4; ++nt) {
            int col = bn + wn + nt * 8 + (lane & 3) * 2;
            if (col < N) {
                store2(&C[(size_t)r0 * ldc + col], c[mt][nt][0], c[mt][nt][1]);
                store2(&C[(size_t)(r0 + 8) * ldc + col], c[mt][nt][2], c[mt][nt][3]);
            }
        }
    }
}

// ---------------- fused fp32 -> fp16 convert of hs, W_in, W_out ----------------
#define CVT_T1 ((long long)BL * DMODEL / 4)
#define CVT_T2 ((long long)PROJDIM * DMODEL / 4)
#define CVT_T3 ((long long)DMODEL * INTERD / 4)
__global__ void cvt_all_kernel(const float* __restrict__ hs,
                               const float* __restrict__ W_in,
                               const float* __restrict__ W_out,
                               __half* __restrict__ A2,
                               __half* __restrict__ Win2,
                               __half* __restrict__ Wout2)
{
    long long t = (long long)blockIdx.x * blockDim.x + threadIdx.x;
    const float* src; __half* dst; long long o;
    if (t < CVT_T1) { src = hs; dst = A2; o = t; }
    else if (t < CVT_T1 + CVT_T2) { src = W_in; dst = Win2; o = t - CVT_T1; }
    else if (t < CVT_T1 + CVT_T2 + CVT_T3) { src = W_out; dst = Wout2; o = t - CVT_T1 - CVT_T2; }
    else return;
    float4 a = *(const float4*)(src + o * 4);
    float v[4] = {a.x, a.y, a.z, a.w};
    __half h[4];
#pragma unroll
    for (int e = 0; e < 4; ++e) h[e] = __float2half(v[e]);
    uint2 r;
    r.x = ((uint32_t)*(uint16_t*)&h[1] << 16) | *(uint16_t*)&h[0];
    r.y = ((uint32_t)*(uint16_t*)&h[3] << 16) | *(uint16_t*)&h[2];
    *(uint2*)(dst + o * 4) = r;
}

// ---------------- depthwise causal conv (K=4) + bias + silu, half2 ----------------
__global__ void conv_silu_kernel(const __half* __restrict__ projh,
                                 const float* __restrict__ cw,
                                 const float* __restrict__ cb,
                                 __half* __restrict__ xBCh)
{
    int idx = blockIdx.x * blockDim.x + threadIdx.x;   // one half2 (2 channels)
    if (idx >= BL * CONVDIM / 2) return;
    int ch2 = idx % (CONVDIM / 2);
    int bl  = idx / (CONVDIM / 2);
    int ch  = ch2 * 2;
    int l   = bl % LSEQ;
    float4 w0 = *(const float4*)&cw[ch * 4];
    float4 w1 = *(const float4*)&cw[(ch + 1) * 4];
    float acc0 = cb[ch], acc1 = cb[ch + 1];
    const __half2* base = (const __half2*)(projh + (size_t)bl * PROJDIM + INTERD + ch);
    const int str2 = PROJDIM / 2;
    float wa0[4] = {w0.x, w0.y, w0.z, w0.w};
    float wa1[4] = {w1.x, w1.y, w1.z, w1.w};
    int kmin = (l >= 3) ? 0 : (3 - l);
#pragma unroll
    for (int k = 0; k < 4; ++k) {
        if (k >= kmin) {
            float2 t = __half22float2(base[(k - 3) * str2]);
            acc0 += wa0[k] * t.x;
            acc1 += wa1[k] * t.y;
        }
    }
    float o0 = acc0 / (1.f + __expf(-acc0));
    float o1 = acc1 / (1.f + __expf(-acc1));
    __half2 ov; ov.x = __float2half(o0); ov.y = __float2half(o1);
    *(__half2*)(xBCh + (size_t)bl * CONVDIM + ch) = ov;
}

// ---------------- softplus(dt+bias), per-chunk inclusive cumsum ----------------
__global__ void dt_acum_kernel(const __half* __restrict__ projh,
                               const float* __restrict__ dt_bias,
                               const float* __restrict__ A_log,
                               float* __restrict__ dtv,
                               float* __restrict__ Acum)
{
    int cc = blockIdx.x, h = blockIdx.y, b = blockIdx.z;
    int i  = threadIdx.x;
    int l  = cc * CSIZE + i;
    float d  = __half2float(projh[(size_t)(b * LSEQ + l) * PROJDIM + INTERD + CONVDIM + h])
             + dt_bias[h];
    float sp = (d > 20.f) ? d : log1pf(expf(d));
    dtv[(size_t)(b * LSEQ + l) * NHEADS + h] = sp;
    float dA = sp * (-expf(A_log[h]));
    __shared__ float sbuf[CSIZE];
    sbuf[i] = dA;
    __syncthreads();
    for (int off = 1; off < CSIZE; off <<= 1) {
        float v = sbuf[i];
        if (i >= off) v += sbuf[i - off];
        __syncthreads();
        sbuf[i] = v;
        __syncthreads();
    }
    Acum[(((size_t)b * NHEADS + h) * NCHUNK + cc) * CSIZE + i] = sbuf[i];
}

// =====================================================================
// CB via fp16 mma -> fp16 output
// =====================================================================
#define CB_SMEM (2 * 128 * 256)   // 65536 B
__global__ void __launch_bounds__(256) cb_mma(
    const __half* __restrict__ xBCh, __half* __restrict__ CBh)
{
    extern __shared__ __align__(1024) char sm[];
    __half* Cs = (__half*)sm;
    __half* Bs = (__half*)(sm + 32768);
    const uint32_t sC = smem_u32(Cs), sB = smem_u32(Bs);

    const int bj = blockIdx.x * 128, bi = blockIdx.y * 128;
    const int bc = blockIdx.z;
    const int b = bc / NCHUNK, cc = bc % NCHUNK;
    const int l0 = b * LSEQ + cc * CSIZE;
    const int tid = threadIdx.x, wid = tid >> 5, lane = tid & 31;
    const int wm = (wid & 1) * 64;
    const int wn = (wid >> 1) * 32;

#pragma unroll
    for (int it = 0; it < 8; ++it) {
        int u = tid + it * 256;
        int r = u >> 4, cu = u & 15;
        uint4 vc = *(const uint4*)&xBCh[(size_t)(l0 + bi + r) * CONVDIM + INTERD + NSTATE + cu * 8];
        uint4 vb = *(const uint4*)&xBCh[(size_t)(l0 + bj + r) * CONVDIM + INTERD + cu * 8];
        *(uint4*)((char*)Cs + SW256((uint32_t)(r * 256 + cu * 16))) = vc;
        *(uint4*)((char*)Bs + SW256((uint32_t)(r * 256 + cu * 16))) = vb;
    }
    __syncthreads();

    float c[4][4][4];
#pragma unroll
    for (int mt = 0; mt < 4; ++mt)
#pragma unroll
        for (int nt = 0; nt < 4; ++nt)
#pragma unroll
            for (int q = 0; q < 4; ++q) c[mt][nt][q] = 0.f;

    const int a_row = (lane & 15);
    const int a_ku  = (lane >> 4) * 16;
    const int b_row = ((lane >> 4) & 1) * 8 + (lane & 7);
    const int b_ku  = ((lane >> 3) & 1) * 16;

#pragma unroll
    for (int ks = 0; ks < 8; ++ks) {
        uint32_t a[4][4], bf[4][2];
#pragma unroll
        for (int mt = 0; mt < 4; ++mt) {
            uint32_t off = (uint32_t)((wm + mt * 16 + a_row) * 256 + ks * 32 + a_ku);
            ldsm4(a[mt][0], a[mt][1], a[mt][2], a[mt][3], sC + SW256(off));
        }
#pragma unroll
        for (int pr = 0; pr < 2; ++pr) {
            uint32_t off = (uint32_t)((wn + pr * 16 + b_row) * 256 + ks * 32 + b_ku);
            uint32_t r0, r1, r2, r3;
            ldsm4(r0, r1, r2, r3, sB + SW256(off));
            bf[pr * 2][0] = r0; bf[pr * 2][1] = r1;
            bf[pr * 2 + 1][0] = r2; bf[pr * 2 + 1][1] = r3;
        }
#pragma unroll
        for (int mt = 0; mt < 4; ++mt)
#pragma unroll
            for (int nt = 0; nt < 4; ++nt)
                mma16816(c[mt][nt], a[mt], bf[nt]);
    }

    __half* cbo = CBh + (size_t)bc * CSIZE * CSIZE;
#pragma unroll
    for (int mt = 0; mt < 4; ++mt) {
        int gi = bi + wm + mt * 16 + (lane >> 2);
#pragma unroll
        for (int nt = 0; nt < 4; ++nt) {
            int gj = bj + wn + nt * 8 + (lane & 3) * 2;
            store2(&cbo[(size_t)gi * CSIZE + gj], c[mt][nt][0], c[mt][nt][1]);
            store2(&cbo[(size_t)(gi + 8) * CSIZE + gj], c[mt][nt][2], c[mt][nt][3]);
        }
    }
}

// =====================================================================
// states via mma -> fp16 output
// =====================================================================
#define SSM_SMEM (16384 + 32768 + 512)
__global__ void __launch_bounds__(128) states_mma(
    const __half* __restrict__ xBCh, const float* __restrict__ dtv,
    const float* __restrict__ Acum, __half* __restrict__ statesh)
{
    extern __shared__ __align__(1024) char sm[];
    __half* Xw = (__half*)sm;
    __half* Bs = (__half*)(sm + 16384);
    float*  wv = (float*)(sm + 49152);
    const uint32_t sX = smem_u32(Xw), sB = smem_u32(Bs);

    const int cc = blockIdx.x, h = blockIdx.y, b = blockIdx.z;
    const int tid = threadIdx.x, wid = tid >> 5, lane = tid & 31;
    const float* Ab = Acum + (((size_t)b * NHEADS + h) * NCHUNK + cc) * CSIZE;
    const float AcLast = Ab[CSIZE - 1];
    const int l0 = b * LSEQ + cc * CSIZE;

    float c[4][4][4];
#pragma unroll
    for (int mt = 0; mt < 4; ++mt)
#pragma unroll
        for (int nt = 0; nt < 4; ++nt)
#pragma unroll
            for (int q = 0; q < 4; ++q) c[mt][nt][q] = 0.f;

    for (int jt = 0; jt < CSIZE; jt += 128) {
        wv[tid] = __expf(AcLast - Ab[jt + tid]) * dtv[(size_t)(l0 + jt + tid) * NHEADS + h];
        __syncthreads();
#pragma unroll
        for (int it = 0; it < 8; ++it) {
            int u = tid + it * 128;
            int j = u >> 3, cu = u & 7;
            uint4 v = *(const uint4*)&xBCh[(size_t)(l0 + jt + j) * CONVDIM + h * HDIM + cu * 8];
            __half2 w2 = __float2half2_rn(wv[j]);
            *(uint4*)((char*)Xw + SW128((uint32_t)(j * 128 + cu * 16))) = mul8h(v, w2);
        }
#pragma unroll
        for (int it = 0; it < 16; ++it) {
            int u = tid + it * 128;
            int j = u >> 4, cu = u & 15;
            uint4 v = *(const uint4*)&xBCh[(size_t)(l0 + jt + j) * CONVDIM + INTERD + cu * 8];
            *(uint4*)((char*)Bs + SW256((uint32_t)(j * 256 + cu * 16))) = v;
        }
        __syncthreads();
#pragma unroll
        for (int ks = 0; ks < 8; ++ks) {
            uint32_t a[4][4], bf[4][2];
#pragma unroll
            for (int mt = 0; mt < 4; ++mt) {
                int row = ks * 16 + ((lane >> 4) & 1) * 8 + (lane & 7);
                int col = mt * 16 + ((lane >> 3) & 1) * 8;
                ldsm4t(a[mt][0], a[mt][1], a[mt][2], a[mt][3],
                       sX + SW128((uint32_t)(row * 128 + col * 2)));
            }
#pragma unroll
            for (int nt2 = 0; nt2 < 2; ++nt2) {
                int row = ks * 16 + ((lane >> 3) & 1) * 8 + (lane & 7);
                int col = wid * 32 + nt2 * 16 + (lane >> 4) * 8;
                uint32_t r0, r1, r2, r3;
                ldsm4t(r0, r1, r2, r3, sB + SW256((uint32_t)(row * 256 + col * 2)));
                bf[nt2 * 2][0] = r0; bf[nt2 * 2][1] = r1;
                bf[nt2 * 2 + 1][0] = r2; bf[nt2 * 2 + 1][1] = r3;
            }
#pragma unroll
            for (int mt = 0; mt < 4; ++mt)
#pragma unroll
                for (int nt = 0; nt < 4; ++nt)
                    mma16816(c[mt][nt], a[mt], bf[nt]);
        }
        __syncthreads();
    }
    __half* so = statesh + (((size_t)b * NCHUNK + cc) * NHEADS + h) * (HDIM * NSTATE);
#pragma unroll
    for (int mt = 0; mt < 4; ++mt) {
        int p0 = mt * 16 + (lane >> 2);
#pragma unroll
        for (int nt = 0; nt < 4; ++nt) {
            int n = wid * 32 + nt * 8 + (lane & 3) * 2;
            store2(&so[p0 * NSTATE + n], c[mt][nt][0], c[mt][nt][1]);
            store2(&so[(p0 + 8) * NSTATE + n], c[mt][nt][2], c[mt][nt][3]);
        }
    }
}

// ---------------- inter-chunk recurrence (fp16 states -> fp16 prev) ----------------
__global__ void scan_kernel(const __half* __restrict__ statesh,
                            const float* __restrict__ Acum,
                            __half* __restrict__ prevh)
{
    int h = blockIdx.x, b = blockIdx.y, tid = threadIdx.x;
    float carry[32];
#pragma unroll
    for (int t = 0; t < 32; ++t) carry[t] = 0.f;
    for (int cc = 0; cc < NCHUNK; ++cc) {
        float cd = expf(Acum[(((size_t)b * NHEADS + h) * NCHUNK + cc) * CSIZE + CSIZE - 1]);
        size_t base = (((size_t)b * NCHUNK + cc) * NHEADS + h) * (HDIM * NSTATE);
#pragma unroll
        for (int t = 0; t < 32; ++t) {
            size_t idx = base + tid + t * 256;
            prevh[idx] = __float2half(carry[t]);
            carry[t]   = cd * carry[t] + __half2float(statesh[idx]);
        }
    }
}

// =====================================================================
// Y via mma: Y[i,p] = M @ X + Ce @ prev^T + D*x   (CB now fp16)
// =====================================================================
__global__ void __launch_bounds__(256) y_mma(
    const __half* __restrict__ xBCh, const float* __restrict__ dtv,
    const float* __restrict__ Acum, const __half* __restrict__ CBh,
    const __half* __restrict__ prevh, const float* __restrict__ Dp,
    float* __restrict__ Y)
{
    __shared__ float Ac[CSIZE], dts[CSIZE], rowf[CSIZE], eA[CSIZE], colf[64];
    __shared__ __align__(1024) __half Ms[CSIZE * 64];
    __shared__ __align__(1024) __half Xs[64 * 64];
    const uint32_t sM = smem_u32(Ms), sXs = smem_u32(Xs);

    const int cc = blockIdx.x, h = blockIdx.y, b = blockIdx.z;
    const int tid = threadIdx.x, wid = tid >> 5, lane = tid & 31;
    const int wm = (wid & 3) * 64;
    const int wn = (wid >> 2) * 32;
    const int l0 = b * LSEQ + cc * CSIZE;

    Ac[tid]  = Acum[(((size_t)b * NHEADS + h) * NCHUNK + cc) * CSIZE + tid];
    dts[tid] = dtv[(size_t)(l0 + tid) * NHEADS + h];
    __syncthreads();
    eA[tid] = __expf(Ac[tid]);

    const __half* CBb = CBh + ((size_t)b * NCHUNK + cc) * CSIZE * CSIZE;

    float c[4][4][4];
#pragma unroll
    for (int mt = 0; mt < 4; ++mt)
#pragma unroll
        for (int nt = 0; nt < 4; ++nt)
#pragma unroll
            for (int q = 0; q < 4; ++q) c[mt][nt][q] = 0.f;

    for (int jt = 0; jt < CSIZE; jt += 64) {
        float A_ref = Ac[jt + 63];
        if (tid < 64) colf[tid] = __expf(A_ref - Ac[jt + tid]) * dts[jt + tid];
        rowf[tid] = __expf(Ac[tid] - A_ref);
        __syncthreads();
#pragma unroll
        for (int it = 0; it < 8; ++it) {
            int u = tid + it * 256;
            int i = u >> 3, cu = u & 7;
            float v[8];
            if (i < jt) {
#pragma unroll
                for (int e = 0; e < 8; ++e) v[e] = 0.f;
            } else {
                uint4 cbv = *(const uint4*)&CBb[(size_t)i * CSIZE + jt + cu * 8];
                __half2* ch2 = (__half2*)&cbv;
                float cf[8];
#pragma unroll
                for (int e2 = 0; e2 < 4; ++e2) {
                    float2 f = __half22float2(ch2[e2]);
                    cf[e2 * 2] = f.x; cf[e2 * 2 + 1] = f.y;
                }
                if (i >= jt + 64) {
                    float rf = rowf[i];
#pragma unroll
                    for (int e = 0; e < 8; ++e) v[e] = cf[e] * rf * colf[cu * 8 + e];
                } else {
#pragma unroll
                    for (int e = 0; e < 8; ++e) {
                        int j = jt + cu * 8 + e;
                        v[e] = (j <= i) ? cf[e] * __expf(Ac[i] - Ac[j]) * dts[j] : 0.f;
                    }
                }
            }
            *(uint4*)((char*)Ms + SW128((uint32_t)(i * 128 + cu * 16))) = pack8h(v);
        }
#pragma unroll
        for (int it = 0; it < 2; ++it) {
            int u = tid + it * 256;
            int j = u >> 3, cu = u & 7;
            uint4 v = *(const uint4*)&xBCh[(size_t)(l0 + jt + j) * CONVDIM + h * HDIM + cu * 8];
            *(uint4*)((char*)Xs + SW128((uint32_t)(j * 128 + cu * 16))) = v;
        }
        __syncthreads();
#pragma unroll
        for (int ks = 0; ks < 4; ++ks) {
            uint32_t a[4][4], bf[4][2];
#pragma unroll
            for (int mt = 0; mt < 4; ++mt) {
                int row = wm + mt * 16 + (lane & 15);
                int kb  = ks * 32 + (lane >> 4) * 16;
                ldsm4(a[mt][0], a[mt][1], a[mt][2], a[mt][3],
                      sM + SW128((uint32_t)(row * 128 + kb)));
            }
#pragma unroll
            for (int nt2 = 0; nt2 < 2; ++nt2) {
                int row = ks * 16 + ((lane >> 3) & 1) * 8 + (lane & 7);
                int col = wn + nt2 * 16 + (lane >> 4) * 8;
                uint32_t r0, r1, r2, r3;
                ldsm4t(r0, r1, r2, r3, sXs + SW128((uint32_t)(row * 128 + col * 2)));
                bf[nt2 * 2][0] = r0; bf[nt2 * 2][1] = r1;
                bf[nt2 * 2 + 1][0] = r2; bf[nt2 * 2 + 1][1] = r3;
            }
#pragma unroll
            for (int mt = 0; mt < 4; ++mt)
#pragma unroll
                for (int nt = 0; nt < 4; ++nt)
                    mma16816(c[mt][nt], a[mt], bf[nt]);
        }
        __syncthreads();
    }

    const __half* pvb = prevh + (((size_t)b * NCHUNK + cc) * NHEADS + h) * (HDIM * NSTATE);
    for (int nt0 = 0; nt0 < NSTATE; nt0 += 64) {
#pragma unroll
        for (int it = 0; it < 8; ++it) {
            int u = tid + it * 256;
            int i = u >> 3, cu = u & 7;
            uint4 v = *(const uint4*)&xBCh[(size_t)(l0 + i) * CONVDIM + INTERD + NSTATE + nt0 + cu * 8];
            __half2 ea2 = __float2half2_rn(eA[i]);
            *(uint4*)((char*)Ms + SW128((uint32_t)(i * 128 + cu * 16))) = mul8h(v, ea2);
        }
#pragma unroll
        for (int it = 0; it < 2; ++it) {
            int u = tid + it * 256;
            int p = u >> 3, cu = u & 7;
            uint4 v = *(const uint4*)(pvb + (size_t)p * NSTATE + nt0 + cu * 8);
            *(uint4*)((char*)Xs + SW128((uint32_t)(p * 128 + cu * 16))) = v;
        }
        __syncthreads();
#pragma unroll
        for (int ks = 0; ks < 4; ++ks) {
            uint32_t a[4][4], bf[4][2];
#pragma unroll
            for (int mt = 0; mt < 4; ++mt) {
                int row = wm + mt * 16 + (lane & 15);
                int kb  = ks * 32 + (lane >> 4) * 16;
                ldsm4(a[mt][0], a[mt][1], a[mt][2], a[mt][3],
                      sM + SW128((uint32_t)(row * 128 + kb)));
            }
#pragma unroll
            for (int nt2 = 0; nt2 < 2; ++nt2) {
                int prow = wn + nt2 * 16 + ((lane >> 4) & 1) * 8 + (lane & 7);
                int kb   = ks * 32 + ((lane >> 3) & 1) * 16;
                uint32_t r0, r1, r2, r3;
                ldsm4(r0, r1, r2, r3, sXs + SW128((uint32_t)(prow * 128 + kb)));
                bf[nt2 * 2][0] = r0; bf[nt2 * 2][1] = r1;
                bf[nt2 * 2 + 1][0] = r2; bf[nt2 * 2 + 1][1] = r3;
            }
#pragma unroll
            for (int mt = 0; mt < 4; ++mt)
#pragma unroll
                for (int nt = 0; nt < 4; ++nt)
                    mma16816(c[mt][nt], a[mt], bf[nt]);
        }
        __syncthreads();
    }

    float Dh = Dp[h];
#pragma unroll
    for (int mt = 0; mt < 4; ++mt) {
        int i0 = wm + mt * 16 + (lane >> 2);
#pragma unroll
        for (int nt = 0; nt < 4; ++nt) {
            int p = wn + nt * 8 + (lane & 3) * 2;
#pragma unroll
            for (int half = 0; half < 2; ++half) {
                int i = i0 + half * 8;
                __half2 xh = *(const __half2*)&xBCh[(size_t)(l0 + i) * CONVDIM + h * HDIM + p];
                float2 xv = __half22float2(xh);
                float2 ov;
                ov.x = c[mt][nt][half * 2 + 0] + Dh * xv.x;
                ov.y = c[mt][nt][half * 2 + 1] + Dh * xv.y;
                *(float2*)&Y[(size_t)(l0 + i) * INTERD + h * HDIM + p] = ov;
            }
        }
    }
}

// ---------------- gate (silu, fp16 in) + RMSNorm -> fp16 Y2 ----------------
__global__ void gate_rms_kernel(const __half* __restrict__ projh,
                                const float* __restrict__ norm_w,
                                const float* __restrict__ Y,
                                __half* __restrict__ Y2)
{
    int row = blockIdx.x, tid = threadIdx.x;
    const __half* gr = projh + (size_t)row * PROJDIM;
    const float* yr = Y + (size_t)row * INTERD;
    float yv[16];
    float ss = 0.f;
#pragma unroll
    for (int t = 0; t < 16; ++t) {
        int e = tid + t * 256;
        float g = __half2float(gr[e]);
        float v = yr[e] * (g / (1.f + __expf(-g)));
        yv[t] = v;
        ss += v * v;
    }
    __shared__ float red[8];
#pragma unroll
    for (int o = 16; o > 0; o >>= 1) ss += __shfl_xor_sync(0xffffffff, ss, o);
    if ((tid & 31) == 0) red[tid >> 5] = ss;
    __syncthreads();
    float tot = 0.f;
#pragma unroll
    for (int w = 0; w < 8; ++w) tot += red[w];
    float scale = rsqrtf(tot / (float)INTERD + EPSV);
    __half* y2r = Y2 + (size_t)row * INTERD;
#pragma unroll
    for (int t = 0; t < 16; ++t) {
        int e = tid + t * 256;
        y2r[e] = __float2half(yv[t] * scale * norm_w[e]);
    }
}

// ---------------- launch ----------------
extern "C" void kernel_launch(void* const* d_in, const int* in_sizes, int n_in,
                              void* d_out, int out_size)
{
    const float* hs      = (const float*)d_in[0];
    const float* W_in    = (const float*)d_in[1];
    const float* conv_w  = (const float*)d_in[2];
    const float* conv_b  = (const float*)d_in[3];
    const float* dt_bias = (const float*)d_in[4];
    const float* A_log   = (const float*)d_in[5];
    const float* Dp      = (const float*)d_in[6];
    const float* norm_w  = (const float*)d_in[7];
    const float* W_out   = (const float*)d_in[8];
    float* out = (float*)d_out;

    float *dtv, *Acum, *Y;
    __half *projh, *xBCh, *CBh, *statesh, *prevh, *A2, *Win2, *Y2, *Wout2;
    cudaGetSymbolAddress((void**)&projh,   g_projh);
    cudaGetSymbolAddress((void**)&xBCh,    g_xBCh);
    cudaGetSymbolAddress((void**)&dtv,     g_dtv);
    cudaGetSymbolAddress((void**)&Acum,    g_Acum);
    cudaGetSymbolAddress((void**)&CBh,     g_CBh);
    cudaGetSymbolAddress((void**)&statesh, g_statesh);
    cudaGetSymbolAddress((void**)&prevh,   g_prevh);
    cudaGetSymbolAddress((void**)&Y,       g_Y);
    cudaGetSymbolAddress((void**)&A2,      g_A2);
    cudaGetSymbolAddress((void**)&Win2,    g_Win2);
    cudaGetSymbolAddress((void**)&Y2,      g_Y2);
    cudaGetSymbolAddress((void**)&Wout2,   g_Wout2);

    cudaFuncSetAttribute(gemm_fp16_mma<__half>,
                         cudaFuncAttributeMaxDynamicSharedMemorySize, TSMEM);
    cudaFuncSetAttribute(gemm_fp16_mma<float>,
                         cudaFuncAttributeMaxDynamicSharedMemorySize, TSMEM);
    cudaFuncSetAttribute(states_mma,
                         cudaFuncAttributeMaxDynamicSharedMemorySize, SSM_SMEM);
    cudaFuncSetAttribute(cb_mma,
                         cudaFuncAttributeMaxDynamicSharedMemorySize, CB_SMEM);

    // 0) fused fp32 -> fp16 conversion (hs, W_in, W_out)
    {
        long long tot = CVT_T1 + CVT_T2 + CVT_T3;
        cvt_all_kernel<<<(unsigned)((tot + 255) / 256), 256>>>(
            hs, W_in, W_out, A2, Win2, Wout2);
    }

    // 1) proj = hs @ W_in^T  (fp16 output)
    gemm_fp16_mma<__half><<<dim3(BL / 128, (PROJDIM + 255) / 256), 512, TSMEM>>>(
        A2, Win2, projh, BL, PROJDIM, DMODEL, PROJDIM);

    // 2) conv + silu -> fp16 xBC (half2)
    {
        int total2 = BL * CONVDIM / 2;
        conv_silu_kernel<<<(total2 + 255) / 256, 256>>>(projh, conv_w, conv_b, xBCh);
    }

    // 3) softplus(dt) + cumsum
    dt_acum_kernel<<<dim3(NCHUNK, NHEADS, BATCH), CSIZE>>>(projh, dt_bias, A_log, dtv, Acum);

    // 4) CB = C . B^T via fp16 mma -> fp16
    cb_mma<<<dim3(2, 2, BATCH * NCHUNK), 256, CB_SMEM>>>(xBCh, CBh);

    // 5) states via mma -> fp16
    states_mma<<<dim3(NCHUNK, NHEADS, BATCH), 128, SSM_SMEM>>>(xBCh, dtv, Acum, statesh);

    // 6) scan -> fp16 prev
    scan_kernel<<<dim3(NHEADS, BATCH), 256>>>(statesh, Acum, prevh);

    // 7) Y via mma (Ydiag + Yoff + D*x)
    y_mma<<<dim3(NCHUNK, NHEADS, BATCH), 256>>>(xBCh, dtv, Acum, CBh, prevh, Dp, Y);

    // 8) gate + RMSNorm -> fp16
    gate_rms_kernel<<<BL, 256>>>(projh, norm_w, Y, Y2);

    // 9) out = Y @ W_out^T (fp32 output)
    gemm_fp16_mma<float><<<dim3(BL / 128, DMODEL / 256), 512, TSMEM>>>(
        Y2, Wout2, out, BL, DMODEL, INTERD, DMODEL);
}

// round 10
// speedup vs baseline: 7.1378x; 1.0308x over previous
#include <cuda_runtime.h>
#include <cuda_fp16.h>
#include <cstdint>

// ---------------- problem constants ----------------
#define BATCH    2
#define LSEQ     2048
#define DMODEL   2048
#define INTERD   4096
#define NHEADS   64
#define HDIM     64
#define NSTATE   128
#define KCONV    4
#define CSIZE    256
#define NCHUNK   (LSEQ / CSIZE)                 // 8
#define CONVDIM  (INTERD + 2 * NSTATE)          // 4352
#define PROJDIM  (INTERD + CONVDIM + NHEADS)    // 8512
#define BL       (BATCH * LSEQ)                 // 4096
#define EPSV     1e-5f

// ---------------- device scratch (static; no allocs allowed) ----------------
__device__ __half g_projh [(size_t)BL * PROJDIM];
__device__ __half g_xBCh  [(size_t)BL * CONVDIM];
__device__ float g_dtv    [(size_t)BL * NHEADS];
__device__ float g_Acum   [(size_t)BATCH * NHEADS * NCHUNK * CSIZE];
__device__ __half g_CBh   [(size_t)BATCH * NCHUNK * CSIZE * CSIZE];
__device__ __half g_statesh[(size_t)BATCH * NCHUNK * NHEADS * HDIM * NSTATE];
__device__ __half g_prevh [(size_t)BATCH * NCHUNK * NHEADS * HDIM * NSTATE];
__device__ float g_Y      [(size_t)BL * INTERD];
__device__ __half g_A2    [(size_t)BL * DMODEL];
__device__ __half g_Win2  [(size_t)PROJDIM * DMODEL];
__device__ __half g_Y2    [(size_t)BL * INTERD];
__device__ __half g_Wout2 [(size_t)DMODEL * INTERD];

// =====================================================================
// common mma helpers
// =====================================================================
__device__ __forceinline__ uint32_t smem_u32(const void* p) {
    return (uint32_t)__cvta_generic_to_shared(p);
}
#define SW128(o) ((o) ^ (((o) >> 3) & 0x70))
#define SW256(o) ((o) ^ (((o) >> 4) & 0x70))

__device__ __forceinline__ void cp_async16(uint32_t d, const void* g, int sz) {
    asm volatile("cp.async.cg.shared.global [%0], [%1], 16, %2;"
                 :: "r"(d), "l"(g), "r"(sz) : "memory");
}
#define CP_COMMIT() asm volatile("cp.async.commit_group;" ::: "memory")
#define CP_WAIT1()  asm volatile("cp.async.wait_group 1;" ::: "memory")

__device__ __forceinline__ void ldsm4(uint32_t& r0, uint32_t& r1, uint32_t& r2,
                                      uint32_t& r3, uint32_t a) {
    asm volatile("ldmatrix.sync.aligned.m8n8.x4.shared.b16 {%0,%1,%2,%3}, [%4];"
                 : "=r"(r0), "=r"(r1), "=r"(r2), "=r"(r3) : "r"(a));
}
__device__ __forceinline__ void ldsm4t(uint32_t& r0, uint32_t& r1, uint32_t& r2,
                                       uint32_t& r3, uint32_t a) {
    asm volatile("ldmatrix.sync.aligned.m8n8.x4.trans.shared.b16 {%0,%1,%2,%3}, [%4];"
                 : "=r"(r0), "=r"(r1), "=r"(r2), "=r"(r3) : "r"(a));
}
__device__ __forceinline__ void mma16816(float* c, const uint32_t* a, const uint32_t* b) {
    asm volatile(
        "mma.sync.aligned.m16n8k16.row.col.f32.f16.f16.f32 "
        "{%0,%1,%2,%3}, {%4,%5,%6,%7}, {%8,%9}, {%0,%1,%2,%3};"
        : "+f"(c[0]), "+f"(c[1]), "+f"(c[2]), "+f"(c[3])
        : "r"(a[0]), "r"(a[1]), "r"(a[2]), "r"(a[3]), "r"(b[0]), "r"(b[1]));
}

__device__ __forceinline__ uint4 pack8h(const float* v) {
    __half h[8];
#pragma unroll
    for (int e = 0; e < 8; ++e) h[e] = __float2half(v[e]);
    uint4 r;
    r.x = ((uint32_t)*(uint16_t*)&h[1] << 16) | *(uint16_t*)&h[0];
    r.y = ((uint32_t)*(uint16_t*)&h[3] << 16) | *(uint16_t*)&h[2];
    r.z = ((uint32_t)*(uint16_t*)&h[5] << 16) | *(uint16_t*)&h[4];
    r.w = ((uint32_t)*(uint16_t*)&h[7] << 16) | *(uint16_t*)&h[6];
    return r;
}
__device__ __forceinline__ uint4 mul8h(uint4 v, __half2 w) {
    __half2* p = (__half2*)&v;
    p[0] = __hmul2(p[0], w); p[1] = __hmul2(p[1], w);
    p[2] = __hmul2(p[2], w); p[3] = __hmul2(p[3], w);
    return v;
}

__device__ __forceinline__ void store2(float* p, float a, float b) {
    *(float2*)p = make_float2(a, b);
}
__device__ __forceinline__ void store2(__half* p, float a, float b) {
    __half2 h; h.x = __float2half(a); h.y = __float2half(b);
    *(__half2*)p = h;
}

// =====================================================================
// big fp16 GEMM v2: BM=BN=128, BK=64, 3 stages, 256 threads, 2 CTAs/SM
// =====================================================================
#define TSTAGE_B (128 * 128 * 2)             // 32768 (A 16KB + B 16KB)
#define TNSTG    3
#define TSMEM    (TNSTG * TSTAGE_B)          // 98304

template <typename TOUT>
__global__ void __launch_bounds__(256, 2) gemm_fp16_mma(
    const __half* __restrict__ A, const __half* __restrict__ Bm,
    TOUT* __restrict__ C, int M, int N, int K, int ldc)
{
    extern __shared__ __align__(1024) char smem[];
    const uint32_t sbase = smem_u32(smem);
    const int tid  = threadIdx.x;
    const int wid  = tid >> 5, lane = tid & 31;
    const int bm   = blockIdx.x * 128, bn = blockIdx.y * 128;
    const int wm   = (wid & 1) * 64;          // 2 warps over M
    const int wn   = (wid >> 1) * 32;         // 4 warps over N
    const int KT   = K >> 6;

    float c[4][4][4];
#pragma unroll
    for (int mt = 0; mt < 4; ++mt)
#pragma unroll
        for (int nt = 0; nt < 4; ++nt)
#pragma unroll
            for (int q = 0; q < 4; ++q) c[mt][nt][q] = 0.f;

#define LOAD_STAGE(kt, s) do {                                               \
    uint32_t st_ = sbase + (s) * TSTAGE_B;                                   \
    _Pragma("unroll")                                                        \
    for (int i_ = 0; i_ < 4; ++i_) {                                         \
        int u_ = tid + i_ * 256;                                             \
        int r_ = u_ >> 3, lu_ = u_ & 7;                                      \
        uint32_t d_ = st_ + SW128((uint32_t)(r_ * 128 + lu_ * 16));          \
        const void* g_ = (const char*)A +                                    \
            (((size_t)(bm + r_) * K + (size_t)(kt) * 64 + lu_ * 8) << 1);    \
        cp_async16(d_, g_, 16);                                              \
    }                                                                        \
    _Pragma("unroll")                                                        \
    for (int i_ = 0; i_ < 4; ++i_) {                                         \
        int u_ = tid + i_ * 256;                                             \
        int r_ = u_ >> 3, lu_ = u_ & 7;                                      \
        int gn_ = bn + r_;                                                   \
        uint32_t d_ = st_ + 16384 + SW128((uint32_t)(r_ * 128 + lu_ * 16));  \
        const void* g_ = (const char*)Bm +                                   \
            (((size_t)gn_ * K + (size_t)(kt) * 64 + lu_ * 8) << 1);          \
        cp_async16(d_, g_, gn_ < N ? 16 : 0);                                \
    }                                                                        \
} while (0)

    LOAD_STAGE(0, 0); CP_COMMIT();
    LOAD_STAGE(1, 1); CP_COMMIT();

    const int a_row = (lane & 15);
    const int a_ku  = (lane >> 4) * 16;
    const int b_row = ((lane >> 4) & 1) * 8 + (lane & 7);
    const int b_ku  = ((lane >> 3) & 1) * 16;

    for (int kt = 0; kt < KT; ++kt) {
        const int s = kt % 3;
        CP_WAIT1();
        __syncthreads();
        if (kt + 2 < KT) LOAD_STAGE(kt + 2, (kt + 2) % 3);
        CP_COMMIT();

        const uint32_t stA = sbase + s * TSTAGE_B;
        const uint32_t stB = stA + 16384;
#pragma unroll
        for (int ks = 0; ks < 4; ++ks) {
            uint32_t a[4][4], b[4][2];
#pragma unroll
            for (int mt = 0; mt < 4; ++mt) {
                uint32_t off = (uint32_t)((wm + mt * 16 + a_row) * 128 + ks * 32 + a_ku);
                ldsm4(a[mt][0], a[mt][1], a[mt][2], a[mt][3], stA + SW128(off));
            }
#pragma unroll
            for (int pr = 0; pr < 2; ++pr) {
                uint32_t off = (uint32_t)((wn + pr * 16 + b_row) * 128 + ks * 32 + b_ku);
                uint32_t r0, r1, r2, r3;
                ldsm4(r0, r1, r2, r3, stB + SW128(off));
                b[pr * 2][0] = r0; b[pr * 2][1] = r1;
                b[pr * 2 + 1][0] = r2; b[pr * 2 + 1][1] = r3;
            }
#pragma unroll
            for (int mt = 0; mt < 4; ++mt)
#pragma unroll
                for (int nt = 0; nt < 4; ++nt)
                    mma16816(c[mt][nt], a[mt], b[nt]);
        }
        __syncthreads();
    }

#pragma unroll
    for (int mt = 0; mt < 4; ++mt) {
        int r0 = bm + wm + mt * 16 + (lane >> 2);
#pragma unroll
        for (int nt = 0; nt < 4; ++nt) {
            int col = bn + wn + nt * 8 + (lane & 3) * 2;
            if (col < N) {
                store2(&C[(size_t)r0 * ldc + col], c[mt][nt][0], c[mt][nt][1]);
                store2(&C[(size_t)(r0 + 8) * ldc + col], c[mt][nt][2], c[mt][nt][3]);
            }
        }
    }
}

// ---------------- fused fp32 -> fp16 convert of hs, W_in, W_out ----------------
#define CVT_T1 ((long long)BL * DMODEL / 4)
#define CVT_T2 ((long long)PROJDIM * DMODEL / 4)
#define CVT_T3 ((long long)DMODEL * INTERD / 4)
__global__ void cvt_all_kernel(const float* __restrict__ hs,
                               const float* __restrict__ W_in,
                               const float* __restrict__ W_out,
                               __half* __restrict__ A2,
                               __half* __restrict__ Win2,
                               __half* __restrict__ Wout2)
{
    long long t = (long long)blockIdx.x * blockDim.x + threadIdx.x;
    const float* src; __half* dst; long long o;
    if (t < CVT_T1) { src = hs; dst = A2; o = t; }
    else if (t < CVT_T1 + CVT_T2) { src = W_in; dst = Win2; o = t - CVT_T1; }
    else if (t < CVT_T1 + CVT_T2 + CVT_T3) { src = W_out; dst = Wout2; o = t - CVT_T1 - CVT_T2; }
    else return;
    float4 a = *(const float4*)(src + o * 4);
    float v[4] = {a.x, a.y, a.z, a.w};
    __half h[4];
#pragma unroll
    for (int e = 0; e < 4; ++e) h[e] = __float2half(v[e]);
    uint2 r;
    r.x = ((uint32_t)*(uint16_t*)&h[1] << 16) | *(uint16_t*)&h[0];
    r.y = ((uint32_t)*(uint16_t*)&h[3] << 16) | *(uint16_t*)&h[2];
    *(uint2*)(dst + o * 4) = r;
}

// ---------------- depthwise causal conv (K=4) + bias + silu, half2 ----------------
__global__ void conv_silu_kernel(const __half* __restrict__ projh,
                                 const float* __restrict__ cw,
                                 const float* __restrict__ cb,
                                 __half* __restrict__ xBCh)
{
    int idx = blockIdx.x * blockDim.x + threadIdx.x;
    if (idx >= BL * CONVDIM / 2) return;
    int ch2 = idx % (CONVDIM / 2);
    int bl  = idx / (CONVDIM / 2);
    int ch  = ch2 * 2;
    int l   = bl % LSEQ;
    float4 w0 = *(const float4*)&cw[ch * 4];
    float4 w1 = *(const float4*)&cw[(ch + 1) * 4];
    float acc0 = cb[ch], acc1 = cb[ch + 1];
    const __half2* base = (const __half2*)(projh + (size_t)bl * PROJDIM + INTERD + ch);
    const int str2 = PROJDIM / 2;
    float wa0[4] = {w0.x, w0.y, w0.z, w0.w};
    float wa1[4] = {w1.x, w1.y, w1.z, w1.w};
    int kmin = (l >= 3) ? 0 : (3 - l);
#pragma unroll
    for (int k = 0; k < 4; ++k) {
        if (k >= kmin) {
            float2 t = __half22float2(base[(k - 3) * str2]);
            acc0 += wa0[k] * t.x;
            acc1 += wa1[k] * t.y;
        }
    }
    float o0 = acc0 / (1.f + __expf(-acc0));
    float o1 = acc1 / (1.f + __expf(-acc1));
    __half2 ov; ov.x = __float2half(o0); ov.y = __float2half(o1);
    *(__half2*)(xBCh + (size_t)bl * CONVDIM + ch) = ov;
}

// ---------------- softplus(dt+bias), per-chunk inclusive cumsum ----------------
__global__ void dt_acum_kernel(const __half* __restrict__ projh,
                               const float* __restrict__ dt_bias,
                               const float* __restrict__ A_log,
                               float* __restrict__ dtv,
                               float* __restrict__ Acum)
{
    int cc = blockIdx.x, h = blockIdx.y, b = blockIdx.z;
    int i  = threadIdx.x;
    int l  = cc * CSIZE + i;
    float d  = __half2float(projh[(size_t)(b * LSEQ + l) * PROJDIM + INTERD + CONVDIM + h])
             + dt_bias[h];
    float sp = (d > 20.f) ? d : log1pf(expf(d));
    dtv[(size_t)(b * LSEQ + l) * NHEADS + h] = sp;
    float dA = sp * (-expf(A_log[h]));
    __shared__ float sbuf[CSIZE];
    sbuf[i] = dA;
    __syncthreads();
    for (int off = 1; off < CSIZE; off <<= 1) {
        float v = sbuf[i];
        if (i >= off) v += sbuf[i - off];
        __syncthreads();
        sbuf[i] = v;
        __syncthreads();
    }
    Acum[(((size_t)b * NHEADS + h) * NCHUNK + cc) * CSIZE + i] = sbuf[i];
}

// =====================================================================
// CB via fp16 mma -> fp16 output
// =====================================================================
#define CB_SMEM (2 * 128 * 256)   // 65536 B
__global__ void __launch_bounds__(256) cb_mma(
    const __half* __restrict__ xBCh, __half* __restrict__ CBh)
{
    extern __shared__ __align__(1024) char sm[];
    __half* Cs = (__half*)sm;
    __half* Bs = (__half*)(sm + 32768);
    const uint32_t sC = smem_u32(Cs), sB = smem_u32(Bs);

    const int bj = blockIdx.x * 128, bi = blockIdx.y * 128;
    const int bc = blockIdx.z;
    const int b = bc / NCHUNK, cc = bc % NCHUNK;
    const int l0 = b * LSEQ + cc * CSIZE;
    const int tid = threadIdx.x, wid = tid >> 5, lane = tid & 31;
    const int wm = (wid & 1) * 64;
    const int wn = (wid >> 1) * 32;

#pragma unroll
    for (int it = 0; it < 8; ++it) {
        int u = tid + it * 256;
        int r = u >> 4, cu = u & 15;
        uint4 vc = *(const uint4*)&xBCh[(size_t)(l0 + bi + r) * CONVDIM + INTERD + NSTATE + cu * 8];
        uint4 vb = *(const uint4*)&xBCh[(size_t)(l0 + bj + r) * CONVDIM + INTERD + cu * 8];
        *(uint4*)((char*)Cs + SW256((uint32_t)(r * 256 + cu * 16))) = vc;
        *(uint4*)((char*)Bs + SW256((uint32_t)(r * 256 + cu * 16))) = vb;
    }
    __syncthreads();

    float c[4][4][4];
#pragma unroll
    for (int mt = 0; mt < 4; ++mt)
#pragma unroll
        for (int nt = 0; nt < 4; ++nt)
#pragma unroll
            for (int q = 0; q < 4; ++q) c[mt][nt][q] = 0.f;

    const int a_row = (lane & 15);
    const int a_ku  = (lane >> 4) * 16;
    const int b_row = ((lane >> 4) & 1) * 8 + (lane & 7);
    const int b_ku  = ((lane >> 3) & 1) * 16;

#pragma unroll
    for (int ks = 0; ks < 8; ++ks) {
        uint32_t a[4][4], bf[4][2];
#pragma unroll
        for (int mt = 0; mt < 4; ++mt) {
            uint32_t off = (uint32_t)((wm + mt * 16 + a_row) * 256 + ks * 32 + a_ku);
            ldsm4(a[mt][0], a[mt][1], a[mt][2], a[mt][3], sC + SW256(off));
        }
#pragma unroll
        for (int pr = 0; pr < 2; ++pr) {
            uint32_t off = (uint32_t)((wn + pr * 16 + b_row) * 256 + ks * 32 + b_ku);
            uint32_t r0, r1, r2, r3;
            ldsm4(r0, r1, r2, r3, sB + SW256(off));
            bf[pr * 2][0] = r0; bf[pr * 2][1] = r1;
            bf[pr * 2 + 1][0] = r2; bf[pr * 2 + 1][1] = r3;
        }
#pragma unroll
        for (int mt = 0; mt < 4; ++mt)
#pragma unroll
            for (int nt = 0; nt < 4; ++nt)
                mma16816(c[mt][nt], a[mt], bf[nt]);
    }

    __half* cbo = CBh + (size_t)bc * CSIZE * CSIZE;
#pragma unroll
    for (int mt = 0; mt < 4; ++mt) {
        int gi = bi + wm + mt * 16 + (lane >> 2);
#pragma unroll
        for (int nt = 0; nt < 4; ++nt) {
            int gj = bj + wn + nt * 8 + (lane & 3) * 2;
            store2(&cbo[(size_t)gi * CSIZE + gj], c[mt][nt][0], c[mt][nt][1]);
            store2(&cbo[(size_t)(gi + 8) * CSIZE + gj], c[mt][nt][2], c[mt][nt][3]);
        }
    }
}

// =====================================================================
// states via mma -> fp16 output
// =====================================================================
#define SSM_SMEM (16384 + 32768 + 512)
__global__ void __launch_bounds__(128) states_mma(
    const __half* __restrict__ xBCh, const float* __restrict__ dtv,
    const float* __restrict__ Acum, __half* __restrict__ statesh)
{
    extern __shared__ __align__(1024) char sm[];
    __half* Xw = (__half*)sm;
    __half* Bs = (__half*)(sm + 16384);
    float*  wv = (float*)(sm + 49152);
    const uint32_t sX = smem_u32(Xw), sB = smem_u32(Bs);

    const int cc = blockIdx.x, h = blockIdx.y, b = blockIdx.z;
    const int tid = threadIdx.x, wid = tid >> 5, lane = tid & 31;
    const float* Ab = Acum + (((size_t)b * NHEADS + h) * NCHUNK + cc) * CSIZE;
    const float AcLast = Ab[CSIZE - 1];
    const int l0 = b * LSEQ + cc * CSIZE;

    float c[4][4][4];
#pragma unroll
    for (int mt = 0; mt < 4; ++mt)
#pragma unroll
        for (int nt = 0; nt < 4; ++nt)
#pragma unroll
            for (int q = 0; q < 4; ++q) c[mt][nt][q] = 0.f;

    for (int jt = 0; jt < CSIZE; jt += 128) {
        wv[tid] = __expf(AcLast - Ab[jt + tid]) * dtv[(size_t)(l0 + jt + tid) * NHEADS + h];
        __syncthreads();
#pragma unroll
        for (int it = 0; it < 8; ++it) {
            int u = tid + it * 128;
            int j = u >> 3, cu = u & 7;
            uint4 v = *(const uint4*)&xBCh[(size_t)(l0 + jt + j) * CONVDIM + h * HDIM + cu * 8];
            __half2 w2 = __float2half2_rn(wv[j]);
            *(uint4*)((char*)Xw + SW128((uint32_t)(j * 128 + cu * 16))) = mul8h(v, w2);
        }
#pragma unroll
        for (int it = 0; it < 16; ++it) {
            int u = tid + it * 128;
            int j = u >> 4, cu = u & 15;
            uint4 v = *(const uint4*)&xBCh[(size_t)(l0 + jt + j) * CONVDIM + INTERD + cu * 8];
            *(uint4*)((char*)Bs + SW256((uint32_t)(j * 256 + cu * 16))) = v;
        }
        __syncthreads();
#pragma unroll
        for (int ks = 0; ks < 8; ++ks) {
            uint32_t a[4][4], bf[4][2];
#pragma unroll
            for (int mt = 0; mt < 4; ++mt) {
                int row = ks * 16 + ((lane >> 4) & 1) * 8 + (lane & 7);
                int col = mt * 16 + ((lane >> 3) & 1) * 8;
                ldsm4t(a[mt][0], a[mt][1], a[mt][2], a[mt][3],
                       sX + SW128((uint32_t)(row * 128 + col * 2)));
            }
#pragma unroll
            for (int nt2 = 0; nt2 < 2; ++nt2) {
                int row = ks * 16 + ((lane >> 3) & 1) * 8 + (lane & 7);
                int col = wid * 32 + nt2 * 16 + (lane >> 4) * 8;
                uint32_t r0, r1, r2, r3;
                ldsm4t(r0, r1, r2, r3, sB + SW256((uint32_t)(row * 256 + col * 2)));
                bf[nt2 * 2][0] = r0; bf[nt2 * 2][1] = r1;
                bf[nt2 * 2 + 1][0] = r2; bf[nt2 * 2 + 1][1] = r3;
            }
#pragma unroll
            for (int mt = 0; mt < 4; ++mt)
#pragma unroll
                for (int nt = 0; nt < 4; ++nt)
                    mma16816(c[mt][nt], a[mt], bf[nt]);
        }
        __syncthreads();
    }
    __half* so = statesh + (((size_t)b * NCHUNK + cc) * NHEADS + h) * (HDIM * NSTATE);
#pragma unroll
    for (int mt = 0; mt < 4; ++mt) {
        int p0 = mt * 16 + (lane >> 2);
#pragma unroll
        for (int nt = 0; nt < 4; ++nt) {
            int n = wid * 32 + nt * 8 + (lane & 3) * 2;
            store2(&so[p0 * NSTATE + n], c[mt][nt][0], c[mt][nt][1]);
            store2(&so[(p0 + 8) * NSTATE + n], c[mt][nt][2], c[mt][nt][3]);
        }
    }
}

// ---------------- inter-chunk recurrence (fp16 states -> fp16 prev) ----------------
__global__ void scan_kernel(const __half* __restrict__ statesh,
                            const float* __restrict__ Acum,
                            __half* __restrict__ prevh)
{
    int h = blockIdx.x, b = blockIdx.y, tid = threadIdx.x;
    float carry[32];
#pragma unroll
    for (int t = 0; t < 32; ++t) carry[t] = 0.f;
    for (int cc = 0; cc < NCHUNK; ++cc) {
        float cd = expf(Acum[(((size_t)b * NHEADS + h) * NCHUNK + cc) * CSIZE + CSIZE - 1]);
        size_t base = (((size_t)b * NCHUNK + cc) * NHEADS + h) * (HDIM * NSTATE);
#pragma unroll
        for (int t = 0; t < 32; ++t) {
            size_t idx = base + tid + t * 256;
            prevh[idx] = __float2half(carry[t]);
            carry[t]   = cd * carry[t] + __half2float(statesh[idx]);
        }
    }
}

// =====================================================================
// Y via mma: Y[i,p] = M @ X + Ce @ prev^T + D*x
// =====================================================================
__global__ void __launch_bounds__(256) y_mma(
    const __half* __restrict__ xBCh, const float* __restrict__ dtv,
    const float* __restrict__ Acum, const __half* __restrict__ CBh,
    const __half* __restrict__ prevh, const float* __restrict__ Dp,
    float* __restrict__ Y)
{
    __shared__ float Ac[CSIZE], dts[CSIZE], rowf[CSIZE], eA[CSIZE], colf[64];
    __shared__ __align__(1024) __half Ms[CSIZE * 64];
    __shared__ __align__(1024) __half Xs[64 * 64];
    const uint32_t sM = smem_u32(Ms), sXs = smem_u32(Xs);

    const int cc = blockIdx.x, h = blockIdx.y, b = blockIdx.z;
    const int tid = threadIdx.x, wid = tid >> 5, lane = tid & 31;
    const int wm = (wid & 3) * 64;
    const int wn = (wid >> 2) * 32;
    const int l0 = b * LSEQ + cc * CSIZE;

    Ac[tid]  = Acum[(((size_t)b * NHEADS + h) * NCHUNK + cc) * CSIZE + tid];
    dts[tid] = dtv[(size_t)(l0 + tid) * NHEADS + h];
    __syncthreads();
    eA[tid] = __expf(Ac[tid]);

    const __half* CBb = CBh + ((size_t)b * NCHUNK + cc) * CSIZE * CSIZE;

    float c[4][4][4];
#pragma unroll
    for (int mt = 0; mt < 4; ++mt)
#pragma unroll
        for (int nt = 0; nt < 4; ++nt)
#pragma unroll
            for (int q = 0; q < 4; ++q) c[mt][nt][q] = 0.f;

    for (int jt = 0; jt < CSIZE; jt += 64) {
        float A_ref = Ac[jt + 63];
        if (tid < 64) colf[tid] = __expf(A_ref - Ac[jt + tid]) * dts[jt + tid];
        rowf[tid] = __expf(Ac[tid] - A_ref);
        __syncthreads();
#pragma unroll
        for (int it = 0; it < 8; ++it) {
            int u = tid + it * 256;
            int i = u >> 3, cu = u & 7;
            float v[8];
            if (i < jt) {
#pragma unroll
                for (int e = 0; e < 8; ++e) v[e] = 0.f;
            } else {
                uint4 cbv = *(const uint4*)&CBb[(size_t)i * CSIZE + jt + cu * 8];
                __half2* ch2 = (__half2*)&cbv;
                float cf[8];
#pragma unroll
                for (int e2 = 0; e2 < 4; ++e2) {
                    float2 f = __half22float2(ch2[e2]);
                    cf[e2 * 2] = f.x; cf[e2 * 2 + 1] = f.y;
                }
                if (i >= jt + 64) {
                    float rf = rowf[i];
#pragma unroll
                    for (int e = 0; e < 8; ++e) v[e] = cf[e] * rf * colf[cu * 8 + e];
                } else {
#pragma unroll
                    for (int e = 0; e < 8; ++e) {
                        int j = jt + cu * 8 + e;
                        v[e] = (j <= i) ? cf[e] * __expf(Ac[i] - Ac[j]) * dts[j] : 0.f;
                    }
                }
            }
            *(uint4*)((char*)Ms + SW128((uint32_t)(i * 128 + cu * 16))) = pack8h(v);
        }
#pragma unroll
        for (int it = 0; it < 2; ++it) {
            int u = tid + it * 256;
            int j = u >> 3, cu = u & 7;
            uint4 v = *(const uint4*)&xBCh[(size_t)(l0 + jt + j) * CONVDIM + h * HDIM + cu * 8];
            *(uint4*)((char*)Xs + SW128((uint32_t)(j * 128 + cu * 16))) = v;
        }
        __syncthreads();
#pragma unroll
        for (int ks = 0; ks < 4; ++ks) {
            uint32_t a[4][4], bf[4][2];
#pragma unroll
            for (int mt = 0; mt < 4; ++mt) {
                int row = wm + mt * 16 + (lane & 15);
                int kb  = ks * 32 + (lane >> 4) * 16;
                ldsm4(a[mt][0], a[mt][1], a[mt][2], a[mt][3],
                      sM + SW128((uint32_t)(row * 128 + kb)));
            }
#pragma unroll
            for (int nt2 = 0; nt2 < 2; ++nt2) {
                int row = ks * 16 + ((lane >> 3) & 1) * 8 + (lane & 7);
                int col = wn + nt2 * 16 + (lane >> 4) * 8;
                uint32_t r0, r1, r2, r3;
                ldsm4t(r0, r1, r2, r3, sXs + SW128((uint32_t)(row * 128 + col * 2)));
                bf[nt2 * 2][0] = r0; bf[nt2 * 2][1] = r1;
                bf[nt2 * 2 + 1][0] = r2; bf[nt2 * 2 + 1][1] = r3;
            }
#pragma unroll
            for (int mt = 0; mt < 4; ++mt)
#pragma unroll
                for (int nt = 0; nt < 4; ++nt)
                    mma16816(c[mt][nt], a[mt], bf[nt]);
        }
        __syncthreads();
    }

    const __half* pvb = prevh + (((size_t)b * NCHUNK + cc) * NHEADS + h) * (HDIM * NSTATE);
    for (int nt0 = 0; nt0 < NSTATE; nt0 += 64) {
#pragma unroll
        for (int it = 0; it < 8; ++it) {
            int u = tid + it * 256;
            int i = u >> 3, cu = u & 7;
            uint4 v = *(const uint4*)&xBCh[(size_t)(l0 + i) * CONVDIM + INTERD + NSTATE + nt0 + cu * 8];
            __half2 ea2 = __float2half2_rn(eA[i]);
            *(uint4*)((char*)Ms + SW128((uint32_t)(i * 128 + cu * 16))) = mul8h(v, ea2);
        }
#pragma unroll
        for (int it = 0; it < 2; ++it) {
            int u = tid + it * 256;
            int p = u >> 3, cu = u & 7;
            uint4 v = *(const uint4*)(pvb + (size_t)p * NSTATE + nt0 + cu * 8);
            *(uint4*)((char*)Xs + SW128((uint32_t)(p * 128 + cu * 16))) = v;
        }
        __syncthreads();
#pragma unroll
        for (int ks = 0; ks < 4; ++ks) {
            uint32_t a[4][4], bf[4][2];
#pragma unroll
            for (int mt = 0; mt < 4; ++mt) {
                int row = wm + mt * 16 + (lane & 15);
                int kb  = ks * 32 + (lane >> 4) * 16;
                ldsm4(a[mt][0], a[mt][1], a[mt][2], a[mt][3],
                      sM + SW128((uint32_t)(row * 128 + kb)));
            }
#pragma unroll
            for (int nt2 = 0; nt2 < 2; ++nt2) {
                int prow = wn + nt2 * 16 + ((lane >> 4) & 1) * 8 + (lane & 7);
                int kb   = ks * 32 + ((lane >> 3) & 1) * 16;
                uint32_t r0, r1, r2, r3;
                ldsm4(r0, r1, r2, r3, sXs + SW128((uint32_t)(prow * 128 + kb)));
                bf[nt2 * 2][0] = r0; bf[nt2 * 2][1] = r1;
                bf[nt2 * 2 + 1][0] = r2; bf[nt2 * 2 + 1][1] = r3;
            }
#pragma unroll
            for (int mt = 0; mt < 4; ++mt)
#pragma unroll
                for (int nt = 0; nt < 4; ++nt)
                    mma16816(c[mt][nt], a[mt], bf[nt]);
        }
        __syncthreads();
    }

    float Dh = Dp[h];
#pragma unroll
    for (int mt = 0; mt < 4; ++mt) {
        int i0 = wm + mt * 16 + (lane >> 2);
#pragma unroll
        for (int nt = 0; nt < 4; ++nt) {
            int p = wn + nt * 8 + (lane & 3) * 2;
#pragma unroll
            for (int half = 0; half < 2; ++half) {
                int i = i0 + half * 8;
                __half2 xh = *(const __half2*)&xBCh[(size_t)(l0 + i) * CONVDIM + h * HDIM + p];
                float2 xv = __half22float2(xh);
                float2 ov;
                ov.x = c[mt][nt][half * 2 + 0] + Dh * xv.x;
                ov.y = c[mt][nt][half * 2 + 1] + Dh * xv.y;
                *(float2*)&Y[(size_t)(l0 + i) * INTERD + h * HDIM + p] = ov;
            }
        }
    }
}

// ---------------- gate (silu, fp16 in) + RMSNorm -> fp16 Y2 ----------------
__global__ void gate_rms_kernel(const __half* __restrict__ projh,
                                const float* __restrict__ norm_w,
                                const float* __restrict__ Y,
                                __half* __restrict__ Y2)
{
    int row = blockIdx.x, tid = threadIdx.x;
    const __half* gr = projh + (size_t)row * PROJDIM;
    const float* yr = Y + (size_t)row * INTERD;
    float yv[16];
    float ss = 0.f;
#pragma unroll
    for (int t = 0; t < 16; ++t) {
        int e = tid + t * 256;
        float g = __half2float(gr[e]);
        float v = yr[e] * (g / (1.f + __expf(-g)));
        yv[t] = v;
        ss += v * v;
    }
    __shared__ float red[8];
#pragma unroll
    for (int o = 16; o > 0; o >>= 1) ss += __shfl_xor_sync(0xffffffff, ss, o);
    if ((tid & 31) == 0) red[tid >> 5] = ss;
    __syncthreads();
    float tot = 0.f;
#pragma unroll
    for (int w = 0; w < 8; ++w) tot += red[w];
    float scale = rsqrtf(tot / (float)INTERD + EPSV);
    __half* y2r = Y2 + (size_t)row * INTERD;
#pragma unroll
    for (int t = 0; t < 16; ++t) {
        int e = tid + t * 256;
        y2r[e] = __float2half(yv[t] * scale * norm_w[e]);
    }
}

// ---------------- launch ----------------
extern "C" void kernel_launch(void* const* d_in, const int* in_sizes, int n_in,
                              void* d_out, int out_size)
{
    const float* hs      = (const float*)d_in[0];
    const float* W_in    = (const float*)d_in[1];
    const float* conv_w  = (const float*)d_in[2];
    const float* conv_b  = (const float*)d_in[3];
    const float* dt_bias = (const float*)d_in[4];
    const float* A_log   = (const float*)d_in[5];
    const float* Dp      = (const float*)d_in[6];
    const float* norm_w  = (const float*)d_in[7];
    const float* W_out   = (const float*)d_in[8];
    float* out = (float*)d_out;

    float *dtv, *Acum, *Y;
    __half *projh, *xBCh, *CBh, *statesh, *prevh, *A2, *Win2, *Y2, *Wout2;
    cudaGetSymbolAddress((void**)&projh,   g_projh);
    cudaGetSymbolAddress((void**)&xBCh,    g_xBCh);
    cudaGetSymbolAddress((void**)&dtv,     g_dtv);
    cudaGetSymbolAddress((void**)&Acum,    g_Acum);
    cudaGetSymbolAddress((void**)&CBh,     g_CBh);
    cudaGetSymbolAddress((void**)&statesh, g_statesh);
    cudaGetSymbolAddress((void**)&prevh,   g_prevh);
    cudaGetSymbolAddress((void**)&Y,       g_Y);
    cudaGetSymbolAddress((void**)&A2,      g_A2);
    cudaGetSymbolAddress((void**)&Win2,    g_Win2);
    cudaGetSymbolAddress((void**)&Y2,      g_Y2);
    cudaGetSymbolAddress((void**)&Wout2,   g_Wout2);

    cudaFuncSetAttribute(gemm_fp16_mma<__half>,
                         cudaFuncAttributeMaxDynamicSharedMemorySize, TSMEM);
    cudaFuncSetAttribute(gemm_fp16_mma<float>,
                         cudaFuncAttributeMaxDynamicSharedMemorySize, TSMEM);
    cudaFuncSetAttribute(states_mma,
                         cudaFuncAttributeMaxDynamicSharedMemorySize, SSM_SMEM);
    cudaFuncSetAttribute(cb_mma,
                         cudaFuncAttributeMaxDynamicSharedMemorySize, CB_SMEM);

    // 0) fused fp32 -> fp16 conversion (hs, W_in, W_out)
    {
        long long tot = CVT_T1 + CVT_T2 + CVT_T3;
        cvt_all_kernel<<<(unsigned)((tot + 255) / 256), 256>>>(
            hs, W_in, W_out, A2, Win2, Wout2);
    }

    // 1) proj = hs @ W_in^T  (fp16 output), 128x128 tiles, 2 CTAs/SM
    gemm_fp16_mma<__half><<<dim3(BL / 128, (PROJDIM + 127) / 128), 256, TSMEM>>>(
        A2, Win2, projh, BL, PROJDIM, DMODEL, PROJDIM);

    // 2) conv + silu -> fp16 xBC (half2)
    {
        int total2 = BL * CONVDIM / 2;
        conv_silu_kernel<<<(total2 + 255) / 256, 256>>>(projh, conv_w, conv_b, xBCh);
    }

    // 3) softplus(dt) + cumsum
    dt_acum_kernel<<<dim3(NCHUNK, NHEADS, BATCH), CSIZE>>>(projh, dt_bias, A_log, dtv, Acum);

    // 4) CB = C . B^T via fp16 mma -> fp16
    cb_mma<<<dim3(2, 2, BATCH * NCHUNK), 256, CB_SMEM>>>(xBCh, CBh);

    // 5) states via mma -> fp16
    states_mma<<<dim3(NCHUNK, NHEADS, BATCH), 128, SSM_SMEM>>>(xBCh, dtv, Acum, statesh);

    // 6) scan -> fp16 prev
    scan_kernel<<<dim3(NHEADS, BATCH), 256>>>(statesh, Acum, prevh);

    // 7) Y via mma (Ydiag + Yoff + D*x)
    y_mma<<<dim3(NCHUNK, NHEADS, BATCH), 256>>>(xBCh, dtv, Acum, CBh, prevh, Dp, Y);

    // 8) gate + RMSNorm -> fp16
    gate_rms_kernel<<<BL, 256>>>(projh, norm_w, Y, Y2);

    // 9) out = Y @ W_out^T (fp32 output)
    gemm_fp16_mma<float><<<dim3(BL / 128, DMODEL / 128), 256, TSMEM>>>(
        Y2, Wout2, out, BL, DMODEL, INTERD, DMODEL);
}

// round 11
// speedup vs baseline: 7.1431x; 1.0007x over previous
#include <cuda_runtime.h>
#include <cuda_fp16.h>
#include <cstdint>

// ---------------- problem constants ----------------
#define BATCH    2
#define LSEQ     2048
#define DMODEL   2048
#define INTERD   4096
#define NHEADS   64
#define HDIM     64
#define NSTATE   128
#define KCONV    4
#define CSIZE    256
#define NCHUNK   (LSEQ / CSIZE)                 // 8
#define CONVDIM  (INTERD + 2 * NSTATE)          // 4352
#define PROJDIM  (INTERD + CONVDIM + NHEADS)    // 8512
#define BL       (BATCH * LSEQ)                 // 4096
#define EPSV     1e-5f

// ---------------- device scratch (static; no allocs allowed) ----------------
__device__ __half g_projh [(size_t)BL * PROJDIM];
__device__ __half g_xBCh  [(size_t)BL * CONVDIM];
__device__ float g_dtv    [(size_t)BL * NHEADS];
__device__ float g_Acum   [(size_t)BATCH * NHEADS * NCHUNK * CSIZE];
__device__ __half g_CBh   [(size_t)BATCH * NCHUNK * CSIZE * CSIZE];
__device__ __half g_statesh[(size_t)BATCH * NCHUNK * NHEADS * HDIM * NSTATE];
__device__ __half g_prevh [(size_t)BATCH * NCHUNK * NHEADS * HDIM * NSTATE];
__device__ float g_Y      [(size_t)BL * INTERD];
__device__ __half g_A2    [(size_t)BL * DMODEL];
__device__ __half g_Win2  [(size_t)PROJDIM * DMODEL];
__device__ __half g_Y2    [(size_t)BL * INTERD];
__device__ __half g_Wout2 [(size_t)DMODEL * INTERD];

// =====================================================================
// common mma helpers
// =====================================================================
__device__ __forceinline__ uint32_t smem_u32(const void* p) {
    return (uint32_t)__cvta_generic_to_shared(p);
}
#define SW128(o) ((o) ^ (((o) >> 3) & 0x70))
#define SW256(o) ((o) ^ (((o) >> 4) & 0x70))

__device__ __forceinline__ void cp_async16(uint32_t d, const void* g, int sz) {
    asm volatile("cp.async.cg.shared.global [%0], [%1], 16, %2;"
                 :: "r"(d), "l"(g), "r"(sz) : "memory");
}
#define CP_COMMIT() asm volatile("cp.async.commit_group;" ::: "memory")
#define CP_WAIT1()  asm volatile("cp.async.wait_group 1;" ::: "memory")

__device__ __forceinline__ void ldsm4(uint32_t& r0, uint32_t& r1, uint32_t& r2,
                                      uint32_t& r3, uint32_t a) {
    asm volatile("ldmatrix.sync.aligned.m8n8.x4.shared.b16 {%0,%1,%2,%3}, [%4];"
                 : "=r"(r0), "=r"(r1), "=r"(r2), "=r"(r3) : "r"(a));
}
__device__ __forceinline__ void ldsm4t(uint32_t& r0, uint32_t& r1, uint32_t& r2,
                                       uint32_t& r3, uint32_t a) {
    asm volatile("ldmatrix.sync.aligned.m8n8.x4.trans.shared.b16 {%0,%1,%2,%3}, [%4];"
                 : "=r"(r0), "=r"(r1), "=r"(r2), "=r"(r3) : "r"(a));
}
__device__ __forceinline__ void mma16816(float* c, const uint32_t* a, const uint32_t* b) {
    asm volatile(
        "mma.sync.aligned.m16n8k16.row.col.f32.f16.f16.f32 "
        "{%0,%1,%2,%3}, {%4,%5,%6,%7}, {%8,%9}, {%0,%1,%2,%3};"
        : "+f"(c[0]), "+f"(c[1]), "+f"(c[2]), "+f"(c[3])
        : "r"(a[0]), "r"(a[1]), "r"(a[2]), "r"(a[3]), "r"(b[0]), "r"(b[1]));
}

__device__ __forceinline__ uint4 pack8h(const float* v) {
    __half h[8];
#pragma unroll
    for (int e = 0; e < 8; ++e) h[e] = __float2half(v[e]);
    uint4 r;
    r.x = ((uint32_t)*(uint16_t*)&h[1] << 16) | *(uint16_t*)&h[0];
    r.y = ((uint32_t)*(uint16_t*)&h[3] << 16) | *(uint16_t*)&h[2];
    r.z = ((uint32_t)*(uint16_t*)&h[5] << 16) | *(uint16_t*)&h[4];
    r.w = ((uint32_t)*(uint16_t*)&h[7] << 16) | *(uint16_t*)&h[6];
    return r;
}
__device__ __forceinline__ uint4 mul8h(uint4 v, __half2 w) {
    __half2* p = (__half2*)&v;
    p[0] = __hmul2(p[0], w); p[1] = __hmul2(p[1], w);
    p[2] = __hmul2(p[2], w); p[3] = __hmul2(p[3], w);
    return v;
}

__device__ __forceinline__ void store2(float* p, float a, float b) {
    *(float2*)p = make_float2(a, b);
}
__device__ __forceinline__ void store2(__half* p, float a, float b) {
    __half2 h; h.x = __float2half(a); h.y = __float2half(b);
    *(__half2*)p = h;
}

// =====================================================================
// big fp16 GEMM: BM=BN=128, BK=64, 3 stages, 256 threads, 2 CTAs/SM,
// single __syncthreads per K-iteration (trailing barrier removed).
// =====================================================================
#define TSTAGE_B (128 * 128 * 2)             // 32768 (A 16KB + B 16KB)
#define TNSTG    3
#define TSMEM    (TNSTG * TSTAGE_B)          // 98304

template <typename TOUT>
__global__ void __launch_bounds__(256, 2) gemm_fp16_mma(
    const __half* __restrict__ A, const __half* __restrict__ Bm,
    TOUT* __restrict__ C, int M, int N, int K, int ldc)
{
    extern __shared__ __align__(1024) char smem[];
    const uint32_t sbase = smem_u32(smem);
    const int tid  = threadIdx.x;
    const int wid  = tid >> 5, lane = tid & 31;
    const int bm   = blockIdx.x * 128, bn = blockIdx.y * 128;
    const int wm   = (wid & 1) * 64;          // 2 warps over M
    const int wn   = (wid >> 1) * 32;         // 4 warps over N
    const int KT   = K >> 6;

    float c[4][4][4];
#pragma unroll
    for (int mt = 0; mt < 4; ++mt)
#pragma unroll
        for (int nt = 0; nt < 4; ++nt)
#pragma unroll
            for (int q = 0; q < 4; ++q) c[mt][nt][q] = 0.f;

#define LOAD_STAGE(kt, s) do {                                               \
    uint32_t st_ = sbase + (s) * TSTAGE_B;                                   \
    _Pragma("unroll")                                                        \
    for (int i_ = 0; i_ < 4; ++i_) {                                         \
        int u_ = tid + i_ * 256;                                             \
        int r_ = u_ >> 3, lu_ = u_ & 7;                                      \
        uint32_t d_ = st_ + SW128((uint32_t)(r_ * 128 + lu_ * 16));          \
        const void* g_ = (const char*)A +                                    \
            (((size_t)(bm + r_) * K + (size_t)(kt) * 64 + lu_ * 8) << 1);    \
        cp_async16(d_, g_, 16);                                              \
    }                                                                        \
    _Pragma("unroll")                                                        \
    for (int i_ = 0; i_ < 4; ++i_) {                                         \
        int u_ = tid + i_ * 256;                                             \
        int r_ = u_ >> 3, lu_ = u_ & 7;                                      \
        int gn_ = bn + r_;                                                   \
        uint32_t d_ = st_ + 16384 + SW128((uint32_t)(r_ * 128 + lu_ * 16));  \
        const void* g_ = (const char*)Bm +                                   \
            (((size_t)gn_ * K + (size_t)(kt) * 64 + lu_ * 8) << 1);          \
        cp_async16(d_, g_, gn_ < N ? 16 : 0);                                \
    }                                                                        \
} while (0)

    LOAD_STAGE(0, 0); CP_COMMIT();
    LOAD_STAGE(1, 1); CP_COMMIT();

    const int a_row = (lane & 15);
    const int a_ku  = (lane >> 4) * 16;
    const int b_row = ((lane >> 4) & 1) * 8 + (lane & 7);
    const int b_ku  = ((lane >> 3) & 1) * 16;

    for (int kt = 0; kt < KT; ++kt) {
        const int s = kt % 3;
        CP_WAIT1();
        __syncthreads();   // all warps done consuming stage kt-1; safe to refill it
        if (kt + 2 < KT) LOAD_STAGE(kt + 2, (kt + 2) % 3);
        CP_COMMIT();

        const uint32_t stA = sbase + s * TSTAGE_B;
        const uint32_t stB = stA + 16384;
#pragma unroll
        for (int ks = 0; ks < 4; ++ks) {
            uint32_t a[4][4], b[4][2];
#pragma unroll
            for (int mt = 0; mt < 4; ++mt) {
                uint32_t off = (uint32_t)((wm + mt * 16 + a_row) * 128 + ks * 32 + a_ku);
                ldsm4(a[mt][0], a[mt][1], a[mt][2], a[mt][3], stA + SW128(off));
            }
#pragma unroll
            for (int pr = 0; pr < 2; ++pr) {
                uint32_t off = (uint32_t)((wn + pr * 16 + b_row) * 128 + ks * 32 + b_ku);
                uint32_t r0, r1, r2, r3;
                ldsm4(r0, r1, r2, r3, stB + SW128(off));
                b[pr * 2][0] = r0; b[pr * 2][1] = r1;
                b[pr * 2 + 1][0] = r2; b[pr * 2 + 1][1] = r3;
            }
#pragma unroll
            for (int mt = 0; mt < 4; ++mt)
#pragma unroll
                for (int nt = 0; nt < 4; ++nt)
                    mma16816(c[mt][nt], a[mt], b[nt]);
        }
    }

#pragma unroll
    for (int mt = 0; mt < 4; ++mt) {
        int r0 = bm + wm + mt * 16 + (lane >> 2);
#pragma unroll
        for (int nt = 0; nt < 4; ++nt) {
            int col = bn + wn + nt * 8 + (lane & 3) * 2;
            if (col < N) {
                store2(&C[(size_t)r0 * ldc + col], c[mt][nt][0], c[mt][nt][1]);
                store2(&C[(size_t)(r0 + 8) * ldc + col], c[mt][nt][2], c[mt][nt][3]);
            }
        }
    }
}

// ---------------- fused fp32 -> fp16 convert of hs, W_in, W_out ----------------
#define CVT_T1 ((long long)BL * DMODEL / 4)
#define CVT_T2 ((long long)PROJDIM * DMODEL / 4)
#define CVT_T3 ((long long)DMODEL * INTERD / 4)
__global__ void cvt_all_kernel(const float* __restrict__ hs,
                               const float* __restrict__ W_in,
                               const float* __restrict__ W_out,
                               __half* __restrict__ A2,
                               __half* __restrict__ Win2,
                               __half* __restrict__ Wout2)
{
    long long t = (long long)blockIdx.x * blockDim.x + threadIdx.x;
    const float* src; __half* dst; long long o;
    if (t < CVT_T1) { src = hs; dst = A2; o = t; }
    else if (t < CVT_T1 + CVT_T2) { src = W_in; dst = Win2; o = t - CVT_T1; }
    else if (t < CVT_T1 + CVT_T2 + CVT_T3) { src = W_out; dst = Wout2; o = t - CVT_T1 - CVT_T2; }
    else return;
    float4 a = *(const float4*)(src + o * 4);
    float v[4] = {a.x, a.y, a.z, a.w};
    __half h[4];
#pragma unroll
    for (int e = 0; e < 4; ++e) h[e] = __float2half(v[e]);
    uint2 r;
    r.x = ((uint32_t)*(uint16_t*)&h[1] << 16) | *(uint16_t*)&h[0];
    r.y = ((uint32_t)*(uint16_t*)&h[3] << 16) | *(uint16_t*)&h[2];
    *(uint2*)(dst + o * 4) = r;
}

// ---------------- depthwise causal conv (K=4) + bias + silu, half2 ----------------
__global__ void conv_silu_kernel(const __half* __restrict__ projh,
                                 const float* __restrict__ cw,
                                 const float* __restrict__ cb,
                                 __half* __restrict__ xBCh)
{
    int idx = blockIdx.x * blockDim.x + threadIdx.x;
    if (idx >= BL * CONVDIM / 2) return;
    int ch2 = idx % (CONVDIM / 2);
    int bl  = idx / (CONVDIM / 2);
    int ch  = ch2 * 2;
    int l   = bl % LSEQ;
    float4 w0 = *(const float4*)&cw[ch * 4];
    float4 w1 = *(const float4*)&cw[(ch + 1) * 4];
    float acc0 = cb[ch], acc1 = cb[ch + 1];
    const __half2* base = (const __half2*)(projh + (size_t)bl * PROJDIM + INTERD + ch);
    const int str2 = PROJDIM / 2;
    float wa0[4] = {w0.x, w0.y, w0.z, w0.w};
    float wa1[4] = {w1.x, w1.y, w1.z, w1.w};
    int kmin = (l >= 3) ? 0 : (3 - l);
#pragma unroll
    for (int k = 0; k < 4; ++k) {
        if (k >= kmin) {
            float2 t = __half22float2(base[(k - 3) * str2]);
            acc0 += wa0[k] * t.x;
            acc1 += wa1[k] * t.y;
        }
    }
    float o0 = acc0 / (1.f + __expf(-acc0));
    float o1 = acc1 / (1.f + __expf(-acc1));
    __half2 ov; ov.x = __float2half(o0); ov.y = __float2half(o1);
    *(__half2*)(xBCh + (size_t)bl * CONVDIM + ch) = ov;
}

// ---------------- softplus(dt+bias), per-chunk inclusive cumsum ----------------
__global__ void dt_acum_kernel(const __half* __restrict__ projh,
                               const float* __restrict__ dt_bias,
                               const float* __restrict__ A_log,
                               float* __restrict__ dtv,
                               float* __restrict__ Acum)
{
    int cc = blockIdx.x, h = blockIdx.y, b = blockIdx.z;
    int i  = threadIdx.x;
    int l  = cc * CSIZE + i;
    float d  = __half2float(projh[(size_t)(b * LSEQ + l) * PROJDIM + INTERD + CONVDIM + h])
             + dt_bias[h];
    float sp = (d > 20.f) ? d : log1pf(expf(d));
    dtv[(size_t)(b * LSEQ + l) * NHEADS + h] = sp;
    float dA = sp * (-expf(A_log[h]));
    __shared__ float sbuf[CSIZE];
    sbuf[i] = dA;
    __syncthreads();
    for (int off = 1; off < CSIZE; off <<= 1) {
        float v = sbuf[i];
        if (i >= off) v += sbuf[i - off];
        __syncthreads();
        sbuf[i] = v;
        __syncthreads();
    }
    Acum[(((size_t)b * NHEADS + h) * NCHUNK + cc) * CSIZE + i] = sbuf[i];
}

// =====================================================================
// CB via fp16 mma -> fp16 output
// =====================================================================
#define CB_SMEM (2 * 128 * 256)   // 65536 B
__global__ void __launch_bounds__(256) cb_mma(
    const __half* __restrict__ xBCh, __half* __restrict__ CBh)
{
    extern __shared__ __align__(1024) char sm[];
    __half* Cs = (__half*)sm;
    __half* Bs = (__half*)(sm + 32768);
    const uint32_t sC = smem_u32(Cs), sB = smem_u32(Bs);

    const int bj = blockIdx.x * 128, bi = blockIdx.y * 128;
    const int bc = blockIdx.z;
    const int b = bc / NCHUNK, cc = bc % NCHUNK;
    const int l0 = b * LSEQ + cc * CSIZE;
    const int tid = threadIdx.x, wid = tid >> 5, lane = tid & 31;
    const int wm = (wid & 1) * 64;
    const int wn = (wid >> 1) * 32;

#pragma unroll
    for (int it = 0; it < 8; ++it) {
        int u = tid + it * 256;
        int r = u >> 4, cu = u & 15;
        uint4 vc = *(const uint4*)&xBCh[(size_t)(l0 + bi + r) * CONVDIM + INTERD + NSTATE + cu * 8];
        uint4 vb = *(const uint4*)&xBCh[(size_t)(l0 + bj + r) * CONVDIM + INTERD + cu * 8];
        *(uint4*)((char*)Cs + SW256((uint32_t)(r * 256 + cu * 16))) = vc;
        *(uint4*)((char*)Bs + SW256((uint32_t)(r * 256 + cu * 16))) = vb;
    }
    __syncthreads();

    float c[4][4][4];
#pragma unroll
    for (int mt = 0; mt < 4; ++mt)
#pragma unroll
        for (int nt = 0; nt < 4; ++nt)
#pragma unroll
            for (int q = 0; q < 4; ++q) c[mt][nt][q] = 0.f;

    const int a_row = (lane & 15);
    const int a_ku  = (lane >> 4) * 16;
    const int b_row = ((lane >> 4) & 1) * 8 + (lane & 7);
    const int b_ku  = ((lane >> 3) & 1) * 16;

#pragma unroll
    for (int ks = 0; ks < 8; ++ks) {
        uint32_t a[4][4], bf[4][2];
#pragma unroll
        for (int mt = 0; mt < 4; ++mt) {
            uint32_t off = (uint32_t)((wm + mt * 16 + a_row) * 256 + ks * 32 + a_ku);
            ldsm4(a[mt][0], a[mt][1], a[mt][2], a[mt][3], sC + SW256(off));
        }
#pragma unroll
        for (int pr = 0; pr < 2; ++pr) {
            uint32_t off = (uint32_t)((wn + pr * 16 + b_row) * 256 + ks * 32 + b_ku);
            uint32_t r0, r1, r2, r3;
            ldsm4(r0, r1, r2, r3, sB + SW256(off));
            bf[pr * 2][0] = r0; bf[pr * 2][1] = r1;
            bf[pr * 2 + 1][0] = r2; bf[pr * 2 + 1][1] = r3;
        }
#pragma unroll
        for (int mt = 0; mt < 4; ++mt)
#pragma unroll
            for (int nt = 0; nt < 4; ++nt)
                mma16816(c[mt][nt], a[mt], bf[nt]);
    }

    __half* cbo = CBh + (size_t)bc * CSIZE * CSIZE;
#pragma unroll
    for (int mt = 0; mt < 4; ++mt) {
        int gi = bi + wm + mt * 16 + (lane >> 2);
#pragma unroll
        for (int nt = 0; nt < 4; ++nt) {
            int gj = bj + wn + nt * 8 + (lane & 3) * 2;
            store2(&cbo[(size_t)gi * CSIZE + gj], c[mt][nt][0], c[mt][nt][1]);
            store2(&cbo[(size_t)(gi + 8) * CSIZE + gj], c[mt][nt][2], c[mt][nt][3]);
        }
    }
}

// =====================================================================
// states via mma -> fp16 output
// =====================================================================
#define SSM_SMEM (16384 + 32768 + 512)
__global__ void __launch_bounds__(128) states_mma(
    const __half* __restrict__ xBCh, const float* __restrict__ dtv,
    const float* __restrict__ Acum, __half* __restrict__ statesh)
{
    extern __shared__ __align__(1024) char sm[];
    __half* Xw = (__half*)sm;
    __half* Bs = (__half*)(sm + 16384);
    float*  wv = (float*)(sm + 49152);
    const uint32_t sX = smem_u32(Xw), sB = smem_u32(Bs);

    const int cc = blockIdx.x, h = blockIdx.y, b = blockIdx.z;
    const int tid = threadIdx.x, wid = tid >> 5, lane = tid & 31;
    const float* Ab = Acum + (((size_t)b * NHEADS + h) * NCHUNK + cc) * CSIZE;
    const float AcLast = Ab[CSIZE - 1];
    const int l0 = b * LSEQ + cc * CSIZE;

    float c[4][4][4];
#pragma unroll
    for (int mt = 0; mt < 4; ++mt)
#pragma unroll
        for (int nt = 0; nt < 4; ++nt)
#pragma unroll
            for (int q = 0; q < 4; ++q) c[mt][nt][q] = 0.f;

    for (int jt = 0; jt < CSIZE; jt += 128) {
        wv[tid] = __expf(AcLast - Ab[jt + tid]) * dtv[(size_t)(l0 + jt + tid) * NHEADS + h];
        __syncthreads();
#pragma unroll
        for (int it = 0; it < 8; ++it) {
            int u = tid + it * 128;
            int j = u >> 3, cu = u & 7;
            uint4 v = *(const uint4*)&xBCh[(size_t)(l0 + jt + j) * CONVDIM + h * HDIM + cu * 8];
            __half2 w2 = __float2half2_rn(wv[j]);
            *(uint4*)((char*)Xw + SW128((uint32_t)(j * 128 + cu * 16))) = mul8h(v, w2);
        }
#pragma unroll
        for (int it = 0; it < 16; ++it) {
            int u = tid + it * 128;
            int j = u >> 4, cu = u & 15;
            uint4 v = *(const uint4*)&xBCh[(size_t)(l0 + jt + j) * CONVDIM + INTERD + cu * 8];
            *(uint4*)((char*)Bs + SW256((uint32_t)(j * 256 + cu * 16))) = v;
        }
        __syncthreads();
#pragma unroll
        for (int ks = 0; ks < 8; ++ks) {
            uint32_t a[4][4], bf[4][2];
#pragma unroll
            for (int mt = 0; mt < 4; ++mt) {
                int row = ks * 16 + ((lane >> 4) & 1) * 8 + (lane & 7);
                int col = mt * 16 + ((lane >> 3) & 1) * 8;
                ldsm4t(a[mt][0], a[mt][1], a[mt][2], a[mt][3],
                       sX + SW128((uint32_t)(row * 128 + col * 2)));
            }
#pragma unroll
            for (int nt2 = 0; nt2 < 2; ++nt2) {
                int row = ks * 16 + ((lane >> 3) & 1) * 8 + (lane & 7);
                int col = wid * 32 + nt2 * 16 + (lane >> 4) * 8;
                uint32_t r0, r1, r2, r3;
                ldsm4t(r0, r1, r2, r3, sB + SW256((uint32_t)(row * 256 + col * 2)));
                bf[nt2 * 2][0] = r0; bf[nt2 * 2][1] = r1;
                bf[nt2 * 2 + 1][0] = r2; bf[nt2 * 2 + 1][1] = r3;
            }
#pragma unroll
            for (int mt = 0; mt < 4; ++mt)
#pragma unroll
                for (int nt = 0; nt < 4; ++nt)
                    mma16816(c[mt][nt], a[mt], bf[nt]);
        }
        __syncthreads();
    }
    __half* so = statesh + (((size_t)b * NCHUNK + cc) * NHEADS + h) * (HDIM * NSTATE);
#pragma unroll
    for (int mt = 0; mt < 4; ++mt) {
        int p0 = mt * 16 + (lane >> 2);
#pragma unroll
        for (int nt = 0; nt < 4; ++nt) {
            int n = wid * 32 + nt * 8 + (lane & 3) * 2;
            store2(&so[p0 * NSTATE + n], c[mt][nt][0], c[mt][nt][1]);
            store2(&so[(p0 + 8) * NSTATE + n], c[mt][nt][2], c[mt][nt][3]);
        }
    }
}

// ---------------- inter-chunk recurrence (fp16 states -> fp16 prev) ----------------
__global__ void scan_kernel(const __half* __restrict__ statesh,
                            const float* __restrict__ Acum,
                            __half* __restrict__ prevh)
{
    int h = blockIdx.x, b = blockIdx.y, tid = threadIdx.x;
    float carry[32];
#pragma unroll
    for (int t = 0; t < 32; ++t) carry[t] = 0.f;
    for (int cc = 0; cc < NCHUNK; ++cc) {
        float cd = expf(Acum[(((size_t)b * NHEADS + h) * NCHUNK + cc) * CSIZE + CSIZE - 1]);
        size_t base = (((size_t)b * NCHUNK + cc) * NHEADS + h) * (HDIM * NSTATE);
#pragma unroll
        for (int t = 0; t < 32; ++t) {
            size_t idx = base + tid + t * 256;
            prevh[idx] = __float2half(carry[t]);
            carry[t]   = cd * carry[t] + __half2float(statesh[idx]);
        }
    }
}

// =====================================================================
// Y via mma: Y[i,p] = M @ X + Ce @ prev^T + D*x
// =====================================================================
__global__ void __launch_bounds__(256) y_mma(
    const __half* __restrict__ xBCh, const float* __restrict__ dtv,
    const float* __restrict__ Acum, const __half* __restrict__ CBh,
    const __half* __restrict__ prevh, const float* __restrict__ Dp,
    float* __restrict__ Y)
{
    __shared__ float Ac[CSIZE], dts[CSIZE], rowf[CSIZE], eA[CSIZE], colf[64];
    __shared__ __align__(1024) __half Ms[CSIZE * 64];
    __shared__ __align__(1024) __half Xs[64 * 64];
    const uint32_t sM = smem_u32(Ms), sXs = smem_u32(Xs);

    const int cc = blockIdx.x, h = blockIdx.y, b = blockIdx.z;
    const int tid = threadIdx.x, wid = tid >> 5, lane = tid & 31;
    const int wm = (wid & 3) * 64;
    const int wn = (wid >> 2) * 32;
    const int l0 = b * LSEQ + cc * CSIZE;

    Ac[tid]  = Acum[(((size_t)b * NHEADS + h) * NCHUNK + cc) * CSIZE + tid];
    dts[tid] = dtv[(size_t)(l0 + tid) * NHEADS + h];
    __syncthreads();
    eA[tid] = __expf(Ac[tid]);

    const __half* CBb = CBh + ((size_t)b * NCHUNK + cc) * CSIZE * CSIZE;

    float c[4][4][4];
#pragma unroll
    for (int mt = 0; mt < 4; ++mt)
#pragma unroll
        for (int nt = 0; nt < 4; ++nt)
#pragma unroll
            for (int q = 0; q < 4; ++q) c[mt][nt][q] = 0.f;

    for (int jt = 0; jt < CSIZE; jt += 64) {
        float A_ref = Ac[jt + 63];
        if (tid < 64) colf[tid] = __expf(A_ref - Ac[jt + tid]) * dts[jt + tid];
        rowf[tid] = __expf(Ac[tid] - A_ref);
        __syncthreads();
#pragma unroll
        for (int it = 0; it < 8; ++it) {
            int u = tid + it * 256;
            int i = u >> 3, cu = u & 7;
            float v[8];
            if (i < jt) {
#pragma unroll
                for (int e = 0; e < 8; ++e) v[e] = 0.f;
            } else {
                uint4 cbv = *(const uint4*)&CBb[(size_t)i * CSIZE + jt + cu * 8];
                __half2* ch2 = (__half2*)&cbv;
                float cf[8];
#pragma unroll
                for (int e2 = 0; e2 < 4; ++e2) {
                    float2 f = __half22float2(ch2[e2]);
                    cf[e2 * 2] = f.x; cf[e2 * 2 + 1] = f.y;
                }
                if (i >= jt + 64) {
                    float rf = rowf[i];
#pragma unroll
                    for (int e = 0; e < 8; ++e) v[e] = cf[e] * rf * colf[cu * 8 + e];
                } else {
#pragma unroll
                    for (int e = 0; e < 8; ++e) {
                        int j = jt + cu * 8 + e;
                        v[e] = (j <= i) ? cf[e] * __expf(Ac[i] - Ac[j]) * dts[j] : 0.f;
                    }
                }
            }
            *(uint4*)((char*)Ms + SW128((uint32_t)(i * 128 + cu * 16))) = pack8h(v);
        }
#pragma unroll
        for (int it = 0; it < 2; ++it) {
            int u = tid + it * 256;
            int j = u >> 3, cu = u & 7;
            uint4 v = *(const uint4*)&xBCh[(size_t)(l0 + jt + j) * CONVDIM + h * HDIM + cu * 8];
            *(uint4*)((char*)Xs + SW128((uint32_t)(j * 128 + cu * 16))) = v;
        }
        __syncthreads();
#pragma unroll
        for (int ks = 0; ks < 4; ++ks) {
            uint32_t a[4][4], bf[4][2];
#pragma unroll
            for (int mt = 0; mt < 4; ++mt) {
                int row = wm + mt * 16 + (lane & 15);
                int kb  = ks * 32 + (lane >> 4) * 16;
                ldsm4(a[mt][0], a[mt][1], a[mt][2], a[mt][3],
                      sM + SW128((uint32_t)(row * 128 + kb)));
            }
#pragma unroll
            for (int nt2 = 0; nt2 < 2; ++nt2) {
                int row = ks * 16 + ((lane >> 3) & 1) * 8 + (lane & 7);
                int col = wn + nt2 * 16 + (lane >> 4) * 8;
                uint32_t r0, r1, r2, r3;
                ldsm4t(r0, r1, r2, r3, sXs + SW128((uint32_t)(row * 128 + col * 2)));
                bf[nt2 * 2][0] = r0; bf[nt2 * 2][1] = r1;
                bf[nt2 * 2 + 1][0] = r2; bf[nt2 * 2 + 1][1] = r3;
            }
#pragma unroll
            for (int mt = 0; mt < 4; ++mt)
#pragma unroll
                for (int nt = 0; nt < 4; ++nt)
                    mma16816(c[mt][nt], a[mt], bf[nt]);
        }
        __syncthreads();
    }

    const __half* pvb = prevh + (((size_t)b * NCHUNK + cc) * NHEADS + h) * (HDIM * NSTATE);
    for (int nt0 = 0; nt0 < NSTATE; nt0 += 64) {
#pragma unroll
        for (int it = 0; it < 8; ++it) {
            int u = tid + it * 256;
            int i = u >> 3, cu = u & 7;
            uint4 v = *(const uint4*)&xBCh[(size_t)(l0 + i) * CONVDIM + INTERD + NSTATE + nt0 + cu * 8];
            __half2 ea2 = __float2half2_rn(eA[i]);
            *(uint4*)((char*)Ms + SW128((uint32_t)(i * 128 + cu * 16))) = mul8h(v, ea2);
        }
#pragma unroll
        for (int it = 0; it < 2; ++it) {
            int u = tid + it * 256;
            int p = u >> 3, cu = u & 7;
            uint4 v = *(const uint4*)(pvb + (size_t)p * NSTATE + nt0 + cu * 8);
            *(uint4*)((char*)Xs + SW128((uint32_t)(p * 128 + cu * 16))) = v;
        }
        __syncthreads();
#pragma unroll
        for (int ks = 0; ks < 4; ++ks) {
            uint32_t a[4][4], bf[4][2];
#pragma unroll
            for (int mt = 0; mt < 4; ++mt) {
                int row = wm + mt * 16 + (lane & 15);
                int kb  = ks * 32 + (lane >> 4) * 16;
                ldsm4(a[mt][0], a[mt][1], a[mt][2], a[mt][3],
                      sM + SW128((uint32_t)(row * 128 + kb)));
            }
#pragma unroll
            for (int nt2 = 0; nt2 < 2; ++nt2) {
                int prow = wn + nt2 * 16 + ((lane >> 4) & 1) * 8 + (lane & 7);
                int kb   = ks * 32 + ((lane >> 3) & 1) * 16;
                uint32_t r0, r1, r2, r3;
                ldsm4(r0, r1, r2, r3, sXs + SW128((uint32_t)(prow * 128 + kb)));
                bf[nt2 * 2][0] = r0; bf[nt2 * 2][1] = r1;
                bf[nt2 * 2 + 1][0] = r2; bf[nt2 * 2 + 1][1] = r3;
            }
#pragma unroll
            for (int mt = 0; mt < 4; ++mt)
#pragma unroll
                for (int nt = 0; nt < 4; ++nt)
                    mma16816(c[mt][nt], a[mt], bf[nt]);
        }
        __syncthreads();
    }

    float Dh = Dp[h];
#pragma unroll
    for (int mt = 0; mt < 4; ++mt) {
        int i0 = wm + mt * 16 + (lane >> 2);
#pragma unroll
        for (int nt = 0; nt < 4; ++nt) {
            int p = wn + nt * 8 + (lane & 3) * 2;
#pragma unroll
            for (int half = 0; half < 2; ++half) {
                int i = i0 + half * 8;
                __half2 xh = *(const __half2*)&xBCh[(size_t)(l0 + i) * CONVDIM + h * HDIM + p];
                float2 xv = __half22float2(xh);
                float2 ov;
                ov.x = c[mt][nt][half * 2 + 0] + Dh * xv.x;
                ov.y = c[mt][nt][half * 2 + 1] + Dh * xv.y;
                *(float2*)&Y[(size_t)(l0 + i) * INTERD + h * HDIM + p] = ov;
            }
        }
    }
}

// ---------------- gate (silu, fp16 in) + RMSNorm -> fp16 Y2 ----------------
__global__ void gate_rms_kernel(const __half* __restrict__ projh,
                                const float* __restrict__ norm_w,
                                const float* __restrict__ Y,
                                __half* __restrict__ Y2)
{
    int row = blockIdx.x, tid = threadIdx.x;
    const __half* gr = projh + (size_t)row * PROJDIM;
    const float* yr = Y + (size_t)row * INTERD;
    float yv[16];
    float ss = 0.f;
#pragma unroll
    for (int t = 0; t < 16; ++t) {
        int e = tid + t * 256;
        float g = __half2float(gr[e]);
        float v = yr[e] * (g / (1.f + __expf(-g)));
        yv[t] = v;
        ss += v * v;
    }
    __shared__ float red[8];
#pragma unroll
    for (int o = 16; o > 0; o >>= 1) ss += __shfl_xor_sync(0xffffffff, ss, o);
    if ((tid & 31) == 0) red[tid >> 5] = ss;
    __syncthreads();
    float tot = 0.f;
#pragma unroll
    for (int w = 0; w < 8; ++w) tot += red[w];
    float scale = rsqrtf(tot / (float)INTERD + EPSV);
    __half* y2r = Y2 + (size_t)row * INTERD;
#pragma unroll
    for (int t = 0; t < 16; ++t) {
        int e = tid + t * 256;
        y2r[e] = __float2half(yv[t] * scale * norm_w[e]);
    }
}

// ---------------- launch ----------------
extern "C" void kernel_launch(void* const* d_in, const int* in_sizes, int n_in,
                              void* d_out, int out_size)
{
    const float* hs      = (const float*)d_in[0];
    const float* W_in    = (const float*)d_in[1];
    const float* conv_w  = (const float*)d_in[2];
    const float* conv_b  = (const float*)d_in[3];
    const float* dt_bias = (const float*)d_in[4];
    const float* A_log   = (const float*)d_in[5];
    const float* Dp      = (const float*)d_in[6];
    const float* norm_w  = (const float*)d_in[7];
    const float* W_out   = (const float*)d_in[8];
    float* out = (float*)d_out;

    float *dtv, *Acum, *Y;
    __half *projh, *xBCh, *CBh, *statesh, *prevh, *A2, *Win2, *Y2, *Wout2;
    cudaGetSymbolAddress((void**)&projh,   g_projh);
    cudaGetSymbolAddress((void**)&xBCh,    g_xBCh);
    cudaGetSymbolAddress((void**)&dtv,     g_dtv);
    cudaGetSymbolAddress((void**)&Acum,    g_Acum);
    cudaGetSymbolAddress((void**)&CBh,     g_CBh);
    cudaGetSymbolAddress((void**)&statesh, g_statesh);
    cudaGetSymbolAddress((void**)&prevh,   g_prevh);
    cudaGetSymbolAddress((void**)&Y,       g_Y);
    cudaGetSymbolAddress((void**)&A2,      g_A2);
    cudaGetSymbolAddress((void**)&Win2,    g_Win2);
    cudaGetSymbolAddress((void**)&Y2,      g_Y2);
    cudaGetSymbolAddress((void**)&Wout2,   g_Wout2);

    cudaFuncSetAttribute(gemm_fp16_mma<__half>,
                         cudaFuncAttributeMaxDynamicSharedMemorySize, TSMEM);
    cudaFuncSetAttribute(gemm_fp16_mma<float>,
                         cudaFuncAttributeMaxDynamicSharedMemorySize, TSMEM);
    cudaFuncSetAttribute(states_mma,
                         cudaFuncAttributeMaxDynamicSharedMemorySize, SSM_SMEM);
    cudaFuncSetAttribute(cb_mma,
                         cudaFuncAttributeMaxDynamicSharedMemorySize, CB_SMEM);

    // side stream + events for fork-join overlap (created once; graph-capture safe)
    static cudaStream_t s1 = nullptr;
    static cudaEvent_t evA = nullptr, evB = nullptr, evC = nullptr, evD = nullptr;
    if (!s1) {
        cudaStreamCreateWithFlags(&s1, cudaStreamNonBlocking);
        cudaEventCreateWithFlags(&evA, cudaEventDisableTiming);
        cudaEventCreateWithFlags(&evB, cudaEventDisableTiming);
        cudaEventCreateWithFlags(&evC, cudaEventDisableTiming);
        cudaEventCreateWithFlags(&evD, cudaEventDisableTiming);
    }

    // 0) fused fp32 -> fp16 conversion (hs, W_in, W_out)
    {
        long long tot = CVT_T1 + CVT_T2 + CVT_T3;
        cvt_all_kernel<<<(unsigned)((tot + 255) / 256), 256>>>(
            hs, W_in, W_out, A2, Win2, Wout2);
    }

    // 1) proj = hs @ W_in^T  (fp16 output)
    gemm_fp16_mma<__half><<<dim3(BL / 128, (PROJDIM + 127) / 128), 256, TSMEM>>>(
        A2, Win2, projh, BL, PROJDIM, DMODEL, PROJDIM);

    // fork: dt_acum (needs proj only) runs on s1 concurrently with conv_silu
    cudaEventRecord(evA, 0);
    cudaStreamWaitEvent(s1, evA, 0);
    dt_acum_kernel<<<dim3(NCHUNK, NHEADS, BATCH), CSIZE, 0, s1>>>(
        projh, dt_bias, A_log, dtv, Acum);

    // 2) conv + silu -> fp16 xBC (half2) on main stream
    {
        int total2 = BL * CONVDIM / 2;
        conv_silu_kernel<<<(total2 + 255) / 256, 256>>>(projh, conv_w, conv_b, xBCh);
    }

    // fork: cb_mma (needs xBC only) on s1, concurrent with states (needs xBC+dt)
    cudaEventRecord(evC, 0);                 // conv done
    cudaStreamWaitEvent(s1, evC, 0);         // s1 already finished dt_acum
    cb_mma<<<dim3(2, 2, BATCH * NCHUNK), 256, CB_SMEM, s1>>>(xBCh, CBh);

    // main stream must see dt results before states
    cudaEventRecord(evB, s1);                // after cb_mma (and dt_acum) queued on s1
    // states needs dtv/Acum (s1) — but evB is after cb too; instead wait on dt via evB
    cudaStreamWaitEvent(0, evB, 0);

    // 5) states via mma -> fp16
    states_mma<<<dim3(NCHUNK, NHEADS, BATCH), 128, SSM_SMEM>>>(xBCh, dtv, Acum, statesh);

    // 6) scan -> fp16 prev
    scan_kernel<<<dim3(NHEADS, BATCH), 256>>>(statesh, Acum, prevh);

    // 7) Y via mma (Ydiag + Yoff + D*x)
    y_mma<<<dim3(NCHUNK, NHEADS, BATCH), 256>>>(xBCh, dtv, Acum, CBh, prevh, Dp, Y);

    // 8) gate + RMSNorm -> fp16
    gate_rms_kernel<<<BL, 256>>>(projh, norm_w, Y, Y2);

    // 9) out = Y @ W_out^T (fp32 output)
    gemm_fp16_mma<float><<<dim3(BL / 128, DMODEL / 128), 256, TSMEM>>>(
        Y2, Wout2, out, BL, DMODEL, INTERD, DMODEL);
}